// round 1
// baseline (speedup 1.0000x reference)
#include <cuda_runtime.h>

typedef unsigned long long ull;

#define B_   32
#define SV   512
#define SQ   256
#define SC   512
#define D_   1024
#define H_   8
#define DHD  128
#define N3   3072

// ---------------- scratch (device globals; no allocations allowed) ----------------
__device__ float g_qkv_v[50331648];   // [32*512, 3072]  (k | q | v)
__device__ float g_qkv_q[25165824];   // [32*256, 3072]
__device__ float g_qkv_c[50331648];   // [32*512, 3072]
__device__ float g_upd_v[16777216];   // [32*512, 1024]
__device__ float g_upd_q[8388608];    // [32*256, 1024]
__device__ float g_upd_c[16777216];   // [32*512, 1024]
__device__ float g_gate_v4q[32768];   // [32,1024]  stores (1+sigmoid)
__device__ float g_gate_q4v[32768];
__device__ float g_mean_v[32768];     // relu(masked mean)
__device__ float g_mean_q[32768];
__device__ float g_inv_v[32];
__device__ float g_inv_q[32];

// ---------------- packed f32x2 helpers (Blackwell FFMA2 path) ----------------
__device__ __forceinline__ ull pack2(float x, float y) {
    ull r; asm("mov.b64 %0, {%1,%2};" : "=l"(r) : "f"(x), "f"(y)); return r;
}
__device__ __forceinline__ void unpack2(ull v, float& x, float& y) {
    asm("mov.b64 {%0,%1}, %2;" : "=f"(x), "=f"(y) : "l"(v));
}
__device__ __forceinline__ ull ffma2(ull a, ull b, ull c) {
    ull d; asm("fma.rn.f32x2 %0, %1, %2, %3;" : "=l"(d) : "l"(a), "l"(b), "l"(c)); return d;
}
__device__ __forceinline__ ull fmul2(ull a, ull b) {
    ull d; asm("mul.rn.f32x2 %0, %1, %2;" : "=l"(d) : "l"(a), "l"(b)); return d;
}

// ---------------- small kernels ----------------
__global__ void masksum_kernel(const float* __restrict__ mask, float* __restrict__ inv, int S) {
    __shared__ float red[256];
    int b = blockIdx.x;
    float s = 0.f;
    for (int t = threadIdx.x; t < S; t += 256) s += mask[(size_t)b * S + t];
    red[threadIdx.x] = s;
    __syncthreads();
    for (int w = 128; w > 0; w >>= 1) {
        if (threadIdx.x < w) red[threadIdx.x] += red[threadIdx.x + w];
        __syncthreads();
    }
    if (threadIdx.x == 0) inv[b] = 1.f / red[0];
}

__global__ void mean_relu_kernel(const float* __restrict__ x, const float* __restrict__ mask,
                                 const float* __restrict__ inv, float* __restrict__ out, int S) {
    int b = blockIdx.y;
    int d = blockIdx.x * 256 + threadIdx.x;
    const float* xp = x + (size_t)b * S * D_ + d;
    const float* mp = mask + (size_t)b * S;
    float s = 0.f;
    for (int t = 0; t < S; t++) s += xp[(size_t)t * D_] * mp[t];
    out[b * D_ + d] = fmaxf(s * inv[b], 0.f);
}

// out[b,n] = 1 + sigmoid(rmean[b,:] @ W[:,n] + bias[n])
__global__ void gate_kernel(const float* __restrict__ rmean, const float* __restrict__ W,
                            const float* __restrict__ bias, float* __restrict__ out) {
    __shared__ float sm[D_];
    int b = blockIdx.y;
    int n = blockIdx.x * 128 + threadIdx.x;
    for (int k = threadIdx.x; k < D_; k += 128) sm[k] = rmean[b * D_ + k];
    __syncthreads();
    float acc = bias[n];
    #pragma unroll 8
    for (int k = 0; k < D_; k++) acc = fmaf(sm[k], W[(size_t)k * D_ + n], acc);
    out[b * D_ + n] = 1.f + 1.f / (1.f + __expf(-acc));
}

// ---------------- tiled SGEMM: C[M,N] = f(A) @ W[K,N] + bias, fused mask/relu/add ----------------
// 128x128 tile, BK=16, 256 threads, 8x8 per thread using FFMA2 pairs.
template <bool RELU, bool ADD, bool MASK>
__global__ __launch_bounds__(256) void sgemm_kernel(
    const float* __restrict__ A, const float* __restrict__ A2,
    const float* __restrict__ W, const float* __restrict__ bias,
    const float* __restrict__ mask, float* __restrict__ C,
    int M, int N, int K)
{
    __shared__ float As[16][128];   // [k][m]
    __shared__ float Bs[16][128];   // [k][n]
    int tid = threadIdx.x;
    int bm = blockIdx.y * 128;
    int bn = blockIdx.x * 128;
    int tx = tid & 15, ty = tid >> 4;

    int arow = tid >> 2;            // 0..63 (+64 second pass)
    int ak   = (tid & 3) << 2;      // 0,4,8,12
    int bk   = tid >> 5;            // 0..7  (+8 second pass)
    int bcol = (tid & 31) << 2;     // 0..124

    const float* Aptr  = A + (size_t)(bm + arow) * K + ak;
    const float* A2ptr = ADD ? (A2 + (size_t)(bm + arow) * K + ak) : nullptr;
    const float* Wptr  = W + (size_t)bk * N + bn + bcol;

    ull acc[8][4];
    #pragma unroll
    for (int i = 0; i < 8; i++)
        #pragma unroll
        for (int j = 0; j < 4; j++) acc[i][j] = 0ull;

    float4 pa[2], pb[2];
    // prefetch k0 = 0
    #pragma unroll
    for (int p = 0; p < 2; p++) {
        float4 av = *(const float4*)(Aptr + (size_t)p * 64 * K);
        if (ADD) {
            float4 a2 = *(const float4*)(A2ptr + (size_t)p * 64 * K);
            av.x += a2.x; av.y += a2.y; av.z += a2.z; av.w += a2.w;
        }
        if (RELU) { av.x = fmaxf(av.x, 0.f); av.y = fmaxf(av.y, 0.f); av.z = fmaxf(av.z, 0.f); av.w = fmaxf(av.w, 0.f); }
        pa[p] = av;
        pb[p] = *(const float4*)(Wptr + (size_t)(p * 8) * N);
    }

    for (int k0 = 0; k0 < K; k0 += 16) {
        // commit prefetched tile to smem
        #pragma unroll
        for (int p = 0; p < 2; p++) {
            int r = arow + p * 64;
            As[ak + 0][r] = pa[p].x; As[ak + 1][r] = pa[p].y;
            As[ak + 2][r] = pa[p].z; As[ak + 3][r] = pa[p].w;
            *(float4*)&Bs[bk + p * 8][bcol] = pb[p];
        }
        __syncthreads();
        // prefetch next tile
        if (k0 + 16 < K) {
            int kn = k0 + 16;
            #pragma unroll
            for (int p = 0; p < 2; p++) {
                float4 av = *(const float4*)(Aptr + (size_t)p * 64 * K + kn);
                if (ADD) {
                    float4 a2 = *(const float4*)(A2ptr + (size_t)p * 64 * K + kn);
                    av.x += a2.x; av.y += a2.y; av.z += a2.z; av.w += a2.w;
                }
                if (RELU) { av.x = fmaxf(av.x, 0.f); av.y = fmaxf(av.y, 0.f); av.z = fmaxf(av.z, 0.f); av.w = fmaxf(av.w, 0.f); }
                pa[p] = av;
                pb[p] = *(const float4*)(Wptr + (size_t)(kn + p * 8) * N);
            }
        }
        // compute
        #pragma unroll
        for (int kk = 0; kk < 16; kk++) {
            float4 a0 = *(const float4*)&As[kk][ty * 8];
            float4 a1 = *(const float4*)&As[kk][ty * 8 + 4];
            float4 b0 = *(const float4*)&Bs[kk][tx * 8];
            float4 b1 = *(const float4*)&Bs[kk][tx * 8 + 4];
            ull bp[4] = { pack2(b0.x, b0.y), pack2(b0.z, b0.w),
                          pack2(b1.x, b1.y), pack2(b1.z, b1.w) };
            float a[8] = { a0.x, a0.y, a0.z, a0.w, a1.x, a1.y, a1.z, a1.w };
            #pragma unroll
            for (int i = 0; i < 8; i++) {
                ull ad = pack2(a[i], a[i]);
                #pragma unroll
                for (int j = 0; j < 4; j++) acc[i][j] = ffma2(ad, bp[j], acc[i][j]);
            }
        }
        __syncthreads();
    }

    // epilogue
    #pragma unroll
    for (int i = 0; i < 8; i++) {
        int row = bm + ty * 8 + i;
        float mk = 1.f;
        if (MASK) mk = mask[row];
        #pragma unroll
        for (int j = 0; j < 4; j++) {
            int col = bn + tx * 8 + j * 2;
            float x0, x1; unpack2(acc[i][j], x0, x1);
            float2 bb = *(const float2*)&bias[col];
            x0 += bb.x; x1 += bb.y;
            if (MASK) { x0 *= mk; x1 *= mk; }
            float2 r2; r2.x = x0; r2.y = x1;
            *(float2*)&C[(size_t)row * N + col] = r2;
        }
    }
}

// ---------------- attention ----------------
// One block = (64 queries) x (one head) x (one batch). Streams keys in 64-tiles,
// online softmax, dh=128. Handles memory token (t==0) and cross-modal gating.
constexpr int SM_QS = 128 * 64;
constexpr int SM_KS = 128 * 64;
constexpr int SM_VS = 64 * 128;
constexpr int SM_SS = 64 * 65;
constexpr int ATTN_SMEM_FLOATS = SM_QS + SM_KS + SM_VS + SM_SS + 4 * 64;
constexpr size_t ATTN_SMEM_BYTES = (size_t)ATTN_SMEM_FLOATS * 4;

__global__ __launch_bounds__(256) void attn_kernel(
    const float* __restrict__ qkv,   // [B*S, 3072] : k|q|v
    const float* __restrict__ gate,  // [B,1024] (1+g) or null
    const float* __restrict__ memk,  // [1024] or null
    const float* __restrict__ memv,  // [1024] or null
    const float* __restrict__ mask,  // [B,S]
    float* __restrict__ upd,         // [B*S, 1024]
    int S, int T, int hasMem)
{
    extern __shared__ float smA[];
    float (*Qs)[64]  = (float(*)[64])(smA);                            // [d][m]
    float (*Ks)[64]  = (float(*)[64])(smA + SM_QS);                    // [d][t]
    float (*Vs)[128] = (float(*)[128])(smA + SM_QS + SM_KS);           // [t][d]
    float (*Ss)[65]  = (float(*)[65])(smA + SM_QS + SM_KS + SM_VS);    // [m][t]
    float* rowm = smA + SM_QS + SM_KS + SM_VS + SM_SS;
    float* rowl = rowm + 64;
    float* rowc = rowl + 64;
    float* km   = rowc + 64;

    int b = blockIdx.z, h = blockIdx.y;
    int m0 = blockIdx.x * 64;
    int tid = threadIdx.x;
    int tx = tid & 15, ty = tid >> 4;
    size_t base = (size_t)b * S * N3;
    int hd = h * DHD;
    const float* gb = gate ? (gate + (size_t)b * D_ + hd) : nullptr;
    const float inv_s = 0.088388347648318447f;      // 1/sqrt(128)
    const float NEGS  = -1e9f * 0.088388347648318447f;

    // load Q tile (gated), transposed: Qs[d][m]
    {
        int r = tid >> 2;
        int d0 = (tid & 3) << 2;
        #pragma unroll
        for (int it = 0; it < 8; it++) {
            int d = d0 + it * 16;
            float4 qv = *(const float4*)(qkv + base + (size_t)(m0 + r) * N3 + D_ + hd + d);
            if (gb) { qv.x *= gb[d]; qv.y *= gb[d + 1]; qv.z *= gb[d + 2]; qv.w *= gb[d + 3]; }
            Qs[d + 0][r] = qv.x; Qs[d + 1][r] = qv.y; Qs[d + 2][r] = qv.z; Qs[d + 3][r] = qv.w;
        }
    }
    if (tid < 64) { rowm[tid] = -1e30f; rowl[tid] = 0.f; }

    ull o[4][4];
    #pragma unroll
    for (int i = 0; i < 4; i++)
        #pragma unroll
        for (int j = 0; j < 4; j++) o[i][j] = 0ull;

    int nTiles = (T + 63) / 64;
    for (int kt = 0; kt < nTiles; kt++) {
        int t0 = kt * 64;
        __syncthreads();   // smem reuse barrier (also covers Q/rowm init on first iter)

        // load K (transposed, gated, mem token) and V
        {
            int r = tid >> 2;
            int d0 = (tid & 3) << 2;
            int t = t0 + r;
            #pragma unroll
            for (int it = 0; it < 8; it++) {
                int d = d0 + it * 16;
                float4 kv = make_float4(0.f, 0.f, 0.f, 0.f);
                if (t < T) {
                    if (hasMem && t == 0) {
                        float4 mk = *(const float4*)(memk + hd + d);
                        kv.x = 32.f * mk.x; kv.y = 32.f * mk.y; kv.z = 32.f * mk.z; kv.w = 32.f * mk.w;
                    } else {
                        kv = *(const float4*)(qkv + base + (size_t)(t - hasMem) * N3 + hd + d);
                    }
                    if (gb) { kv.x *= gb[d]; kv.y *= gb[d + 1]; kv.z *= gb[d + 2]; kv.w *= gb[d + 3]; }
                }
                Ks[d + 0][r] = kv.x; Ks[d + 1][r] = kv.y; Ks[d + 2][r] = kv.z; Ks[d + 3][r] = kv.w;
            }
            #pragma unroll
            for (int it = 0; it < 8; it++) {
                int d = d0 + it * 16;
                float4 vv = make_float4(0.f, 0.f, 0.f, 0.f);
                if (t < T) {
                    if (hasMem && t == 0) vv = *(const float4*)(memv + hd + d);
                    else vv = *(const float4*)(qkv + base + (size_t)(t - hasMem) * N3 + 2 * D_ + hd + d);
                }
                *(float4*)&Vs[r][d] = vv;
            }
        }
        if (tid < 64) {
            int t = t0 + tid;
            float mv = 0.f;
            if (t < T) mv = (hasMem && t == 0) ? 1.f : mask[(size_t)b * S + (t - hasMem)];
            km[tid] = mv;
        }
        __syncthreads();

        // scores: S[m][t] = sum_d Q[m][d] K[t][d]
        ull sacc[4][2];
        #pragma unroll
        for (int i = 0; i < 4; i++) { sacc[i][0] = 0ull; sacc[i][1] = 0ull; }
        #pragma unroll 8
        for (int d = 0; d < DHD; d++) {
            float4 aq = *(const float4*)&Qs[d][ty * 4];
            float4 bk = *(const float4*)&Ks[d][tx * 4];
            ull bp0 = pack2(bk.x, bk.y), bp1 = pack2(bk.z, bk.w);
            float a[4] = { aq.x, aq.y, aq.z, aq.w };
            #pragma unroll
            for (int i = 0; i < 4; i++) {
                ull ad = pack2(a[i], a[i]);
                sacc[i][0] = ffma2(ad, bp0, sacc[i][0]);
                sacc[i][1] = ffma2(ad, bp1, sacc[i][1]);
            }
        }
        // masked_fill BEFORE scale (matches reference), write scores
        #pragma unroll
        for (int i = 0; i < 4; i++) {
            int r = ty * 4 + i;
            #pragma unroll
            for (int j2 = 0; j2 < 2; j2++) {
                float x0, x1; unpack2(sacc[i][j2], x0, x1);
                int tl = tx * 4 + j2 * 2;
                Ss[r][tl]     = (km[tl]     != 0.f) ? x0 * inv_s : NEGS;
                Ss[r][tl + 1] = (km[tl + 1] != 0.f) ? x1 * inv_s : NEGS;
            }
        }
        __syncthreads();

        // online softmax per row
        if (tid < 64) {
            float mprev = rowm[tid];
            float mx = mprev;
            #pragma unroll 8
            for (int t = 0; t < 64; t++) mx = fmaxf(mx, Ss[tid][t]);
            float corr = __expf(mprev - mx);
            float ssum = 0.f;
            #pragma unroll 8
            for (int t = 0; t < 64; t++) {
                float p = __expf(Ss[tid][t] - mx);
                Ss[tid][t] = p;
                ssum += p;
            }
            rowl[tid] = rowl[tid] * corr + ssum;
            rowm[tid] = mx;
            rowc[tid] = corr;
        }
        __syncthreads();

        // rescale accumulators, then O += P @ V
        #pragma unroll
        for (int i = 0; i < 4; i++) {
            float cr = rowc[ty * 4 + i];
            ull cd = pack2(cr, cr);
            #pragma unroll
            for (int j = 0; j < 4; j++) o[i][j] = fmul2(o[i][j], cd);
        }
        #pragma unroll 8
        for (int t = 0; t < 64; t++) {
            float4 v0 = *(const float4*)&Vs[t][tx * 8];
            float4 v1 = *(const float4*)&Vs[t][tx * 8 + 4];
            ull vp0 = pack2(v0.x, v0.y), vp1 = pack2(v0.z, v0.w);
            ull vp2 = pack2(v1.x, v1.y), vp3 = pack2(v1.z, v1.w);
            #pragma unroll
            for (int i = 0; i < 4; i++) {
                float p = Ss[ty * 4 + i][t];
                ull pd = pack2(p, p);
                o[i][0] = ffma2(pd, vp0, o[i][0]);
                o[i][1] = ffma2(pd, vp1, o[i][1]);
                o[i][2] = ffma2(pd, vp2, o[i][2]);
                o[i][3] = ffma2(pd, vp3, o[i][3]);
            }
        }
    }
    __syncthreads();

    // normalize + write update
    #pragma unroll
    for (int i = 0; i < 4; i++) {
        int m = m0 + ty * 4 + i;
        float invl = 1.f / rowl[ty * 4 + i];
        float* op = upd + (size_t)(b * S + m) * D_ + hd + tx * 8;
        #pragma unroll
        for (int j = 0; j < 4; j++) {
            float x0, x1; unpack2(o[i][j], x0, x1);
            float2 r2; r2.x = x0 * invl; r2.y = x1 * invl;
            *(float2*)&op[j * 2] = r2;
        }
    }
}

// ---------------- launch ----------------
extern "C" void kernel_launch(void* const* d_in, const int* in_sizes, int n_in,
                              void* d_out, int out_size) {
    const float* v      = (const float*)d_in[0];
    const float* q      = (const float*)d_in[1];
    const float* c      = (const float*)d_in[2];
    const float* v_mask = (const float*)d_in[3];
    const float* q_mask = (const float*)d_in[4];
    const float* c_mask = (const float*)d_in[5];
    const float* Wv4q   = (const float*)d_in[6];
    const float* bv4q   = (const float*)d_in[7];
    const float* Wq4v   = (const float*)d_in[8];
    const float* bq4v   = (const float*)d_in[9];
    const float* Wv     = (const float*)d_in[10];
    const float* bv     = (const float*)d_in[11];
    const float* Wq     = (const float*)d_in[12];
    const float* bq     = (const float*)d_in[13];
    const float* Wc     = (const float*)d_in[14];
    const float* bcin   = (const float*)d_in[15];
    const float* m_v_k  = (const float*)d_in[16];
    const float* m_v_v  = (const float*)d_in[17];
    const float* m_c_k  = (const float*)d_in[18];
    const float* m_c_v  = (const float*)d_in[19];
    const float* Wvo    = (const float*)d_in[20];
    const float* bvo    = (const float*)d_in[21];
    const float* Wqo    = (const float*)d_in[22];
    const float* bqo    = (const float*)d_in[23];
    const float* Wco    = (const float*)d_in[24];
    const float* bco    = (const float*)d_in[25];
    (void)in_sizes; (void)n_in; (void)out_size;

    float *qkv_v, *qkv_q, *qkv_c, *upd_v, *upd_q, *upd_c;
    float *gv4q, *gq4v, *mnv, *mnq, *iv, *iq;
    cudaGetSymbolAddress((void**)&qkv_v, g_qkv_v);
    cudaGetSymbolAddress((void**)&qkv_q, g_qkv_q);
    cudaGetSymbolAddress((void**)&qkv_c, g_qkv_c);
    cudaGetSymbolAddress((void**)&upd_v, g_upd_v);
    cudaGetSymbolAddress((void**)&upd_q, g_upd_q);
    cudaGetSymbolAddress((void**)&upd_c, g_upd_c);
    cudaGetSymbolAddress((void**)&gv4q,  g_gate_v4q);
    cudaGetSymbolAddress((void**)&gq4v,  g_gate_q4v);
    cudaGetSymbolAddress((void**)&mnv,   g_mean_v);
    cudaGetSymbolAddress((void**)&mnq,   g_mean_q);
    cudaGetSymbolAddress((void**)&iv,    g_inv_v);
    cudaGetSymbolAddress((void**)&iq,    g_inv_q);

    cudaFuncSetAttribute(attn_kernel, cudaFuncAttributeMaxDynamicSharedMemorySize,
                         (int)ATTN_SMEM_BYTES);

    // 1) mask sums -> reciprocals
    masksum_kernel<<<B_, 256>>>(v_mask, iv, SV);
    masksum_kernel<<<B_, 256>>>(q_mask, iq, SQ);
    // 2) relu(masked mean)
    mean_relu_kernel<<<dim3(4, B_), 256>>>(v, v_mask, iv, mnv, SV);
    mean_relu_kernel<<<dim3(4, B_), 256>>>(q, q_mask, iq, mnq, SQ);
    // 3) gates (store 1+sigmoid)
    gate_kernel<<<dim3(8, B_), 128>>>(mnv, Wv4q, bv4q, gv4q);
    gate_kernel<<<dim3(8, B_), 128>>>(mnq, Wq4v, bq4v, gq4v);
    // 4) QKV projections: relu(x) @ W + b, masked
    sgemm_kernel<true, false, true><<<dim3(24, 128), 256>>>(v, nullptr, Wv, bv,   v_mask, qkv_v, B_ * SV, N3, D_);
    sgemm_kernel<true, false, true><<<dim3(24, 64),  256>>>(q, nullptr, Wq, bq,   q_mask, qkv_q, B_ * SQ, N3, D_);
    sgemm_kernel<true, false, true><<<dim3(24, 128), 256>>>(c, nullptr, Wc, bcin, c_mask, qkv_c, B_ * SC, N3, D_);
    // 5) attention (v: gated by q4v + mem token; q: gated by v4q; c: ungated + mem token)
    attn_kernel<<<dim3(SV / 64, H_, B_), 256, ATTN_SMEM_BYTES>>>(qkv_v, gq4v, m_v_k, m_v_v, v_mask, upd_v, SV, SV + 1, 1);
    attn_kernel<<<dim3(SQ / 64, H_, B_), 256, ATTN_SMEM_BYTES>>>(qkv_q, gv4q, nullptr, nullptr, q_mask, upd_q, SQ, SQ, 0);
    attn_kernel<<<dim3(SC / 64, H_, B_), 256, ATTN_SMEM_BYTES>>>(qkv_c, nullptr, m_c_k, m_c_v, c_mask, upd_c, SC, SC + 1, 1);
    // 6) output projections: (x + update) @ Wo + bo
    float* out = (float*)d_out;
    sgemm_kernel<false, true, false><<<dim3(8, 128), 256>>>(v, upd_v, Wvo, bvo, nullptr, out, B_ * SV, D_, D_);
    sgemm_kernel<false, true, false><<<dim3(8, 64),  256>>>(q, upd_q, Wqo, bqo, nullptr, out + (size_t)B_ * SV * D_, B_ * SQ, D_, D_);
    sgemm_kernel<false, true, false><<<dim3(8, 128), 256>>>(c, upd_c, Wco, bco, nullptr, out + (size_t)B_ * (SV + SQ) * D_, B_ * SC, D_, D_);
}

// round 3
// speedup vs baseline: 1.5759x; 1.5759x over previous
#include <cuda_runtime.h>
#include <cuda_bf16.h>
#include <cstdint>

typedef unsigned long long ull;

#define B_   32
#define SV   512
#define SQ   256
#define SC   512
#define D_   1024
#define H_   8
#define DHD  128
#define N3   3072
#define GK   1024   // GEMM K (always 1024)

// ---------------- scratch (device globals; no allocations allowed) ----------------
__device__ float g_qkv_v[50331648];   // [32*512, 3072]  (k | q | v)
__device__ float g_qkv_q[25165824];   // [32*256, 3072]
__device__ float g_qkv_c[50331648];   // [32*512, 3072]
__device__ float g_upd_v[16777216];   // [32*512, 1024]
__device__ float g_upd_q[8388608];    // [32*256, 1024]
__device__ float g_upd_c[16777216];   // [32*512, 1024]
__device__ float g_gate_v4q[32768];   // [32,1024]  stores (1+sigmoid)
__device__ float g_gate_q4v[32768];
__device__ float g_mean_v[32768];     // relu(masked mean)
__device__ float g_mean_q[32768];
__device__ float g_inv_v[32];
__device__ float g_inv_q[32];

// bf16 hi/lo split operands for tensor-core GEMMs
__device__ __nv_bfloat16 g_ahi_v[16777216];
__device__ __nv_bfloat16 g_alo_v[16777216];
__device__ __nv_bfloat16 g_ahi_q[8388608];
__device__ __nv_bfloat16 g_alo_q[8388608];
__device__ __nv_bfloat16 g_ahi_c[16777216];
__device__ __nv_bfloat16 g_alo_c[16777216];
__device__ __nv_bfloat16 g_wthi[12582912];   // transposed weights [N,K], hi
__device__ __nv_bfloat16 g_wtlo[12582912];   // lo
// offsets: Wv=0, Wq=3145728, Wc=6291456, Wvo=9437184, Wqo=10485760, Wco=11534336

// ---------------- packed f32x2 helpers (attention path) ----------------
__device__ __forceinline__ ull pack2(float x, float y) {
    ull r; asm("mov.b64 %0, {%1,%2};" : "=l"(r) : "f"(x), "f"(y)); return r;
}
__device__ __forceinline__ void unpack2(ull v, float& x, float& y) {
    asm("mov.b64 {%0,%1}, %2;" : "=f"(x), "=f"(y) : "l"(v));
}
__device__ __forceinline__ ull ffma2(ull a, ull b, ull c) {
    ull d; asm("fma.rn.f32x2 %0, %1, %2, %3;" : "=l"(d) : "l"(a), "l"(b), "l"(c)); return d;
}
__device__ __forceinline__ ull fmul2(ull a, ull b) {
    ull d; asm("mul.rn.f32x2 %0, %1, %2;" : "=l"(d) : "l"(a), "l"(b)); return d;
}

// ---------------- base-target tensor helpers (no sm_103a features) ----------------
__device__ __forceinline__ uint32_t smem_u32(const void* p) {
    uint32_t a;
    asm("{ .reg .u64 t; cvta.to.shared.u64 t, %1; cvt.u32.u64 %0, t; }" : "=r"(a) : "l"(p));
    return a;
}
__device__ __forceinline__ void cp16(uint32_t dst, const void* src) {
    asm volatile("cp.async.cg.shared.global [%0], [%1], 16;" :: "r"(dst), "l"(src));
}
__device__ __forceinline__ void cp_commit() { asm volatile("cp.async.commit_group;" ::: "memory"); }
__device__ __forceinline__ void cp_wait1()  { asm volatile("cp.async.wait_group 1;" ::: "memory"); }
__device__ __forceinline__ void cp_wait0()  { asm volatile("cp.async.wait_group 0;" ::: "memory"); }

__device__ __forceinline__ void ldmx4(uint32_t* r, uint32_t addr) {
    asm volatile("ldmatrix.sync.aligned.m8n8.x4.shared.b16 {%0,%1,%2,%3}, [%4];"
                 : "=r"(r[0]), "=r"(r[1]), "=r"(r[2]), "=r"(r[3]) : "r"(addr));
}
__device__ __forceinline__ void mma16816(float* d, const uint32_t* a, uint32_t b0, uint32_t b1) {
    asm volatile("mma.sync.aligned.m16n8k16.row.col.f32.bf16.bf16.f32 "
                 "{%0,%1,%2,%3}, {%4,%5,%6,%7}, {%8,%9}, {%0,%1,%2,%3};"
                 : "+f"(d[0]), "+f"(d[1]), "+f"(d[2]), "+f"(d[3])
                 : "r"(a[0]), "r"(a[1]), "r"(a[2]), "r"(a[3]), "r"(b0), "r"(b1));
}

// ---------------- conversion kernels ----------------
__device__ __forceinline__ void split1(float v, unsigned short& h, unsigned short& l) {
    __nv_bfloat16 hb = __float2bfloat16_rn(v);
    __nv_bfloat16 lb = __float2bfloat16_rn(v - __bfloat162float(hb));
    h = __bfloat16_as_ushort(hb);
    l = __bfloat16_as_ushort(lb);
}

__global__ void split_act_kernel(const float* __restrict__ x, const float* __restrict__ x2,
                                 __nv_bfloat16* __restrict__ hi, __nv_bfloat16* __restrict__ lo,
                                 int relu, int add) {
    int idx = blockIdx.x * 256 + threadIdx.x;
    float4 v = ((const float4*)x)[idx];
    if (add) {
        float4 w = ((const float4*)x2)[idx];
        v.x += w.x; v.y += w.y; v.z += w.z; v.w += w.w;
    }
    if (relu) {
        v.x = fmaxf(v.x, 0.f); v.y = fmaxf(v.y, 0.f);
        v.z = fmaxf(v.z, 0.f); v.w = fmaxf(v.w, 0.f);
    }
    unsigned short h0,h1,h2,h3,l0,l1,l2,l3;
    split1(v.x,h0,l0); split1(v.y,h1,l1); split1(v.z,h2,l2); split1(v.w,h3,l3);
    uint2 hv, lv;
    hv.x = ((uint32_t)h1 << 16) | h0; hv.y = ((uint32_t)h3 << 16) | h2;
    lv.x = ((uint32_t)l1 << 16) | l0; lv.y = ((uint32_t)l3 << 16) | l2;
    ((uint2*)hi)[idx] = hv;
    ((uint2*)lo)[idx] = lv;
}

// transpose W[K,N] -> Wt[N,K] with hi/lo split (K = 1024)
__global__ void split_wT_kernel(const float* __restrict__ W,
                                __nv_bfloat16* __restrict__ thi, __nv_bfloat16* __restrict__ tlo,
                                int N) {
    __shared__ float t[32][33];
    int n0 = blockIdx.x * 32, k0 = blockIdx.y * 32;
    int tx = threadIdx.x, ty = threadIdx.y;   // (32, 8)
    #pragma unroll
    for (int r = 0; r < 4; r++)
        t[ty + 8 * r][tx] = W[(size_t)(k0 + ty + 8 * r) * N + n0 + tx];
    __syncthreads();
    #pragma unroll
    for (int r = 0; r < 4; r++) {
        float v = t[tx][ty + 8 * r];
        unsigned short h, l; split1(v, h, l);
        size_t o = (size_t)(n0 + ty + 8 * r) * GK + k0 + tx;
        thi[o] = __ushort_as_bfloat16(h);
        tlo[o] = __ushort_as_bfloat16(l);
    }
}

// ---------------- small kernels ----------------
__global__ void masksum_kernel(const float* __restrict__ mask, float* __restrict__ inv, int S) {
    __shared__ float red[256];
    int b = blockIdx.x;
    float s = 0.f;
    for (int t = threadIdx.x; t < S; t += 256) s += mask[(size_t)b * S + t];
    red[threadIdx.x] = s;
    __syncthreads();
    for (int w = 128; w > 0; w >>= 1) {
        if (threadIdx.x < w) red[threadIdx.x] += red[threadIdx.x + w];
        __syncthreads();
    }
    if (threadIdx.x == 0) inv[b] = 1.f / red[0];
}

__global__ void mean_relu_kernel(const float* __restrict__ x, const float* __restrict__ mask,
                                 const float* __restrict__ inv, float* __restrict__ out, int S) {
    int b = blockIdx.y;
    int d = blockIdx.x * 256 + threadIdx.x;
    const float* xp = x + (size_t)b * S * D_ + d;
    const float* mp = mask + (size_t)b * S;
    float s = 0.f;
    for (int t = 0; t < S; t++) s += xp[(size_t)t * D_] * mp[t];
    out[b * D_ + d] = fmaxf(s * inv[b], 0.f);
}

__global__ void gate_kernel(const float* __restrict__ rmean, const float* __restrict__ W,
                            const float* __restrict__ bias, float* __restrict__ out) {
    __shared__ float sm[D_];
    int b = blockIdx.y;
    int n = blockIdx.x * 128 + threadIdx.x;
    for (int k = threadIdx.x; k < D_; k += 128) sm[k] = rmean[b * D_ + k];
    __syncthreads();
    float acc = bias[n];
    #pragma unroll 8
    for (int k = 0; k < D_; k++) acc = fmaf(sm[k], W[(size_t)k * D_ + n], acc);
    out[b * D_ + n] = 1.f + 1.f / (1.f + __expf(-acc));
}

// ---------------- mma.sync bf16x3 GEMM ----------------
// C[M,N] = A @ Wt^T + bias, A=ahi+alo, Wt=bhi+blo (3 MMA terms).
// 128x128 tile, BK=32, 8 warps (4x2, each 32x64), cp.async double buffer.
#define ROWB 40                               // padded b16 per smem row (80B, conflict-free)
#define MAT_BYTES (128 * ROWB * 2)            // 10240
#define STAGE_BYTES (4 * MAT_BYTES)           // 40960
#define MMA_SMEM_BYTES (2 * STAGE_BYTES)      // 81920

template <bool MASK>
__global__ __launch_bounds__(256, 2) void mma_gemm_kernel(
    const __nv_bfloat16* __restrict__ Ahi, const __nv_bfloat16* __restrict__ Alo,
    const __nv_bfloat16* __restrict__ Bhi, const __nv_bfloat16* __restrict__ Blo,
    const float* __restrict__ bias, const float* __restrict__ mask,
    float* __restrict__ C, int N)
{
    extern __shared__ char smem[];
    uint32_t sbase = smem_u32(smem);
    int tid = threadIdx.x;
    int wid = tid >> 5, lane = tid & 31;
    int bm = blockIdx.y * 128, bn = blockIdx.x * 128;
    int wm = (wid & 3) * 32;    // warp rows
    int wn = (wid >> 2) * 64;   // warp cols

    const __nv_bfloat16* srcs[4] = {
        Ahi + (size_t)bm * GK, Alo + (size_t)bm * GK,
        Bhi + (size_t)bn * GK, Blo + (size_t)bn * GK };

    float acc[2][8][4];
    #pragma unroll
    for (int i = 0; i < 2; i++)
        #pragma unroll
        for (int j = 0; j < 8; j++)
            #pragma unroll
            for (int k = 0; k < 4; k++) acc[i][j][k] = 0.f;

    int lrow = tid >> 2, lc = (tid & 3);         // loader: 128 rows x 4 x16B chunks... (2 rows/thread)
    auto load_stage = [&](int kc, int s) {
        uint32_t st = sbase + s * STAGE_BYTES;
        int k0 = kc * 32;
        #pragma unroll
        for (int m = 0; m < 4; m++) {
            const __nv_bfloat16* src = srcs[m];
            uint32_t dst = st + m * MAT_BYTES;
            #pragma unroll
            for (int it = 0; it < 2; it++) {
                int row = lrow + it * 64;
                cp16(dst + row * 80 + lc * 16, src + (size_t)row * GK + k0 + lc * 8);
            }
        }
        cp_commit();
    };

    load_stage(0, 0);

    const int NK = GK / 32;   // 32
    for (int kc = 0; kc < NK; kc++) {
        if (kc + 1 < NK) { load_stage(kc + 1, (kc + 1) & 1); cp_wait1(); }
        else cp_wait0();
        __syncthreads();
        uint32_t st  = sbase + (kc & 1) * STAGE_BYTES;
        uint32_t sAh = st, sAl = st + MAT_BYTES;
        uint32_t sBh = st + 2 * MAT_BYTES, sBl = st + 3 * MAT_BYTES;
        #pragma unroll
        for (int ks = 0; ks < 32; ks += 16) {
            uint32_t ah[2][4], al[2][4];
            int arow = wm + (lane & 15);
            int ak = ks + ((lane >> 4) << 3);
            #pragma unroll
            for (int mt = 0; mt < 2; mt++) {
                uint32_t off = (uint32_t)(((arow + mt * 16) * ROWB + ak) * 2);
                ldmx4(ah[mt], sAh + off);
                ldmx4(al[mt], sAl + off);
            }
            int r = lane & 7, qsel = lane >> 3;
            #pragma unroll
            for (int pr = 0; pr < 4; pr++) {
                int nn = wn + pr * 16 + ((qsel >> 1) << 3) + r;
                int kk = ks + ((qsel & 1) << 3);
                uint32_t off = (uint32_t)((nn * ROWB + kk) * 2);
                uint32_t bh[4], bl[4];
                ldmx4(bh, sBh + off);
                ldmx4(bl, sBl + off);
                #pragma unroll
                for (int mt = 0; mt < 2; mt++) {
                    #pragma unroll
                    for (int hf = 0; hf < 2; hf++) {
                        float* d = acc[mt][pr * 2 + hf];
                        mma16816(d, ah[mt], bh[hf * 2], bh[hf * 2 + 1]);
                        mma16816(d, ah[mt], bl[hf * 2], bl[hf * 2 + 1]);
                        mma16816(d, al[mt], bh[hf * 2], bh[hf * 2 + 1]);
                    }
                }
            }
        }
        __syncthreads();
    }

    // epilogue: fragment layout rows r0/r0+8, cols (lane%4)*2
    #pragma unroll
    for (int mt = 0; mt < 2; mt++) {
        int r0 = bm + wm + mt * 16 + (lane >> 2);
        float m0 = MASK ? mask[r0] : 1.f;
        float m1 = MASK ? mask[r0 + 8] : 1.f;
        #pragma unroll
        for (int nt = 0; nt < 8; nt++) {
            int col = bn + wn + nt * 8 + ((lane & 3) << 1);
            float2 bb = *(const float2*)(bias + col);
            float2 o0, o1;
            o0.x = (acc[mt][nt][0] + bb.x) * m0; o0.y = (acc[mt][nt][1] + bb.y) * m0;
            o1.x = (acc[mt][nt][2] + bb.x) * m1; o1.y = (acc[mt][nt][3] + bb.y) * m1;
            *(float2*)(C + (size_t)r0 * N + col) = o0;
            *(float2*)(C + (size_t)(r0 + 8) * N + col) = o1;
        }
    }
}

// ---------------- attention (fp32, FFMA2) ----------------
constexpr int SM_QS = 128 * 64;
constexpr int SM_KS = 128 * 64;
constexpr int SM_VS = 64 * 128;
constexpr int SM_SS = 64 * 65;
constexpr int ATTN_SMEM_FLOATS = SM_QS + SM_KS + SM_VS + SM_SS + 4 * 64;
constexpr size_t ATTN_SMEM_BYTES = (size_t)ATTN_SMEM_FLOATS * 4;

__global__ __launch_bounds__(256) void attn_kernel(
    const float* __restrict__ qkv, const float* __restrict__ gate,
    const float* __restrict__ memk, const float* __restrict__ memv,
    const float* __restrict__ mask, float* __restrict__ upd,
    int S, int T, int hasMem)
{
    extern __shared__ float smA[];
    float (*Qs)[64]  = (float(*)[64])(smA);
    float (*Ks)[64]  = (float(*)[64])(smA + SM_QS);
    float (*Vs)[128] = (float(*)[128])(smA + SM_QS + SM_KS);
    float (*Ss)[65]  = (float(*)[65])(smA + SM_QS + SM_KS + SM_VS);
    float* rowm = smA + SM_QS + SM_KS + SM_VS + SM_SS;
    float* rowl = rowm + 64;
    float* rowc = rowl + 64;
    float* km   = rowc + 64;

    int b = blockIdx.z, h = blockIdx.y;
    int m0 = blockIdx.x * 64;
    int tid = threadIdx.x;
    int tx = tid & 15, ty = tid >> 4;
    size_t base = (size_t)b * S * N3;
    int hd = h * DHD;
    const float* gb = gate ? (gate + (size_t)b * D_ + hd) : nullptr;
    const float inv_s = 0.088388347648318447f;
    const float NEGS  = -1e9f * 0.088388347648318447f;

    {
        int r = tid >> 2;
        int d0 = (tid & 3) << 2;
        #pragma unroll
        for (int it = 0; it < 8; it++) {
            int d = d0 + it * 16;
            float4 qv = *(const float4*)(qkv + base + (size_t)(m0 + r) * N3 + D_ + hd + d);
            if (gb) { qv.x *= gb[d]; qv.y *= gb[d + 1]; qv.z *= gb[d + 2]; qv.w *= gb[d + 3]; }
            Qs[d + 0][r] = qv.x; Qs[d + 1][r] = qv.y; Qs[d + 2][r] = qv.z; Qs[d + 3][r] = qv.w;
        }
    }
    if (tid < 64) { rowm[tid] = -1e30f; rowl[tid] = 0.f; }

    ull o[4][4];
    #pragma unroll
    for (int i = 0; i < 4; i++)
        #pragma unroll
        for (int j = 0; j < 4; j++) o[i][j] = 0ull;

    int nTiles = (T + 63) / 64;
    for (int kt = 0; kt < nTiles; kt++) {
        int t0 = kt * 64;
        __syncthreads();
        {
            int r = tid >> 2;
            int d0 = (tid & 3) << 2;
            int t = t0 + r;
            #pragma unroll
            for (int it = 0; it < 8; it++) {
                int d = d0 + it * 16;
                float4 kv = make_float4(0.f, 0.f, 0.f, 0.f);
                if (t < T) {
                    if (hasMem && t == 0) {
                        float4 mk = *(const float4*)(memk + hd + d);
                        kv.x = 32.f * mk.x; kv.y = 32.f * mk.y; kv.z = 32.f * mk.z; kv.w = 32.f * mk.w;
                    } else {
                        kv = *(const float4*)(qkv + base + (size_t)(t - hasMem) * N3 + hd + d);
                    }
                    if (gb) { kv.x *= gb[d]; kv.y *= gb[d + 1]; kv.z *= gb[d + 2]; kv.w *= gb[d + 3]; }
                }
                Ks[d + 0][r] = kv.x; Ks[d + 1][r] = kv.y; Ks[d + 2][r] = kv.z; Ks[d + 3][r] = kv.w;
            }
            #pragma unroll
            for (int it = 0; it < 8; it++) {
                int d = d0 + it * 16;
                float4 vv = make_float4(0.f, 0.f, 0.f, 0.f);
                if (t < T) {
                    if (hasMem && t == 0) vv = *(const float4*)(memv + hd + d);
                    else vv = *(const float4*)(qkv + base + (size_t)(t - hasMem) * N3 + 2 * D_ + hd + d);
                }
                *(float4*)&Vs[r][d] = vv;
            }
        }
        if (tid < 64) {
            int t = t0 + tid;
            float mv = 0.f;
            if (t < T) mv = (hasMem && t == 0) ? 1.f : mask[(size_t)b * S + (t - hasMem)];
            km[tid] = mv;
        }
        __syncthreads();

        ull sacc[4][2];
        #pragma unroll
        for (int i = 0; i < 4; i++) { sacc[i][0] = 0ull; sacc[i][1] = 0ull; }
        #pragma unroll 8
        for (int d = 0; d < DHD; d++) {
            float4 aq = *(const float4*)&Qs[d][ty * 4];
            float4 bk = *(const float4*)&Ks[d][tx * 4];
            ull bp0 = pack2(bk.x, bk.y), bp1 = pack2(bk.z, bk.w);
            float a[4] = { aq.x, aq.y, aq.z, aq.w };
            #pragma unroll
            for (int i = 0; i < 4; i++) {
                ull ad = pack2(a[i], a[i]);
                sacc[i][0] = ffma2(ad, bp0, sacc[i][0]);
                sacc[i][1] = ffma2(ad, bp1, sacc[i][1]);
            }
        }
        #pragma unroll
        for (int i = 0; i < 4; i++) {
            int r = ty * 4 + i;
            #pragma unroll
            for (int j2 = 0; j2 < 2; j2++) {
                float x0, x1; unpack2(sacc[i][j2], x0, x1);
                int tl = tx * 4 + j2 * 2;
                Ss[r][tl]     = (km[tl]     != 0.f) ? x0 * inv_s : NEGS;
                Ss[r][tl + 1] = (km[tl + 1] != 0.f) ? x1 * inv_s : NEGS;
            }
        }
        __syncthreads();

        if (tid < 64) {
            float mprev = rowm[tid];
            float mx = mprev;
            #pragma unroll 8
            for (int t = 0; t < 64; t++) mx = fmaxf(mx, Ss[tid][t]);
            float corr = __expf(mprev - mx);
            float ssum = 0.f;
            #pragma unroll 8
            for (int t = 0; t < 64; t++) {
                float p = __expf(Ss[tid][t] - mx);
                Ss[tid][t] = p;
                ssum += p;
            }
            rowl[tid] = rowl[tid] * corr + ssum;
            rowm[tid] = mx;
            rowc[tid] = corr;
        }
        __syncthreads();

        #pragma unroll
        for (int i = 0; i < 4; i++) {
            float cr = rowc[ty * 4 + i];
            ull cd = pack2(cr, cr);
            #pragma unroll
            for (int j = 0; j < 4; j++) o[i][j] = fmul2(o[i][j], cd);
        }
        #pragma unroll 8
        for (int t = 0; t < 64; t++) {
            float4 v0 = *(const float4*)&Vs[t][tx * 8];
            float4 v1 = *(const float4*)&Vs[t][tx * 8 + 4];
            ull vp0 = pack2(v0.x, v0.y), vp1 = pack2(v0.z, v0.w);
            ull vp2 = pack2(v1.x, v1.y), vp3 = pack2(v1.z, v1.w);
            #pragma unroll
            for (int i = 0; i < 4; i++) {
                float p = Ss[ty * 4 + i][t];
                ull pd = pack2(p, p);
                o[i][0] = ffma2(pd, vp0, o[i][0]);
                o[i][1] = ffma2(pd, vp1, o[i][1]);
                o[i][2] = ffma2(pd, vp2, o[i][2]);
                o[i][3] = ffma2(pd, vp3, o[i][3]);
            }
        }
    }
    __syncthreads();

    #pragma unroll
    for (int i = 0; i < 4; i++) {
        int m = m0 + ty * 4 + i;
        float invl = 1.f / rowl[ty * 4 + i];
        float* op = upd + (size_t)(b * S + m) * D_ + hd + tx * 8;
        #pragma unroll
        for (int j = 0; j < 4; j++) {
            float x0, x1; unpack2(o[i][j], x0, x1);
            float2 r2; r2.x = x0 * invl; r2.y = x1 * invl;
            *(float2*)&op[j * 2] = r2;
        }
    }
}

// ---------------- launch ----------------
extern "C" void kernel_launch(void* const* d_in, const int* in_sizes, int n_in,
                              void* d_out, int out_size) {
    const float* v      = (const float*)d_in[0];
    const float* q      = (const float*)d_in[1];
    const float* c      = (const float*)d_in[2];
    const float* v_mask = (const float*)d_in[3];
    const float* q_mask = (const float*)d_in[4];
    const float* c_mask = (const float*)d_in[5];
    const float* Wv4q   = (const float*)d_in[6];
    const float* bv4q   = (const float*)d_in[7];
    const float* Wq4v   = (const float*)d_in[8];
    const float* bq4v   = (const float*)d_in[9];
    const float* Wv     = (const float*)d_in[10];
    const float* bv     = (const float*)d_in[11];
    const float* Wq     = (const float*)d_in[12];
    const float* bq     = (const float*)d_in[13];
    const float* Wc     = (const float*)d_in[14];
    const float* bcin   = (const float*)d_in[15];
    const float* m_v_k  = (const float*)d_in[16];
    const float* m_v_v  = (const float*)d_in[17];
    const float* m_c_k  = (const float*)d_in[18];
    const float* m_c_v  = (const float*)d_in[19];
    const float* Wvo    = (const float*)d_in[20];
    const float* bvo    = (const float*)d_in[21];
    const float* Wqo    = (const float*)d_in[22];
    const float* bqo    = (const float*)d_in[23];
    const float* Wco    = (const float*)d_in[24];
    const float* bco    = (const float*)d_in[25];
    (void)in_sizes; (void)n_in; (void)out_size;

    float *qkv_v, *qkv_q, *qkv_c, *upd_v, *upd_q, *upd_c;
    float *gv4q, *gq4v, *mnv, *mnq, *iv, *iq;
    __nv_bfloat16 *ahi_v, *alo_v, *ahi_q, *alo_q, *ahi_c, *alo_c, *wthi, *wtlo;
    cudaGetSymbolAddress((void**)&qkv_v, g_qkv_v);
    cudaGetSymbolAddress((void**)&qkv_q, g_qkv_q);
    cudaGetSymbolAddress((void**)&qkv_c, g_qkv_c);
    cudaGetSymbolAddress((void**)&upd_v, g_upd_v);
    cudaGetSymbolAddress((void**)&upd_q, g_upd_q);
    cudaGetSymbolAddress((void**)&upd_c, g_upd_c);
    cudaGetSymbolAddress((void**)&gv4q,  g_gate_v4q);
    cudaGetSymbolAddress((void**)&gq4v,  g_gate_q4v);
    cudaGetSymbolAddress((void**)&mnv,   g_mean_v);
    cudaGetSymbolAddress((void**)&mnq,   g_mean_q);
    cudaGetSymbolAddress((void**)&iv,    g_inv_v);
    cudaGetSymbolAddress((void**)&iq,    g_inv_q);
    cudaGetSymbolAddress((void**)&ahi_v, g_ahi_v);
    cudaGetSymbolAddress((void**)&alo_v, g_alo_v);
    cudaGetSymbolAddress((void**)&ahi_q, g_ahi_q);
    cudaGetSymbolAddress((void**)&alo_q, g_alo_q);
    cudaGetSymbolAddress((void**)&ahi_c, g_ahi_c);
    cudaGetSymbolAddress((void**)&alo_c, g_alo_c);
    cudaGetSymbolAddress((void**)&wthi,  g_wthi);
    cudaGetSymbolAddress((void**)&wtlo,  g_wtlo);

    cudaFuncSetAttribute(attn_kernel, cudaFuncAttributeMaxDynamicSharedMemorySize,
                         (int)ATTN_SMEM_BYTES);
    cudaFuncSetAttribute(mma_gemm_kernel<true>,  cudaFuncAttributeMaxDynamicSharedMemorySize, MMA_SMEM_BYTES);
    cudaFuncSetAttribute(mma_gemm_kernel<false>, cudaFuncAttributeMaxDynamicSharedMemorySize, MMA_SMEM_BYTES);

    const size_t WO_V = 0, WO_Q = 3145728, WO_C = 6291456;
    const size_t WO_VO = 9437184, WO_QO = 10485760, WO_CO = 11534336;

    // weight transpose+split
    dim3 wtb(32, 8);
    split_wT_kernel<<<dim3(N3 / 32, 32), wtb>>>(Wv, wthi + WO_V, wtlo + WO_V, N3);
    split_wT_kernel<<<dim3(N3 / 32, 32), wtb>>>(Wq, wthi + WO_Q, wtlo + WO_Q, N3);
    split_wT_kernel<<<dim3(N3 / 32, 32), wtb>>>(Wc, wthi + WO_C, wtlo + WO_C, N3);
    split_wT_kernel<<<dim3(D_ / 32, 32), wtb>>>(Wvo, wthi + WO_VO, wtlo + WO_VO, D_);
    split_wT_kernel<<<dim3(D_ / 32, 32), wtb>>>(Wqo, wthi + WO_QO, wtlo + WO_QO, D_);
    split_wT_kernel<<<dim3(D_ / 32, 32), wtb>>>(Wco, wthi + WO_CO, wtlo + WO_CO, D_);
    // activation relu + split
    split_act_kernel<<<16384, 256>>>(v, nullptr, ahi_v, alo_v, 1, 0);
    split_act_kernel<<<8192,  256>>>(q, nullptr, ahi_q, alo_q, 1, 0);
    split_act_kernel<<<16384, 256>>>(c, nullptr, ahi_c, alo_c, 1, 0);
    // mask sums, means, gates
    masksum_kernel<<<B_, 256>>>(v_mask, iv, SV);
    masksum_kernel<<<B_, 256>>>(q_mask, iq, SQ);
    mean_relu_kernel<<<dim3(4, B_), 256>>>(v, v_mask, iv, mnv, SV);
    mean_relu_kernel<<<dim3(4, B_), 256>>>(q, q_mask, iq, mnq, SQ);
    gate_kernel<<<dim3(8, B_), 128>>>(mnv, Wv4q, bv4q, gv4q);
    gate_kernel<<<dim3(8, B_), 128>>>(mnq, Wq4v, bq4v, gq4v);
    // QKV projections on tensor cores (mma.sync)
    mma_gemm_kernel<true><<<dim3(24, 128), 256, MMA_SMEM_BYTES>>>(
        ahi_v, alo_v, wthi + WO_V, wtlo + WO_V, bv, v_mask, qkv_v, N3);
    mma_gemm_kernel<true><<<dim3(24, 64), 256, MMA_SMEM_BYTES>>>(
        ahi_q, alo_q, wthi + WO_Q, wtlo + WO_Q, bq, q_mask, qkv_q, N3);
    mma_gemm_kernel<true><<<dim3(24, 128), 256, MMA_SMEM_BYTES>>>(
        ahi_c, alo_c, wthi + WO_C, wtlo + WO_C, bcin, c_mask, qkv_c, N3);
    // attention
    attn_kernel<<<dim3(SV / 64, H_, B_), 256, ATTN_SMEM_BYTES>>>(qkv_v, gq4v, m_v_k, m_v_v, v_mask, upd_v, SV, SV + 1, 1);
    attn_kernel<<<dim3(SQ / 64, H_, B_), 256, ATTN_SMEM_BYTES>>>(qkv_q, gv4q, nullptr, nullptr, q_mask, upd_q, SQ, SQ, 0);
    attn_kernel<<<dim3(SC / 64, H_, B_), 256, ATTN_SMEM_BYTES>>>(qkv_c, nullptr, m_c_k, m_c_v, c_mask, upd_c, SC, SC + 1, 1);
    // residual add + split for output projections (reuse act buffers)
    split_act_kernel<<<16384, 256>>>(v, upd_v, ahi_v, alo_v, 0, 1);
    split_act_kernel<<<8192,  256>>>(q, upd_q, ahi_q, alo_q, 0, 1);
    split_act_kernel<<<16384, 256>>>(c, upd_c, ahi_c, alo_c, 0, 1);
    // output projections on tensor cores
    float* out = (float*)d_out;
    mma_gemm_kernel<false><<<dim3(8, 128), 256, MMA_SMEM_BYTES>>>(
        ahi_v, alo_v, wthi + WO_VO, wtlo + WO_VO, bvo, nullptr, out, D_);
    mma_gemm_kernel<false><<<dim3(8, 64), 256, MMA_SMEM_BYTES>>>(
        ahi_q, alo_q, wthi + WO_QO, wtlo + WO_QO, bqo, nullptr, out + (size_t)B_ * SV * D_, D_);
    mma_gemm_kernel<false><<<dim3(8, 128), 256, MMA_SMEM_BYTES>>>(
        ahi_c, alo_c, wthi + WO_CO, wtlo + WO_CO, bco, nullptr, out + (size_t)B_ * (SV + SQ) * D_, D_);
}

// round 4
// speedup vs baseline: 3.1184x; 1.9788x over previous
#include <cuda_runtime.h>
#include <cuda_bf16.h>
#include <cstdint>

#define B_   32
#define SV   512
#define SQ   256
#define SC   512
#define D_   1024
#define H_   8
#define DHD  128
#define N3   3072
#define GK   1024

// ---------------- scratch (device globals; no allocations allowed) ----------------
__device__ float g_upd_v[16777216];   // [32*512, 1024]
__device__ float g_upd_q[8388608];
__device__ float g_upd_c[16777216];
__device__ float g_gate_v4q[32768];
__device__ float g_gate_q4v[32768];
__device__ float g_mean_v[32768];
__device__ float g_mean_q[32768];
__device__ float g_inv_v[32];
__device__ float g_inv_q[32];

// bf16 hi/lo split activations + weights for GEMMs
__device__ __nv_bfloat16 g_ahi_v[16777216];
__device__ __nv_bfloat16 g_alo_v[16777216];
__device__ __nv_bfloat16 g_ahi_q[8388608];
__device__ __nv_bfloat16 g_alo_q[8388608];
__device__ __nv_bfloat16 g_ahi_c[16777216];
__device__ __nv_bfloat16 g_alo_c[16777216];
__device__ __nv_bfloat16 g_wthi[12582912];
__device__ __nv_bfloat16 g_wtlo[12582912];

// bf16 hi/lo K/Q/V in [B,H,T,dh] layout (gates + mask pre-applied; mem token at t=0)
__device__ __nv_bfloat16 g_vKh[16809984], g_vKl[16809984];
__device__ __nv_bfloat16 g_vQh[16777216], g_vQl[16777216];
__device__ __nv_bfloat16 g_vVh[16809984], g_vVl[16809984];
__device__ __nv_bfloat16 g_qKh[8388608],  g_qKl[8388608];
__device__ __nv_bfloat16 g_qQh[8388608],  g_qQl[8388608];
__device__ __nv_bfloat16 g_qVh[8388608],  g_qVl[8388608];
__device__ __nv_bfloat16 g_cKh[16809984], g_cKl[16809984];
__device__ __nv_bfloat16 g_cQh[16777216], g_cQl[16777216];
__device__ __nv_bfloat16 g_cVh[16809984], g_cVl[16809984];

// ---------------- base-target tensor helpers ----------------
__device__ __forceinline__ uint32_t smem_u32(const void* p) {
    uint32_t a;
    asm("{ .reg .u64 t; cvta.to.shared.u64 t, %1; cvt.u32.u64 %0, t; }" : "=r"(a) : "l"(p));
    return a;
}
__device__ __forceinline__ void cp16(uint32_t dst, const void* src) {
    asm volatile("cp.async.cg.shared.global [%0], [%1], 16;" :: "r"(dst), "l"(src));
}
__device__ __forceinline__ void cp16z(uint32_t dst, const void* src, int sz) {
    asm volatile("cp.async.cg.shared.global [%0], [%1], 16, %2;" :: "r"(dst), "l"(src), "r"(sz));
}
__device__ __forceinline__ void cp_commit() { asm volatile("cp.async.commit_group;" ::: "memory"); }
__device__ __forceinline__ void cp_wait1()  { asm volatile("cp.async.wait_group 1;" ::: "memory"); }
__device__ __forceinline__ void cp_wait0()  { asm volatile("cp.async.wait_group 0;" ::: "memory"); }

__device__ __forceinline__ void ldmx4(uint32_t* r, uint32_t addr) {
    asm volatile("ldmatrix.sync.aligned.m8n8.x4.shared.b16 {%0,%1,%2,%3}, [%4];"
                 : "=r"(r[0]), "=r"(r[1]), "=r"(r[2]), "=r"(r[3]) : "r"(addr));
}
__device__ __forceinline__ void ldmx4t(uint32_t* r, uint32_t addr) {
    asm volatile("ldmatrix.sync.aligned.m8n8.x4.trans.shared.b16 {%0,%1,%2,%3}, [%4];"
                 : "=r"(r[0]), "=r"(r[1]), "=r"(r[2]), "=r"(r[3]) : "r"(addr));
}
__device__ __forceinline__ void mma16816(float* d, const uint32_t* a, uint32_t b0, uint32_t b1) {
    asm volatile("mma.sync.aligned.m16n8k16.row.col.f32.bf16.bf16.f32 "
                 "{%0,%1,%2,%3}, {%4,%5,%6,%7}, {%8,%9}, {%0,%1,%2,%3};"
                 : "+f"(d[0]), "+f"(d[1]), "+f"(d[2]), "+f"(d[3])
                 : "r"(a[0]), "r"(a[1]), "r"(a[2]), "r"(a[3]), "r"(b0), "r"(b1));
}

// ---------------- hi/lo split helpers ----------------
__device__ __forceinline__ void split1(float v, unsigned short& h, unsigned short& l) {
    __nv_bfloat16 hb = __float2bfloat16_rn(v);
    __nv_bfloat16 lb = __float2bfloat16_rn(v - __bfloat162float(hb));
    h = __bfloat16_as_ushort(hb);
    l = __bfloat16_as_ushort(lb);
}
__device__ __forceinline__ void store_hl(__nv_bfloat16* H, __nv_bfloat16* L, size_t idx,
                                         float x, float y) {
    __nv_bfloat162 h2 = __floats2bfloat162_rn(x, y);
    __nv_bfloat162 l2 = __floats2bfloat162_rn(x - __bfloat162float(h2.x),
                                              y - __bfloat162float(h2.y));
    *(__nv_bfloat162*)(H + idx) = h2;
    *(__nv_bfloat162*)(L + idx) = l2;
}
__device__ __forceinline__ void fsplit2(float x, float y, uint32_t& hi, uint32_t& lo) {
    __nv_bfloat162 h2 = __floats2bfloat162_rn(x, y);
    __nv_bfloat162 l2 = __floats2bfloat162_rn(x - __bfloat162float(h2.x),
                                              y - __bfloat162float(h2.y));
    hi = *(uint32_t*)&h2; lo = *(uint32_t*)&l2;
}

// ---------------- conversion kernels ----------------
__global__ void split_act_kernel(const float* __restrict__ x, const float* __restrict__ x2,
                                 __nv_bfloat16* __restrict__ hi, __nv_bfloat16* __restrict__ lo,
                                 int relu, int add) {
    int idx = blockIdx.x * 256 + threadIdx.x;
    float4 v = ((const float4*)x)[idx];
    if (add) {
        float4 w = ((const float4*)x2)[idx];
        v.x += w.x; v.y += w.y; v.z += w.z; v.w += w.w;
    }
    if (relu) {
        v.x = fmaxf(v.x, 0.f); v.y = fmaxf(v.y, 0.f);
        v.z = fmaxf(v.z, 0.f); v.w = fmaxf(v.w, 0.f);
    }
    unsigned short h0,h1,h2,h3,l0,l1,l2,l3;
    split1(v.x,h0,l0); split1(v.y,h1,l1); split1(v.z,h2,l2); split1(v.w,h3,l3);
    uint2 hv, lv;
    hv.x = ((uint32_t)h1 << 16) | h0; hv.y = ((uint32_t)h3 << 16) | h2;
    lv.x = ((uint32_t)l1 << 16) | l0; lv.y = ((uint32_t)l3 << 16) | l2;
    ((uint2*)hi)[idx] = hv;
    ((uint2*)lo)[idx] = lv;
}

__global__ void split_wT_kernel(const float* __restrict__ W,
                                __nv_bfloat16* __restrict__ thi, __nv_bfloat16* __restrict__ tlo,
                                int N) {
    __shared__ float t[32][33];
    int n0 = blockIdx.x * 32, k0 = blockIdx.y * 32;
    int tx = threadIdx.x, ty = threadIdx.y;
    #pragma unroll
    for (int r = 0; r < 4; r++)
        t[ty + 8 * r][tx] = W[(size_t)(k0 + ty + 8 * r) * N + n0 + tx];
    __syncthreads();
    #pragma unroll
    for (int r = 0; r < 4; r++) {
        float v = t[tx][ty + 8 * r];
        unsigned short h, l; split1(v, h, l);
        size_t o = (size_t)(n0 + ty + 8 * r) * GK + k0 + tx;
        thi[o] = __ushort_as_bfloat16(h);
        tlo[o] = __ushort_as_bfloat16(l);
    }
}

// ---------------- small kernels ----------------
__global__ void masksum_kernel(const float* __restrict__ mask, float* __restrict__ inv, int S) {
    __shared__ float red[256];
    int b = blockIdx.x;
    float s = 0.f;
    for (int t = threadIdx.x; t < S; t += 256) s += mask[(size_t)b * S + t];
    red[threadIdx.x] = s;
    __syncthreads();
    for (int w = 128; w > 0; w >>= 1) {
        if (threadIdx.x < w) red[threadIdx.x] += red[threadIdx.x + w];
        __syncthreads();
    }
    if (threadIdx.x == 0) inv[b] = 1.f / red[0];
}

__global__ void mean_relu_kernel(const float* __restrict__ x, const float* __restrict__ mask,
                                 const float* __restrict__ inv, float* __restrict__ out, int S) {
    int b = blockIdx.y;
    int d = blockIdx.x * 256 + threadIdx.x;
    const float* xp = x + (size_t)b * S * D_ + d;
    const float* mp = mask + (size_t)b * S;
    float s = 0.f;
    for (int t = 0; t < S; t++) s += xp[(size_t)t * D_] * mp[t];
    out[b * D_ + d] = fmaxf(s * inv[b], 0.f);
}

__global__ void gate_kernel(const float* __restrict__ rmean, const float* __restrict__ W,
                            const float* __restrict__ bias, float* __restrict__ out) {
    __shared__ float sm[D_];
    int b = blockIdx.y;
    int n = blockIdx.x * 128 + threadIdx.x;
    for (int k = threadIdx.x; k < D_; k += 128) sm[k] = rmean[b * D_ + k];
    __syncthreads();
    float acc = bias[n];
    #pragma unroll 8
    for (int k = 0; k < D_; k++) acc = fmaf(sm[k], W[(size_t)k * D_ + n], acc);
    out[b * D_ + n] = 1.f + 1.f / (1.f + __expf(-acc));
}

// mem token at t=0: K = 32*memk (gated if gate), V = memv
__global__ void memtok_kernel(__nv_bfloat16* Kh, __nv_bfloat16* Kl,
                              __nv_bfloat16* Vh, __nv_bfloat16* Vl,
                              const float* __restrict__ memk, const float* __restrict__ memv,
                              const float* __restrict__ gate, int T) {
    int b = blockIdx.x;
    int i = threadIdx.x;     // 0..1023
    int h = i >> 7;
    float kv = 32.f * memk[i];
    if (gate) kv *= gate[b * D_ + i];
    float vv = memv[i];
    size_t idx = ((size_t)(b * H_ + h) * T) * DHD + (i & 127);
    unsigned short hb, lb;
    split1(kv, hb, lb); Kh[idx] = __ushort_as_bfloat16(hb); Kl[idx] = __ushort_as_bfloat16(lb);
    split1(vv, hb, lb); Vh[idx] = __ushort_as_bfloat16(hb); Vl[idx] = __ushort_as_bfloat16(lb);
}

// ---------------- mma.sync bf16x3 GEMM ----------------
// 128x128 tile, BK=32, 8 warps (4x2), cp.async double buffer.
// SPLIT mode: epilogue writes gated/masked bf16 hi/lo K/Q/V in [B,H,T,dh] layout.
#define ROWB 40
#define MAT_BYTES (128 * ROWB * 2)
#define STAGE_BYTES (4 * MAT_BYTES)
#define MMA_SMEM_BYTES (2 * STAGE_BYTES)

template <bool MASK, bool SPLIT>
__global__ __launch_bounds__(256, 2) void mma_gemm_kernel(
    const __nv_bfloat16* __restrict__ Ahi, const __nv_bfloat16* __restrict__ Alo,
    const __nv_bfloat16* __restrict__ Bhi, const __nv_bfloat16* __restrict__ Blo,
    const float* __restrict__ bias, const float* __restrict__ mask,
    float* __restrict__ C, int N,
    const float* __restrict__ gate,
    __nv_bfloat16* oKh, __nv_bfloat16* oKl,
    __nv_bfloat16* oQh, __nv_bfloat16* oQl,
    __nv_bfloat16* oVh, __nv_bfloat16* oVl,
    int S, int T, int hasMem)
{
    extern __shared__ char smem[];
    uint32_t sbase = smem_u32(smem);
    int tid = threadIdx.x;
    int wid = tid >> 5, lane = tid & 31;
    int bm = blockIdx.y * 128, bn = blockIdx.x * 128;
    int wm = (wid & 3) * 32;
    int wn = (wid >> 2) * 64;

    const __nv_bfloat16* srcs[4] = {
        Ahi + (size_t)bm * GK, Alo + (size_t)bm * GK,
        Bhi + (size_t)bn * GK, Blo + (size_t)bn * GK };

    float acc[2][8][4];
    #pragma unroll
    for (int i = 0; i < 2; i++)
        #pragma unroll
        for (int j = 0; j < 8; j++)
            #pragma unroll
            for (int k = 0; k < 4; k++) acc[i][j][k] = 0.f;

    int lrow = tid >> 2, lc = (tid & 3);
    auto load_stage = [&](int kc, int s) {
        uint32_t st = sbase + s * STAGE_BYTES;
        int k0 = kc * 32;
        #pragma unroll
        for (int m = 0; m < 4; m++) {
            const __nv_bfloat16* src = srcs[m];
            uint32_t dst = st + m * MAT_BYTES;
            #pragma unroll
            for (int it = 0; it < 2; it++) {
                int row = lrow + it * 64;
                cp16(dst + row * 80 + lc * 16, src + (size_t)row * GK + k0 + lc * 8);
            }
        }
        cp_commit();
    };

    load_stage(0, 0);

    const int NK = GK / 32;
    for (int kc = 0; kc < NK; kc++) {
        if (kc + 1 < NK) { load_stage(kc + 1, (kc + 1) & 1); cp_wait1(); }
        else cp_wait0();
        __syncthreads();
        uint32_t st  = sbase + (kc & 1) * STAGE_BYTES;
        uint32_t sAh = st, sAl = st + MAT_BYTES;
        uint32_t sBh = st + 2 * MAT_BYTES, sBl = st + 3 * MAT_BYTES;
        #pragma unroll
        for (int ks = 0; ks < 32; ks += 16) {
            uint32_t ah[2][4], al[2][4];
            int arow = wm + (lane & 15);
            int ak = ks + ((lane >> 4) << 3);
            #pragma unroll
            for (int mt = 0; mt < 2; mt++) {
                uint32_t off = (uint32_t)(((arow + mt * 16) * ROWB + ak) * 2);
                ldmx4(ah[mt], sAh + off);
                ldmx4(al[mt], sAl + off);
            }
            int r = lane & 7, qsel = lane >> 3;
            #pragma unroll
            for (int pr = 0; pr < 4; pr++) {
                int nn = wn + pr * 16 + ((qsel >> 1) << 3) + r;
                int kk = ks + ((qsel & 1) << 3);
                uint32_t off = (uint32_t)((nn * ROWB + kk) * 2);
                uint32_t bh[4], bl[4];
                ldmx4(bh, sBh + off);
                ldmx4(bl, sBl + off);
                #pragma unroll
                for (int mt = 0; mt < 2; mt++) {
                    #pragma unroll
                    for (int hf = 0; hf < 2; hf++) {
                        float* d = acc[mt][pr * 2 + hf];
                        mma16816(d, ah[mt], bh[hf * 2], bh[hf * 2 + 1]);
                        mma16816(d, ah[mt], bl[hf * 2], bl[hf * 2 + 1]);
                        mma16816(d, al[mt], bh[hf * 2], bh[hf * 2 + 1]);
                    }
                }
            }
        }
        __syncthreads();
    }

    if (!SPLIT) {
        #pragma unroll
        for (int mt = 0; mt < 2; mt++) {
            int r0 = bm + wm + mt * 16 + (lane >> 2);
            float m0 = MASK ? mask[r0] : 1.f;
            float m1 = MASK ? mask[r0 + 8] : 1.f;
            #pragma unroll
            for (int nt = 0; nt < 8; nt++) {
                int col = bn + wn + nt * 8 + ((lane & 3) << 1);
                float2 bb = *(const float2*)&bias[col];
                float2 o0, o1;
                o0.x = (acc[mt][nt][0] + bb.x) * m0; o0.y = (acc[mt][nt][1] + bb.y) * m0;
                o1.x = (acc[mt][nt][2] + bb.x) * m1; o1.y = (acc[mt][nt][3] + bb.y) * m1;
                *(float2*)(C + (size_t)r0 * N + col) = o0;
                *(float2*)(C + (size_t)(r0 + 8) * N + col) = o1;
            }
        }
    } else {
        int colbase = bn + wn;              // 64-aligned; tile stays in one part/head
        int part = colbase >> 10;           // 0=k, 1=q, 2=v
        int hh = (colbase & 1023) >> 7;
        int dwarp = colbase & 127;          // 0 or 64
        int b = bm / S;
        int s0 = bm % S;
        size_t bh64 = (size_t)(b * H_ + hh);
        #pragma unroll
        for (int mt = 0; mt < 2; mt++) {
            int rl0 = wm + mt * 16 + (lane >> 2);
            int gr0 = bm + rl0;
            float mk0 = MASK ? mask[gr0] : 1.f;
            float mk1 = MASK ? mask[gr0 + 8] : 1.f;
            int s_0 = s0 + rl0, s_1 = s_0 + 8;
            #pragma unroll
            for (int nt = 0; nt < 8; nt++) {
                int d = dwarp + nt * 8 + ((lane & 3) << 1);
                int col = colbase + nt * 8 + ((lane & 3) << 1);
                float2 bb = *(const float2*)&bias[col];
                float x0 = (acc[mt][nt][0] + bb.x) * mk0;
                float y0 = (acc[mt][nt][1] + bb.y) * mk0;
                float x1 = (acc[mt][nt][2] + bb.x) * mk1;
                float y1 = (acc[mt][nt][3] + bb.y) * mk1;
                if (gate != nullptr && part < 2) {
                    float2 g2 = *(const float2*)&gate[b * D_ + hh * DHD + d];
                    x0 *= g2.x; y0 *= g2.y; x1 *= g2.x; y1 *= g2.y;
                }
                if (part == 0) {
                    size_t i0 = (bh64 * T + (s_0 + hasMem)) * DHD + d;
                    size_t i1 = (bh64 * T + (s_1 + hasMem)) * DHD + d;
                    store_hl(oKh, oKl, i0, x0, y0);
                    store_hl(oKh, oKl, i1, x1, y1);
                } else if (part == 1) {
                    size_t i0 = (bh64 * S + s_0) * DHD + d;
                    size_t i1 = (bh64 * S + s_1) * DHD + d;
                    store_hl(oQh, oQl, i0, x0, y0);
                    store_hl(oQh, oQl, i1, x1, y1);
                } else {
                    size_t i0 = (bh64 * T + (s_0 + hasMem)) * DHD + d;
                    size_t i1 = (bh64 * T + (s_1 + hasMem)) * DHD + d;
                    store_hl(oVh, oVl, i0, x0, y0);
                    store_hl(oVh, oVl, i1, x1, y1);
                }
            }
        }
    }
}

// ---------------- tensor-core flash attention (bf16 hi/lo x3) ----------------
// CTA: 128 q-rows x 1 head x 1 batch, 8 warps x 16 rows. 64-key tiles, double-buffered.
#define APAD 136
constexpr int A_QH  = 0;
constexpr int A_QL  = 128 * APAD * 2;              // 34816
constexpr int A_ST0 = 2 * 128 * APAD * 2;          // 69632
constexpr int A_STG = 4 * 64 * APAD * 2;           // 69632
constexpr int A_KH  = 0;
constexpr int A_KL  = 64 * APAD * 2;               // 17408
constexpr int A_VH  = 2 * 64 * APAD * 2;           // 34816
constexpr int A_VL  = 3 * 64 * APAD * 2;           // 52224
constexpr int A_KM  = A_ST0 + 2 * A_STG;           // 208896
constexpr int ATT_SMEM_BYTES = A_KM + 2 * 64 * 4;  // 209408

__global__ __launch_bounds__(256, 1) void attn_mma_kernel(
    const __nv_bfloat16* __restrict__ Kh, const __nv_bfloat16* __restrict__ Kl,
    const __nv_bfloat16* __restrict__ Qh, const __nv_bfloat16* __restrict__ Ql,
    const __nv_bfloat16* __restrict__ Vh, const __nv_bfloat16* __restrict__ Vl,
    const float* __restrict__ mask, float* __restrict__ upd,
    int S, int T, int hasMem)
{
    extern __shared__ char sm[];
    uint32_t sb = smem_u32(sm);
    float* km = (float*)(sm + A_KM);
    int tid = threadIdx.x, wid = tid >> 5, lane = tid & 31;
    int b = blockIdx.z, h = blockIdx.y, m0 = blockIdx.x * 128;
    size_t bh = (size_t)(b * H_ + h);
    const __nv_bfloat16* gQh = Qh + (bh * S + m0) * DHD;
    const __nv_bfloat16* gQl = Ql + (bh * S + m0) * DHD;
    const __nv_bfloat16* gKV[4] = { Kh + bh * T * DHD, Kl + bh * T * DHD,
                                    Vh + bh * T * DHD, Vl + bh * T * DHD };

    // Q tile load (once)
    #pragma unroll
    for (int it = 0; it < 8; it++) {
        int id = tid + it * 256; int row = id >> 4, cc = id & 15;
        cp16(sb + A_QH + row * (APAD * 2) + cc * 16, gQh + row * DHD + cc * 8);
        cp16(sb + A_QL + row * (APAD * 2) + cc * 16, gQl + row * DHD + cc * 8);
    }
    auto load_kv = [&](int kt, int s) {
        int t0 = kt * 64;
        uint32_t st = sb + A_ST0 + s * A_STG;
        #pragma unroll
        for (int m = 0; m < 4; m++) {
            #pragma unroll
            for (int it = 0; it < 4; it++) {
                int id = tid + it * 256; int row = id >> 4, cc = id & 15;
                int t = t0 + row;
                int tc = (t < T) ? t : (T - 1);
                int sz = (t < T) ? 16 : 0;
                cp16z(st + m * (64 * APAD * 2) + row * (APAD * 2) + cc * 16,
                      gKV[m] + (size_t)tc * DHD + cc * 8, sz);
            }
        }
        if (tid < 64) {
            int t = t0 + tid;
            float mv = 0.f;
            if (t < T) mv = (hasMem && t == 0) ? 1.f : mask[(size_t)b * S + (t - hasMem)];
            km[s * 64 + tid] = mv;
        }
    };

    load_kv(0, 0);
    cp_commit();

    float o[16][4];
    #pragma unroll
    for (int i = 0; i < 16; i++) { o[i][0] = 0.f; o[i][1] = 0.f; o[i][2] = 0.f; o[i][3] = 0.f; }
    float mprev0 = -1e30f, mprev1 = -1e30f, lsum0 = 0.f, lsum1 = 0.f;
    const float SCL  = 0.088388347648318447f;
    const float NEGS = -1e9f * 0.088388347648318447f;
    int wm = wid * 16;
    int ntile = (T + 63) / 64;

    for (int kt = 0; kt < ntile; kt++) {
        if (kt + 1 < ntile) { load_kv(kt + 1, (kt + 1) & 1); cp_commit(); cp_wait1(); }
        else cp_wait0();
        __syncthreads();
        uint32_t st = sb + A_ST0 + (kt & 1) * A_STG;

        // ---- scores S[16 x 64] per warp ----
        float sf[8][4];
        #pragma unroll
        for (int i = 0; i < 8; i++) { sf[i][0]=0.f; sf[i][1]=0.f; sf[i][2]=0.f; sf[i][3]=0.f; }
        #pragma unroll
        for (int ks = 0; ks < 128; ks += 16) {
            int arow = wm + (lane & 15), ak = ks + ((lane >> 4) << 3);
            uint32_t aoff = (uint32_t)(arow * APAD + ak) * 2;
            uint32_t ah[4], al[4];
            ldmx4(ah, sb + A_QH + aoff);
            ldmx4(al, sb + A_QL + aoff);
            int r = lane & 7, qs = lane >> 3;
            #pragma unroll
            for (int pr = 0; pr < 4; pr++) {
                int nn = pr * 16 + ((qs >> 1) << 3) + r;
                int kk2 = ks + ((qs & 1) << 3);
                uint32_t boff = (uint32_t)(nn * APAD + kk2) * 2;
                uint32_t bh4[4], bl4[4];
                ldmx4(bh4, st + A_KH + boff);
                ldmx4(bl4, st + A_KL + boff);
                #pragma unroll
                for (int hf = 0; hf < 2; hf++) {
                    float* d = sf[pr * 2 + hf];
                    mma16816(d, ah, bh4[hf * 2], bh4[hf * 2 + 1]);
                    mma16816(d, ah, bl4[hf * 2], bl4[hf * 2 + 1]);
                    mma16816(d, al, bh4[hf * 2], bh4[hf * 2 + 1]);
                }
            }
        }
        // ---- mask (before scale), scale, online softmax ----
        const float* kmc = km + (kt & 1) * 64;
        float mx0 = mprev0, mx1 = mprev1;
        #pragma unroll
        for (int nt = 0; nt < 8; nt++) {
            int c0 = nt * 8 + ((lane & 3) << 1);
            float k0v = kmc[c0], k1v = kmc[c0 + 1];
            sf[nt][0] = (k0v != 0.f) ? sf[nt][0] * SCL : NEGS;
            sf[nt][1] = (k1v != 0.f) ? sf[nt][1] * SCL : NEGS;
            sf[nt][2] = (k0v != 0.f) ? sf[nt][2] * SCL : NEGS;
            sf[nt][3] = (k1v != 0.f) ? sf[nt][3] * SCL : NEGS;
            mx0 = fmaxf(mx0, fmaxf(sf[nt][0], sf[nt][1]));
            mx1 = fmaxf(mx1, fmaxf(sf[nt][2], sf[nt][3]));
        }
        mx0 = fmaxf(mx0, __shfl_xor_sync(0xffffffffu, mx0, 1));
        mx0 = fmaxf(mx0, __shfl_xor_sync(0xffffffffu, mx0, 2));
        mx1 = fmaxf(mx1, __shfl_xor_sync(0xffffffffu, mx1, 1));
        mx1 = fmaxf(mx1, __shfl_xor_sync(0xffffffffu, mx1, 2));
        float corr0 = __expf(mprev0 - mx0), corr1 = __expf(mprev1 - mx1);
        mprev0 = mx0; mprev1 = mx1;
        float ps0 = 0.f, ps1 = 0.f;
        #pragma unroll
        for (int nt = 0; nt < 8; nt++) {
            sf[nt][0] = __expf(sf[nt][0] - mx0);
            sf[nt][1] = __expf(sf[nt][1] - mx0);
            sf[nt][2] = __expf(sf[nt][2] - mx1);
            sf[nt][3] = __expf(sf[nt][3] - mx1);
            ps0 += sf[nt][0] + sf[nt][1];
            ps1 += sf[nt][2] + sf[nt][3];
        }
        ps0 += __shfl_xor_sync(0xffffffffu, ps0, 1);
        ps0 += __shfl_xor_sync(0xffffffffu, ps0, 2);
        ps1 += __shfl_xor_sync(0xffffffffu, ps1, 1);
        ps1 += __shfl_xor_sync(0xffffffffu, ps1, 2);
        lsum0 = lsum0 * corr0 + ps0;
        lsum1 = lsum1 * corr1 + ps1;
        #pragma unroll
        for (int dd = 0; dd < 16; dd++) {
            o[dd][0] *= corr0; o[dd][1] *= corr0;
            o[dd][2] *= corr1; o[dd][3] *= corr1;
        }
        // ---- PV: O += P @ V ----
        int mi = lane >> 3, rr = lane & 7;
        #pragma unroll
        for (int kk = 0; kk < 4; kk++) {
            uint32_t ph4[4], pl4[4];
            fsplit2(sf[2*kk][0],   sf[2*kk][1],   ph4[0], pl4[0]);
            fsplit2(sf[2*kk][2],   sf[2*kk][3],   ph4[1], pl4[1]);
            fsplit2(sf[2*kk+1][0], sf[2*kk+1][1], ph4[2], pl4[2]);
            fsplit2(sf[2*kk+1][2], sf[2*kk+1][3], ph4[3], pl4[3]);
            #pragma unroll
            for (int db = 0; db < 8; db++) {
                uint32_t voff = (uint32_t)((kk * 16 + (mi & 1) * 8 + rr) * APAD
                                           + db * 16 + (mi >> 1) * 8) * 2;
                uint32_t vh4[4], vl4[4];
                ldmx4t(vh4, st + A_VH + voff);
                ldmx4t(vl4, st + A_VL + voff);
                float* d0 = o[db * 2];
                float* d1 = o[db * 2 + 1];
                mma16816(d0, ph4, vh4[0], vh4[1]);
                mma16816(d0, ph4, vl4[0], vl4[1]);
                mma16816(d0, pl4, vh4[0], vh4[1]);
                mma16816(d1, ph4, vh4[2], vh4[3]);
                mma16816(d1, ph4, vl4[2], vl4[3]);
                mma16816(d1, pl4, vh4[2], vh4[3]);
            }
        }
        __syncthreads();
    }

    float i0 = 1.f / lsum0, i1 = 1.f / lsum1;
    int g = lane >> 2;
    size_t row0 = (size_t)(b * S + m0 + wm + g);
    float* up = upd + row0 * D_ + h * DHD;
    #pragma unroll
    for (int dd = 0; dd < 16; dd++) {
        int d = dd * 8 + ((lane & 3) << 1);
        float2 r0v = { o[dd][0] * i0, o[dd][1] * i0 };
        float2 r1v = { o[dd][2] * i1, o[dd][3] * i1 };
        *(float2*)(up + d) = r0v;
        *(float2*)(up + 8 * D_ + d) = r1v;
    }
}

// ---------------- launch ----------------
extern "C" void kernel_launch(void* const* d_in, const int* in_sizes, int n_in,
                              void* d_out, int out_size) {
    const float* v      = (const float*)d_in[0];
    const float* q      = (const float*)d_in[1];
    const float* c      = (const float*)d_in[2];
    const float* v_mask = (const float*)d_in[3];
    const float* q_mask = (const float*)d_in[4];
    const float* c_mask = (const float*)d_in[5];
    const float* Wv4q   = (const float*)d_in[6];
    const float* bv4q   = (const float*)d_in[7];
    const float* Wq4v   = (const float*)d_in[8];
    const float* bq4v   = (const float*)d_in[9];
    const float* Wv     = (const float*)d_in[10];
    const float* bv     = (const float*)d_in[11];
    const float* Wq     = (const float*)d_in[12];
    const float* bq     = (const float*)d_in[13];
    const float* Wc     = (const float*)d_in[14];
    const float* bcin   = (const float*)d_in[15];
    const float* m_v_k  = (const float*)d_in[16];
    const float* m_v_v  = (const float*)d_in[17];
    const float* m_c_k  = (const float*)d_in[18];
    const float* m_c_v  = (const float*)d_in[19];
    const float* Wvo    = (const float*)d_in[20];
    const float* bvo    = (const float*)d_in[21];
    const float* Wqo    = (const float*)d_in[22];
    const float* bqo    = (const float*)d_in[23];
    const float* Wco    = (const float*)d_in[24];
    const float* bco    = (const float*)d_in[25];
    (void)in_sizes; (void)n_in; (void)out_size;

    float *upd_v, *upd_q, *upd_c, *gv4q, *gq4v, *mnv, *mnq, *iv, *iq;
    __nv_bfloat16 *ahi_v, *alo_v, *ahi_q, *alo_q, *ahi_c, *alo_c, *wthi, *wtlo;
    __nv_bfloat16 *vKh,*vKl,*vQh,*vQl,*vVh,*vVl;
    __nv_bfloat16 *qKh,*qKl,*qQh,*qQl,*qVh,*qVl;
    __nv_bfloat16 *cKh,*cKl,*cQh,*cQl,*cVh,*cVl;
    cudaGetSymbolAddress((void**)&upd_v, g_upd_v);
    cudaGetSymbolAddress((void**)&upd_q, g_upd_q);
    cudaGetSymbolAddress((void**)&upd_c, g_upd_c);
    cudaGetSymbolAddress((void**)&gv4q,  g_gate_v4q);
    cudaGetSymbolAddress((void**)&gq4v,  g_gate_q4v);
    cudaGetSymbolAddress((void**)&mnv,   g_mean_v);
    cudaGetSymbolAddress((void**)&mnq,   g_mean_q);
    cudaGetSymbolAddress((void**)&iv,    g_inv_v);
    cudaGetSymbolAddress((void**)&iq,    g_inv_q);
    cudaGetSymbolAddress((void**)&ahi_v, g_ahi_v);
    cudaGetSymbolAddress((void**)&alo_v, g_alo_v);
    cudaGetSymbolAddress((void**)&ahi_q, g_ahi_q);
    cudaGetSymbolAddress((void**)&alo_q, g_alo_q);
    cudaGetSymbolAddress((void**)&ahi_c, g_ahi_c);
    cudaGetSymbolAddress((void**)&alo_c, g_alo_c);
    cudaGetSymbolAddress((void**)&wthi,  g_wthi);
    cudaGetSymbolAddress((void**)&wtlo,  g_wtlo);
    cudaGetSymbolAddress((void**)&vKh, g_vKh); cudaGetSymbolAddress((void**)&vKl, g_vKl);
    cudaGetSymbolAddress((void**)&vQh, g_vQh); cudaGetSymbolAddress((void**)&vQl, g_vQl);
    cudaGetSymbolAddress((void**)&vVh, g_vVh); cudaGetSymbolAddress((void**)&vVl, g_vVl);
    cudaGetSymbolAddress((void**)&qKh, g_qKh); cudaGetSymbolAddress((void**)&qKl, g_qKl);
    cudaGetSymbolAddress((void**)&qQh, g_qQh); cudaGetSymbolAddress((void**)&qQl, g_qQl);
    cudaGetSymbolAddress((void**)&qVh, g_qVh); cudaGetSymbolAddress((void**)&qVl, g_qVl);
    cudaGetSymbolAddress((void**)&cKh, g_cKh); cudaGetSymbolAddress((void**)&cKl, g_cKl);
    cudaGetSymbolAddress((void**)&cQh, g_cQh); cudaGetSymbolAddress((void**)&cQl, g_cQl);
    cudaGetSymbolAddress((void**)&cVh, g_cVh); cudaGetSymbolAddress((void**)&cVl, g_cVl);

    cudaFuncSetAttribute(mma_gemm_kernel<true, true>,   cudaFuncAttributeMaxDynamicSharedMemorySize, MMA_SMEM_BYTES);
    cudaFuncSetAttribute(mma_gemm_kernel<false, false>, cudaFuncAttributeMaxDynamicSharedMemorySize, MMA_SMEM_BYTES);
    cudaFuncSetAttribute(attn_mma_kernel, cudaFuncAttributeMaxDynamicSharedMemorySize, ATT_SMEM_BYTES);

    const size_t WO_V = 0, WO_Q = 3145728, WO_C = 6291456;
    const size_t WO_VO = 9437184, WO_QO = 10485760, WO_CO = 11534336;

    // weight transpose + split
    dim3 wtb(32, 8);
    split_wT_kernel<<<dim3(N3 / 32, 32), wtb>>>(Wv, wthi + WO_V, wtlo + WO_V, N3);
    split_wT_kernel<<<dim3(N3 / 32, 32), wtb>>>(Wq, wthi + WO_Q, wtlo + WO_Q, N3);
    split_wT_kernel<<<dim3(N3 / 32, 32), wtb>>>(Wc, wthi + WO_C, wtlo + WO_C, N3);
    split_wT_kernel<<<dim3(D_ / 32, 32), wtb>>>(Wvo, wthi + WO_VO, wtlo + WO_VO, D_);
    split_wT_kernel<<<dim3(D_ / 32, 32), wtb>>>(Wqo, wthi + WO_QO, wtlo + WO_QO, D_);
    split_wT_kernel<<<dim3(D_ / 32, 32), wtb>>>(Wco, wthi + WO_CO, wtlo + WO_CO, D_);
    // activation relu + split
    split_act_kernel<<<16384, 256>>>(v, nullptr, ahi_v, alo_v, 1, 0);
    split_act_kernel<<<8192,  256>>>(q, nullptr, ahi_q, alo_q, 1, 0);
    split_act_kernel<<<16384, 256>>>(c, nullptr, ahi_c, alo_c, 1, 0);
    // masked means -> gates
    masksum_kernel<<<B_, 256>>>(v_mask, iv, SV);
    masksum_kernel<<<B_, 256>>>(q_mask, iq, SQ);
    mean_relu_kernel<<<dim3(4, B_), 256>>>(v, v_mask, iv, mnv, SV);
    mean_relu_kernel<<<dim3(4, B_), 256>>>(q, q_mask, iq, mnq, SQ);
    gate_kernel<<<dim3(8, B_), 128>>>(mnv, Wv4q, bv4q, gv4q);
    gate_kernel<<<dim3(8, B_), 128>>>(mnq, Wq4v, bq4v, gq4v);
    // memory tokens (t=0); v-stream K gated by q4v, c ungated
    memtok_kernel<<<B_, 1024>>>(vKh, vKl, vVh, vVl, m_v_k, m_v_v, gq4v, SV + 1);
    memtok_kernel<<<B_, 1024>>>(cKh, cKl, cVh, cVl, m_c_k, m_c_v, nullptr, SC + 1);
    // QKV projections -> fused gated bf16 hi/lo split K/Q/V
    mma_gemm_kernel<true, true><<<dim3(24, 128), 256, MMA_SMEM_BYTES>>>(
        ahi_v, alo_v, wthi + WO_V, wtlo + WO_V, bv, v_mask, nullptr, 0,
        gq4v, vKh, vKl, vQh, vQl, vVh, vVl, SV, SV + 1, 1);
    mma_gemm_kernel<true, true><<<dim3(24, 64), 256, MMA_SMEM_BYTES>>>(
        ahi_q, alo_q, wthi + WO_Q, wtlo + WO_Q, bq, q_mask, nullptr, 0,
        gv4q, qKh, qKl, qQh, qQl, qVh, qVl, SQ, SQ, 0);
    mma_gemm_kernel<true, true><<<dim3(24, 128), 256, MMA_SMEM_BYTES>>>(
        ahi_c, alo_c, wthi + WO_C, wtlo + WO_C, bcin, c_mask, nullptr, 0,
        nullptr, cKh, cKl, cQh, cQl, cVh, cVl, SC, SC + 1, 1);
    // tensor-core flash attention
    attn_mma_kernel<<<dim3(SV / 128, H_, B_), 256, ATT_SMEM_BYTES>>>(
        vKh, vKl, vQh, vQl, vVh, vVl, v_mask, upd_v, SV, SV + 1, 1);
    attn_mma_kernel<<<dim3(SQ / 128, H_, B_), 256, ATT_SMEM_BYTES>>>(
        qKh, qKl, qQh, qQl, qVh, qVl, q_mask, upd_q, SQ, SQ, 0);
    attn_mma_kernel<<<dim3(SC / 128, H_, B_), 256, ATT_SMEM_BYTES>>>(
        cKh, cKl, cQh, cQl, cVh, cVl, c_mask, upd_c, SC, SC + 1, 1);
    // residual add + split for output projections
    split_act_kernel<<<16384, 256>>>(v, upd_v, ahi_v, alo_v, 0, 1);
    split_act_kernel<<<8192,  256>>>(q, upd_q, ahi_q, alo_q, 0, 1);
    split_act_kernel<<<16384, 256>>>(c, upd_c, ahi_c, alo_c, 0, 1);
    // output projections
    float* out = (float*)d_out;
    mma_gemm_kernel<false, false><<<dim3(8, 128), 256, MMA_SMEM_BYTES>>>(
        ahi_v, alo_v, wthi + WO_VO, wtlo + WO_VO, bvo, nullptr, out, D_,
        nullptr, nullptr, nullptr, nullptr, nullptr, nullptr, nullptr, 0, 0, 0);
    mma_gemm_kernel<false, false><<<dim3(8, 64), 256, MMA_SMEM_BYTES>>>(
        ahi_q, alo_q, wthi + WO_QO, wtlo + WO_QO, bqo, nullptr, out + (size_t)B_ * SV * D_, D_,
        nullptr, nullptr, nullptr, nullptr, nullptr, nullptr, nullptr, 0, 0, 0);
    mma_gemm_kernel<false, false><<<dim3(8, 128), 256, MMA_SMEM_BYTES>>>(
        ahi_c, alo_c, wthi + WO_CO, wtlo + WO_CO, bco, nullptr, out + (size_t)B_ * (SV + SQ) * D_, D_,
        nullptr, nullptr, nullptr, nullptr, nullptr, nullptr, nullptr, 0, 0, 0);
}

// round 5
// speedup vs baseline: 3.2267x; 1.0347x over previous
#include <cuda_runtime.h>
#include <cuda_bf16.h>
#include <cstdint>

#define B_   32
#define SV   512
#define SQ   256
#define SC   512
#define D_   1024
#define H_   8
#define DHD  128
#define N3   3072
#define GK   1024

// ---------------- scratch (device globals; no allocations allowed) ----------------
__device__ float g_gate_v4q[32768];
__device__ float g_gate_q4v[32768];
__device__ float g_mean_v[32768];
__device__ float g_mean_q[32768];
__device__ float g_inv_v[32];
__device__ float g_inv_q[32];

// bf16 hi/lo split activations + weights for GEMMs
// (ahi/alo double-duty: relu(x) split for QKV, then x+attn split for out-proj)
__device__ __nv_bfloat16 g_ahi_v[16777216];
__device__ __nv_bfloat16 g_alo_v[16777216];
__device__ __nv_bfloat16 g_ahi_q[8388608];
__device__ __nv_bfloat16 g_alo_q[8388608];
__device__ __nv_bfloat16 g_ahi_c[16777216];
__device__ __nv_bfloat16 g_alo_c[16777216];
__device__ __nv_bfloat16 g_wthi[12582912];
__device__ __nv_bfloat16 g_wtlo[12582912];

// bf16 hi/lo K/Q/V in [B,H,T,dh] layout (gates + mask pre-applied; mem token at t=0)
__device__ __nv_bfloat16 g_vKh[16809984], g_vKl[16809984];
__device__ __nv_bfloat16 g_vQh[16777216], g_vQl[16777216];
__device__ __nv_bfloat16 g_vVh[16809984], g_vVl[16809984];
__device__ __nv_bfloat16 g_qKh[8388608],  g_qKl[8388608];
__device__ __nv_bfloat16 g_qQh[8388608],  g_qQl[8388608];
__device__ __nv_bfloat16 g_qVh[8388608],  g_qVl[8388608];
__device__ __nv_bfloat16 g_cKh[16809984], g_cKl[16809984];
__device__ __nv_bfloat16 g_cQh[16777216], g_cQl[16777216];
__device__ __nv_bfloat16 g_cVh[16809984], g_cVl[16809984];

// ---------------- base-target tensor helpers ----------------
__device__ __forceinline__ uint32_t smem_u32(const void* p) {
    uint32_t a;
    asm("{ .reg .u64 t; cvta.to.shared.u64 t, %1; cvt.u32.u64 %0, t; }" : "=r"(a) : "l"(p));
    return a;
}
__device__ __forceinline__ void cp16(uint32_t dst, const void* src) {
    asm volatile("cp.async.cg.shared.global [%0], [%1], 16;" :: "r"(dst), "l"(src));
}
__device__ __forceinline__ void cp16z(uint32_t dst, const void* src, int sz) {
    asm volatile("cp.async.cg.shared.global [%0], [%1], 16, %2;" :: "r"(dst), "l"(src), "r"(sz));
}
__device__ __forceinline__ void cp_commit() { asm volatile("cp.async.commit_group;" ::: "memory"); }
__device__ __forceinline__ void cp_wait1()  { asm volatile("cp.async.wait_group 1;" ::: "memory"); }
__device__ __forceinline__ void cp_wait0()  { asm volatile("cp.async.wait_group 0;" ::: "memory"); }

__device__ __forceinline__ void ldmx4(uint32_t* r, uint32_t addr) {
    asm volatile("ldmatrix.sync.aligned.m8n8.x4.shared.b16 {%0,%1,%2,%3}, [%4];"
                 : "=r"(r[0]), "=r"(r[1]), "=r"(r[2]), "=r"(r[3]) : "r"(addr));
}
__device__ __forceinline__ void ldmx4t(uint32_t* r, uint32_t addr) {
    asm volatile("ldmatrix.sync.aligned.m8n8.x4.trans.shared.b16 {%0,%1,%2,%3}, [%4];"
                 : "=r"(r[0]), "=r"(r[1]), "=r"(r[2]), "=r"(r[3]) : "r"(addr));
}
__device__ __forceinline__ void mma16816(float* d, const uint32_t* a, uint32_t b0, uint32_t b1) {
    asm volatile("mma.sync.aligned.m16n8k16.row.col.f32.bf16.bf16.f32 "
                 "{%0,%1,%2,%3}, {%4,%5,%6,%7}, {%8,%9}, {%0,%1,%2,%3};"
                 : "+f"(d[0]), "+f"(d[1]), "+f"(d[2]), "+f"(d[3])
                 : "r"(a[0]), "r"(a[1]), "r"(a[2]), "r"(a[3]), "r"(b0), "r"(b1));
}

// ---------------- hi/lo split helpers ----------------
__device__ __forceinline__ void split1(float v, unsigned short& h, unsigned short& l) {
    __nv_bfloat16 hb = __float2bfloat16_rn(v);
    __nv_bfloat16 lb = __float2bfloat16_rn(v - __bfloat162float(hb));
    h = __bfloat16_as_ushort(hb);
    l = __bfloat16_as_ushort(lb);
}
__device__ __forceinline__ void store_hl(__nv_bfloat16* H, __nv_bfloat16* L, size_t idx,
                                         float x, float y) {
    __nv_bfloat162 h2 = __floats2bfloat162_rn(x, y);
    __nv_bfloat162 l2 = __floats2bfloat162_rn(x - __bfloat162float(h2.x),
                                              y - __bfloat162float(h2.y));
    *(__nv_bfloat162*)(H + idx) = h2;
    *(__nv_bfloat162*)(L + idx) = l2;
}
__device__ __forceinline__ void fsplit2(float x, float y, uint32_t& hi, uint32_t& lo) {
    __nv_bfloat162 h2 = __floats2bfloat162_rn(x, y);
    __nv_bfloat162 l2 = __floats2bfloat162_rn(x - __bfloat162float(h2.x),
                                              y - __bfloat162float(h2.y));
    hi = *(uint32_t*)&h2; lo = *(uint32_t*)&l2;
}

// ---------------- conversion kernels ----------------
__global__ void split_act_kernel(const float* __restrict__ x,
                                 __nv_bfloat16* __restrict__ hi, __nv_bfloat16* __restrict__ lo) {
    int idx = blockIdx.x * 256 + threadIdx.x;
    float4 v = ((const float4*)x)[idx];
    v.x = fmaxf(v.x, 0.f); v.y = fmaxf(v.y, 0.f);
    v.z = fmaxf(v.z, 0.f); v.w = fmaxf(v.w, 0.f);
    unsigned short h0,h1,h2,h3,l0,l1,l2,l3;
    split1(v.x,h0,l0); split1(v.y,h1,l1); split1(v.z,h2,l2); split1(v.w,h3,l3);
    uint2 hv, lv;
    hv.x = ((uint32_t)h1 << 16) | h0; hv.y = ((uint32_t)h3 << 16) | h2;
    lv.x = ((uint32_t)l1 << 16) | l0; lv.y = ((uint32_t)l3 << 16) | l2;
    ((uint2*)hi)[idx] = hv;
    ((uint2*)lo)[idx] = lv;
}

__global__ void split_wT_kernel(const float* __restrict__ W,
                                __nv_bfloat16* __restrict__ thi, __nv_bfloat16* __restrict__ tlo,
                                int N) {
    __shared__ float t[32][33];
    int n0 = blockIdx.x * 32, k0 = blockIdx.y * 32;
    int tx = threadIdx.x, ty = threadIdx.y;
    #pragma unroll
    for (int r = 0; r < 4; r++)
        t[ty + 8 * r][tx] = W[(size_t)(k0 + ty + 8 * r) * N + n0 + tx];
    __syncthreads();
    #pragma unroll
    for (int r = 0; r < 4; r++) {
        float v = t[tx][ty + 8 * r];
        unsigned short h, l; split1(v, h, l);
        size_t o = (size_t)(n0 + ty + 8 * r) * GK + k0 + tx;
        thi[o] = __ushort_as_bfloat16(h);
        tlo[o] = __ushort_as_bfloat16(l);
    }
}

// ---------------- small kernels ----------------
__global__ void masksum_kernel(const float* __restrict__ mask, float* __restrict__ inv, int S) {
    __shared__ float red[256];
    int b = blockIdx.x;
    float s = 0.f;
    for (int t = threadIdx.x; t < S; t += 256) s += mask[(size_t)b * S + t];
    red[threadIdx.x] = s;
    __syncthreads();
    for (int w = 128; w > 0; w >>= 1) {
        if (threadIdx.x < w) red[threadIdx.x] += red[threadIdx.x + w];
        __syncthreads();
    }
    if (threadIdx.x == 0) inv[b] = 1.f / red[0];
}

__global__ void mean_relu_kernel(const float* __restrict__ x, const float* __restrict__ mask,
                                 const float* __restrict__ inv, float* __restrict__ out, int S) {
    int b = blockIdx.y;
    int d = blockIdx.x * 256 + threadIdx.x;
    const float* xp = x + (size_t)b * S * D_ + d;
    const float* mp = mask + (size_t)b * S;
    float s = 0.f;
    for (int t = 0; t < S; t++) s += xp[(size_t)t * D_] * mp[t];
    out[b * D_ + d] = fmaxf(s * inv[b], 0.f);
}

__global__ void gate_kernel(const float* __restrict__ rmean, const float* __restrict__ W,
                            const float* __restrict__ bias, float* __restrict__ out) {
    __shared__ float sm[D_];
    int b = blockIdx.y;
    int n = blockIdx.x * 128 + threadIdx.x;
    for (int k = threadIdx.x; k < D_; k += 128) sm[k] = rmean[b * D_ + k];
    __syncthreads();
    float acc = bias[n];
    #pragma unroll 8
    for (int k = 0; k < D_; k++) acc = fmaf(sm[k], W[(size_t)k * D_ + n], acc);
    out[b * D_ + n] = 1.f + 1.f / (1.f + __expf(-acc));
}

__global__ void memtok_kernel(__nv_bfloat16* Kh, __nv_bfloat16* Kl,
                              __nv_bfloat16* Vh, __nv_bfloat16* Vl,
                              const float* __restrict__ memk, const float* __restrict__ memv,
                              const float* __restrict__ gate, int T) {
    int b = blockIdx.x;
    int i = threadIdx.x;
    int h = i >> 7;
    float kv = 32.f * memk[i];
    if (gate) kv *= gate[b * D_ + i];
    float vv = memv[i];
    size_t idx = ((size_t)(b * H_ + h) * T) * DHD + (i & 127);
    unsigned short hb, lb;
    split1(kv, hb, lb); Kh[idx] = __ushort_as_bfloat16(hb); Kl[idx] = __ushort_as_bfloat16(lb);
    split1(vv, hb, lb); Vh[idx] = __ushort_as_bfloat16(hb); Vl[idx] = __ushort_as_bfloat16(lb);
}

// ---------------- mma.sync bf16x3 GEMM ----------------
// 128x128 CTA tile, BK=32, 4 warps (2x2), warp tile 64x64, cp.async double buffer.
#define ROWB 40
#define MAT_BYTES (128 * ROWB * 2)
#define STAGE_BYTES (4 * MAT_BYTES)
#define MMA_SMEM_BYTES (2 * STAGE_BYTES)

template <bool MASK, bool SPLIT>
__global__ __launch_bounds__(128, 2) void mma_gemm_kernel(
    const __nv_bfloat16* __restrict__ Ahi, const __nv_bfloat16* __restrict__ Alo,
    const __nv_bfloat16* __restrict__ Bhi, const __nv_bfloat16* __restrict__ Blo,
    const float* __restrict__ bias, const float* __restrict__ mask,
    float* __restrict__ C, int N,
    const float* __restrict__ gate,
    __nv_bfloat16* oKh, __nv_bfloat16* oKl,
    __nv_bfloat16* oQh, __nv_bfloat16* oQl,
    __nv_bfloat16* oVh, __nv_bfloat16* oVl,
    int S, int T, int hasMem)
{
    extern __shared__ char smem[];
    uint32_t sbase = smem_u32(smem);
    int tid = threadIdx.x;
    int wid = tid >> 5, lane = tid & 31;
    int bm = blockIdx.y * 128, bn = blockIdx.x * 128;
    int wm = (wid & 1) * 64;
    int wn = (wid >> 1) * 64;

    const __nv_bfloat16* srcs[4] = {
        Ahi + (size_t)bm * GK, Alo + (size_t)bm * GK,
        Bhi + (size_t)bn * GK, Blo + (size_t)bn * GK };

    float acc[4][8][4];
    #pragma unroll
    for (int i = 0; i < 4; i++)
        #pragma unroll
        for (int j = 0; j < 8; j++)
            #pragma unroll
            for (int k = 0; k < 4; k++) acc[i][j][k] = 0.f;

    int lrow = tid >> 2, lc = tid & 3;
    auto load_stage = [&](int kc, int s) {
        uint32_t st = sbase + s * STAGE_BYTES;
        int k0 = kc * 32;
        #pragma unroll
        for (int m = 0; m < 4; m++) {
            const __nv_bfloat16* src = srcs[m];
            uint32_t dst = st + m * MAT_BYTES;
            #pragma unroll
            for (int it = 0; it < 4; it++) {
                int row = lrow + it * 32;
                cp16(dst + row * 80 + lc * 16, src + (size_t)row * GK + k0 + lc * 8);
            }
        }
        cp_commit();
    };

    load_stage(0, 0);

    const int NK = GK / 32;
    for (int kc = 0; kc < NK; kc++) {
        if (kc + 1 < NK) { load_stage(kc + 1, (kc + 1) & 1); cp_wait1(); }
        else cp_wait0();
        __syncthreads();
        uint32_t st  = sbase + (kc & 1) * STAGE_BYTES;
        uint32_t sAh = st, sAl = st + MAT_BYTES;
        uint32_t sBh = st + 2 * MAT_BYTES, sBl = st + 3 * MAT_BYTES;
        #pragma unroll
        for (int ks = 0; ks < 32; ks += 16) {
            uint32_t ah[4][4], al[4][4];
            int arow = wm + (lane & 15);
            int ak = ks + ((lane >> 4) << 3);
            #pragma unroll
            for (int mt = 0; mt < 4; mt++) {
                uint32_t off = (uint32_t)(((arow + mt * 16) * ROWB + ak) * 2);
                ldmx4(ah[mt], sAh + off);
                ldmx4(al[mt], sAl + off);
            }
            int r = lane & 7, qsel = lane >> 3;
            #pragma unroll
            for (int nt = 0; nt < 4; nt++) {
                int nn = wn + nt * 16 + ((qsel >> 1) << 3) + r;
                int kk = ks + ((qsel & 1) << 3);
                uint32_t off = (uint32_t)((nn * ROWB + kk) * 2);
                uint32_t bh[4], bl[4];
                ldmx4(bh, sBh + off);
                ldmx4(bl, sBl + off);
                #pragma unroll
                for (int mt = 0; mt < 4; mt++) {
                    #pragma unroll
                    for (int hf = 0; hf < 2; hf++) {
                        float* d = acc[mt][nt * 2 + hf];
                        mma16816(d, ah[mt], bh[hf * 2], bh[hf * 2 + 1]);
                        mma16816(d, ah[mt], bl[hf * 2], bl[hf * 2 + 1]);
                        mma16816(d, al[mt], bh[hf * 2], bh[hf * 2 + 1]);
                    }
                }
            }
        }
        __syncthreads();
    }

    if (!SPLIT) {
        #pragma unroll
        for (int mt = 0; mt < 4; mt++) {
            int r0 = bm + wm + mt * 16 + (lane >> 2);
            float m0 = MASK ? mask[r0] : 1.f;
            float m1 = MASK ? mask[r0 + 8] : 1.f;
            #pragma unroll
            for (int nt = 0; nt < 8; nt++) {
                int col = bn + wn + nt * 8 + ((lane & 3) << 1);
                float2 bb = *(const float2*)&bias[col];
                float2 o0, o1;
                o0.x = (acc[mt][nt][0] + bb.x) * m0; o0.y = (acc[mt][nt][1] + bb.y) * m0;
                o1.x = (acc[mt][nt][2] + bb.x) * m1; o1.y = (acc[mt][nt][3] + bb.y) * m1;
                *(float2*)(C + (size_t)r0 * N + col) = o0;
                *(float2*)(C + (size_t)(r0 + 8) * N + col) = o1;
            }
        }
    } else {
        int colbase = bn + wn;              // 64-aligned; warp tile stays in one part/head
        int part = colbase >> 10;           // 0=k, 1=q, 2=v
        int hh = (colbase & 1023) >> 7;
        int dwarp = colbase & 127;
        int b = bm / S;
        int s0 = bm % S;
        size_t bh64 = (size_t)(b * H_ + hh);
        #pragma unroll
        for (int mt = 0; mt < 4; mt++) {
            int rl0 = wm + mt * 16 + (lane >> 2);
            int gr0 = bm + rl0;
            float mk0 = MASK ? mask[gr0] : 1.f;
            float mk1 = MASK ? mask[gr0 + 8] : 1.f;
            int s_0 = s0 + rl0, s_1 = s_0 + 8;
            #pragma unroll
            for (int nt = 0; nt < 8; nt++) {
                int d = dwarp + nt * 8 + ((lane & 3) << 1);
                int col = colbase + nt * 8 + ((lane & 3) << 1);
                float2 bb = *(const float2*)&bias[col];
                float x0 = (acc[mt][nt][0] + bb.x) * mk0;
                float y0 = (acc[mt][nt][1] + bb.y) * mk0;
                float x1 = (acc[mt][nt][2] + bb.x) * mk1;
                float y1 = (acc[mt][nt][3] + bb.y) * mk1;
                if (gate != nullptr && part < 2) {
                    float2 g2 = *(const float2*)&gate[b * D_ + hh * DHD + d];
                    x0 *= g2.x; y0 *= g2.y; x1 *= g2.x; y1 *= g2.y;
                }
                if (part == 0) {
                    size_t i0 = (bh64 * T + (s_0 + hasMem)) * DHD + d;
                    size_t i1 = (bh64 * T + (s_1 + hasMem)) * DHD + d;
                    store_hl(oKh, oKl, i0, x0, y0);
                    store_hl(oKh, oKl, i1, x1, y1);
                } else if (part == 1) {
                    size_t i0 = (bh64 * S + s_0) * DHD + d;
                    size_t i1 = (bh64 * S + s_1) * DHD + d;
                    store_hl(oQh, oQl, i0, x0, y0);
                    store_hl(oQh, oQl, i1, x1, y1);
                } else {
                    size_t i0 = (bh64 * T + (s_0 + hasMem)) * DHD + d;
                    size_t i1 = (bh64 * T + (s_1 + hasMem)) * DHD + d;
                    store_hl(oVh, oVl, i0, x0, y0);
                    store_hl(oVh, oVl, i1, x1, y1);
                }
            }
        }
    }
}

// ---------------- tensor-core flash attention (bf16 hi/lo x3) ----------------
// CTA: 128 q-rows x 1 head x 1 batch, 8 warps x 16 rows. 64-key tiles, double-buffered.
// Epilogue: writes split(resid + attn_out) into bf16 hi/lo A-operand buffers.
#define APAD 136
constexpr int A_QH  = 0;
constexpr int A_QL  = 128 * APAD * 2;
constexpr int A_ST0 = 2 * 128 * APAD * 2;
constexpr int A_STG = 4 * 64 * APAD * 2;
constexpr int A_KH  = 0;
constexpr int A_KL  = 64 * APAD * 2;
constexpr int A_VH  = 2 * 64 * APAD * 2;
constexpr int A_VL  = 3 * 64 * APAD * 2;
constexpr int A_KM  = A_ST0 + 2 * A_STG;
constexpr int ATT_SMEM_BYTES = A_KM + 2 * 64 * 4;

__global__ __launch_bounds__(256, 1) void attn_mma_kernel(
    const __nv_bfloat16* __restrict__ Kh, const __nv_bfloat16* __restrict__ Kl,
    const __nv_bfloat16* __restrict__ Qh, const __nv_bfloat16* __restrict__ Ql,
    const __nv_bfloat16* __restrict__ Vh, const __nv_bfloat16* __restrict__ Vl,
    const float* __restrict__ mask,
    const float* __restrict__ resid,
    __nv_bfloat16* __restrict__ outh, __nv_bfloat16* __restrict__ outl,
    int S, int T, int hasMem)
{
    extern __shared__ char sm[];
    uint32_t sb = smem_u32(sm);
    float* km = (float*)(sm + A_KM);
    int tid = threadIdx.x, wid = tid >> 5, lane = tid & 31;
    int b = blockIdx.z, h = blockIdx.y, m0 = blockIdx.x * 128;
    size_t bh = (size_t)(b * H_ + h);
    const __nv_bfloat16* gQh = Qh + (bh * S + m0) * DHD;
    const __nv_bfloat16* gQl = Ql + (bh * S + m0) * DHD;
    const __nv_bfloat16* gKV[4] = { Kh + bh * T * DHD, Kl + bh * T * DHD,
                                    Vh + bh * T * DHD, Vl + bh * T * DHD };

    #pragma unroll
    for (int it = 0; it < 8; it++) {
        int id = tid + it * 256; int row = id >> 4, cc = id & 15;
        cp16(sb + A_QH + row * (APAD * 2) + cc * 16, gQh + row * DHD + cc * 8);
        cp16(sb + A_QL + row * (APAD * 2) + cc * 16, gQl + row * DHD + cc * 8);
    }
    auto load_kv = [&](int kt, int s) {
        int t0 = kt * 64;
        uint32_t st = sb + A_ST0 + s * A_STG;
        #pragma unroll
        for (int m = 0; m < 4; m++) {
            #pragma unroll
            for (int it = 0; it < 4; it++) {
                int id = tid + it * 256; int row = id >> 4, cc = id & 15;
                int t = t0 + row;
                int tc = (t < T) ? t : (T - 1);
                int sz = (t < T) ? 16 : 0;
                cp16z(st + m * (64 * APAD * 2) + row * (APAD * 2) + cc * 16,
                      gKV[m] + (size_t)tc * DHD + cc * 8, sz);
            }
        }
        if (tid < 64) {
            int t = t0 + tid;
            float mv = 0.f;
            if (t < T) mv = (hasMem && t == 0) ? 1.f : mask[(size_t)b * S + (t - hasMem)];
            km[s * 64 + tid] = mv;
        }
    };

    load_kv(0, 0);
    cp_commit();

    float o[16][4];
    #pragma unroll
    for (int i = 0; i < 16; i++) { o[i][0] = 0.f; o[i][1] = 0.f; o[i][2] = 0.f; o[i][3] = 0.f; }
    float mprev0 = -1e30f, mprev1 = -1e30f, lsum0 = 0.f, lsum1 = 0.f;
    const float SCL  = 0.088388347648318447f;
    const float NEGS = -1e9f * 0.088388347648318447f;
    int wm = wid * 16;
    int ntile = (T + 63) / 64;

    for (int kt = 0; kt < ntile; kt++) {
        if (kt + 1 < ntile) { load_kv(kt + 1, (kt + 1) & 1); cp_commit(); cp_wait1(); }
        else cp_wait0();
        __syncthreads();
        uint32_t st = sb + A_ST0 + (kt & 1) * A_STG;

        float sf[8][4];
        #pragma unroll
        for (int i = 0; i < 8; i++) { sf[i][0]=0.f; sf[i][1]=0.f; sf[i][2]=0.f; sf[i][3]=0.f; }
        #pragma unroll
        for (int ks = 0; ks < 128; ks += 16) {
            int arow = wm + (lane & 15), ak = ks + ((lane >> 4) << 3);
            uint32_t aoff = (uint32_t)(arow * APAD + ak) * 2;
            uint32_t ah[4], al[4];
            ldmx4(ah, sb + A_QH + aoff);
            ldmx4(al, sb + A_QL + aoff);
            int r = lane & 7, qs = lane >> 3;
            #pragma unroll
            for (int pr = 0; pr < 4; pr++) {
                int nn = pr * 16 + ((qs >> 1) << 3) + r;
                int kk2 = ks + ((qs & 1) << 3);
                uint32_t boff = (uint32_t)(nn * APAD + kk2) * 2;
                uint32_t bh4[4], bl4[4];
                ldmx4(bh4, st + A_KH + boff);
                ldmx4(bl4, st + A_KL + boff);
                #pragma unroll
                for (int hf = 0; hf < 2; hf++) {
                    float* d = sf[pr * 2 + hf];
                    mma16816(d, ah, bh4[hf * 2], bh4[hf * 2 + 1]);
                    mma16816(d, ah, bl4[hf * 2], bl4[hf * 2 + 1]);
                    mma16816(d, al, bh4[hf * 2], bh4[hf * 2 + 1]);
                }
            }
        }
        const float* kmc = km + (kt & 1) * 64;
        float mx0 = mprev0, mx1 = mprev1;
        #pragma unroll
        for (int nt = 0; nt < 8; nt++) {
            int c0 = nt * 8 + ((lane & 3) << 1);
            float k0v = kmc[c0], k1v = kmc[c0 + 1];
            sf[nt][0] = (k0v != 0.f) ? sf[nt][0] * SCL : NEGS;
            sf[nt][1] = (k1v != 0.f) ? sf[nt][1] * SCL : NEGS;
            sf[nt][2] = (k0v != 0.f) ? sf[nt][2] * SCL : NEGS;
            sf[nt][3] = (k1v != 0.f) ? sf[nt][3] * SCL : NEGS;
            mx0 = fmaxf(mx0, fmaxf(sf[nt][0], sf[nt][1]));
            mx1 = fmaxf(mx1, fmaxf(sf[nt][2], sf[nt][3]));
        }
        mx0 = fmaxf(mx0, __shfl_xor_sync(0xffffffffu, mx0, 1));
        mx0 = fmaxf(mx0, __shfl_xor_sync(0xffffffffu, mx0, 2));
        mx1 = fmaxf(mx1, __shfl_xor_sync(0xffffffffu, mx1, 1));
        mx1 = fmaxf(mx1, __shfl_xor_sync(0xffffffffu, mx1, 2));
        float corr0 = __expf(mprev0 - mx0), corr1 = __expf(mprev1 - mx1);
        mprev0 = mx0; mprev1 = mx1;
        float ps0 = 0.f, ps1 = 0.f;
        #pragma unroll
        for (int nt = 0; nt < 8; nt++) {
            sf[nt][0] = __expf(sf[nt][0] - mx0);
            sf[nt][1] = __expf(sf[nt][1] - mx0);
            sf[nt][2] = __expf(sf[nt][2] - mx1);
            sf[nt][3] = __expf(sf[nt][3] - mx1);
            ps0 += sf[nt][0] + sf[nt][1];
            ps1 += sf[nt][2] + sf[nt][3];
        }
        ps0 += __shfl_xor_sync(0xffffffffu, ps0, 1);
        ps0 += __shfl_xor_sync(0xffffffffu, ps0, 2);
        ps1 += __shfl_xor_sync(0xffffffffu, ps1, 1);
        ps1 += __shfl_xor_sync(0xffffffffu, ps1, 2);
        lsum0 = lsum0 * corr0 + ps0;
        lsum1 = lsum1 * corr1 + ps1;
        #pragma unroll
        for (int dd = 0; dd < 16; dd++) {
            o[dd][0] *= corr0; o[dd][1] *= corr0;
            o[dd][2] *= corr1; o[dd][3] *= corr1;
        }
        int mi = lane >> 3, rr = lane & 7;
        #pragma unroll
        for (int kk = 0; kk < 4; kk++) {
            uint32_t ph4[4], pl4[4];
            fsplit2(sf[2*kk][0],   sf[2*kk][1],   ph4[0], pl4[0]);
            fsplit2(sf[2*kk][2],   sf[2*kk][3],   ph4[1], pl4[1]);
            fsplit2(sf[2*kk+1][0], sf[2*kk+1][1], ph4[2], pl4[2]);
            fsplit2(sf[2*kk+1][2], sf[2*kk+1][3], ph4[3], pl4[3]);
            #pragma unroll
            for (int db = 0; db < 8; db++) {
                uint32_t voff = (uint32_t)((kk * 16 + (mi & 1) * 8 + rr) * APAD
                                           + db * 16 + (mi >> 1) * 8) * 2;
                uint32_t vh4[4], vl4[4];
                ldmx4t(vh4, st + A_VH + voff);
                ldmx4t(vl4, st + A_VL + voff);
                float* d0 = o[db * 2];
                float* d1 = o[db * 2 + 1];
                mma16816(d0, ph4, vh4[0], vh4[1]);
                mma16816(d0, ph4, vl4[0], vl4[1]);
                mma16816(d0, pl4, vh4[0], vh4[1]);
                mma16816(d1, ph4, vh4[2], vh4[3]);
                mma16816(d1, ph4, vl4[2], vl4[3]);
                mma16816(d1, pl4, vh4[2], vh4[3]);
            }
        }
        __syncthreads();
    }

    // epilogue: (resid + O/lsum) -> bf16 hi/lo split, row-major [B*S, D]
    float i0 = 1.f / lsum0, i1 = 1.f / lsum1;
    int g = lane >> 2;
    size_t row0 = (size_t)(b * S + m0 + wm + g);
    const float* rs0 = resid + row0 * D_ + h * DHD;
    size_t ob0 = row0 * D_ + h * DHD;
    #pragma unroll
    for (int dd = 0; dd < 16; dd++) {
        int d = dd * 8 + ((lane & 3) << 1);
        float2 rv0 = *(const float2*)(rs0 + d);
        float2 rv1 = *(const float2*)(rs0 + 8 * D_ + d);
        store_hl(outh, outl, ob0 + d,           rv0.x + o[dd][0] * i0, rv0.y + o[dd][1] * i0);
        store_hl(outh, outl, ob0 + 8 * D_ + d,  rv1.x + o[dd][2] * i1, rv1.y + o[dd][3] * i1);
    }
}

// ---------------- launch ----------------
extern "C" void kernel_launch(void* const* d_in, const int* in_sizes, int n_in,
                              void* d_out, int out_size) {
    const float* v      = (const float*)d_in[0];
    const float* q      = (const float*)d_in[1];
    const float* c      = (const float*)d_in[2];
    const float* v_mask = (const float*)d_in[3];
    const float* q_mask = (const float*)d_in[4];
    const float* c_mask = (const float*)d_in[5];
    const float* Wv4q   = (const float*)d_in[6];
    const float* bv4q   = (const float*)d_in[7];
    const float* Wq4v   = (const float*)d_in[8];
    const float* bq4v   = (const float*)d_in[9];
    const float* Wv     = (const float*)d_in[10];
    const float* bv     = (const float*)d_in[11];
    const float* Wq     = (const float*)d_in[12];
    const float* bq     = (const float*)d_in[13];
    const float* Wc     = (const float*)d_in[14];
    const float* bcin   = (const float*)d_in[15];
    const float* m_v_k  = (const float*)d_in[16];
    const float* m_v_v  = (const float*)d_in[17];
    const float* m_c_k  = (const float*)d_in[18];
    const float* m_c_v  = (const float*)d_in[19];
    const float* Wvo    = (const float*)d_in[20];
    const float* bvo    = (const float*)d_in[21];
    const float* Wqo    = (const float*)d_in[22];
    const float* bqo    = (const float*)d_in[23];
    const float* Wco    = (const float*)d_in[24];
    const float* bco    = (const float*)d_in[25];
    (void)in_sizes; (void)n_in; (void)out_size;

    float *gv4q, *gq4v, *mnv, *mnq, *iv, *iq;
    __nv_bfloat16 *ahi_v, *alo_v, *ahi_q, *alo_q, *ahi_c, *alo_c, *wthi, *wtlo;
    __nv_bfloat16 *vKh,*vKl,*vQh,*vQl,*vVh,*vVl;
    __nv_bfloat16 *qKh,*qKl,*qQh,*qQl,*qVh,*qVl;
    __nv_bfloat16 *cKh,*cKl,*cQh,*cQl,*cVh,*cVl;
    cudaGetSymbolAddress((void**)&gv4q,  g_gate_v4q);
    cudaGetSymbolAddress((void**)&gq4v,  g_gate_q4v);
    cudaGetSymbolAddress((void**)&mnv,   g_mean_v);
    cudaGetSymbolAddress((void**)&mnq,   g_mean_q);
    cudaGetSymbolAddress((void**)&iv,    g_inv_v);
    cudaGetSymbolAddress((void**)&iq,    g_inv_q);
    cudaGetSymbolAddress((void**)&ahi_v, g_ahi_v);
    cudaGetSymbolAddress((void**)&alo_v, g_alo_v);
    cudaGetSymbolAddress((void**)&ahi_q, g_ahi_q);
    cudaGetSymbolAddress((void**)&alo_q, g_alo_q);
    cudaGetSymbolAddress((void**)&ahi_c, g_ahi_c);
    cudaGetSymbolAddress((void**)&alo_c, g_alo_c);
    cudaGetSymbolAddress((void**)&wthi,  g_wthi);
    cudaGetSymbolAddress((void**)&wtlo,  g_wtlo);
    cudaGetSymbolAddress((void**)&vKh, g_vKh); cudaGetSymbolAddress((void**)&vKl, g_vKl);
    cudaGetSymbolAddress((void**)&vQh, g_vQh); cudaGetSymbolAddress((void**)&vQl, g_vQl);
    cudaGetSymbolAddress((void**)&vVh, g_vVh); cudaGetSymbolAddress((void**)&vVl, g_vVl);
    cudaGetSymbolAddress((void**)&qKh, g_qKh); cudaGetSymbolAddress((void**)&qKl, g_qKl);
    cudaGetSymbolAddress((void**)&qQh, g_qQh); cudaGetSymbolAddress((void**)&qQl, g_qQl);
    cudaGetSymbolAddress((void**)&qVh, g_qVh); cudaGetSymbolAddress((void**)&qVl, g_qVl);
    cudaGetSymbolAddress((void**)&cKh, g_cKh); cudaGetSymbolAddress((void**)&cKl, g_cKl);
    cudaGetSymbolAddress((void**)&cQh, g_cQh); cudaGetSymbolAddress((void**)&cQl, g_cQl);
    cudaGetSymbolAddress((void**)&cVh, g_cVh); cudaGetSymbolAddress((void**)&cVl, g_cVl);

    cudaFuncSetAttribute(mma_gemm_kernel<true, true>,   cudaFuncAttributeMaxDynamicSharedMemorySize, MMA_SMEM_BYTES);
    cudaFuncSetAttribute(mma_gemm_kernel<false, false>, cudaFuncAttributeMaxDynamicSharedMemorySize, MMA_SMEM_BYTES);
    cudaFuncSetAttribute(attn_mma_kernel, cudaFuncAttributeMaxDynamicSharedMemorySize, ATT_SMEM_BYTES);

    const size_t WO_V = 0, WO_Q = 3145728, WO_C = 6291456;
    const size_t WO_VO = 9437184, WO_QO = 10485760, WO_CO = 11534336;

    // weight transpose + split
    dim3 wtb(32, 8);
    split_wT_kernel<<<dim3(N3 / 32, 32), wtb>>>(Wv, wthi + WO_V, wtlo + WO_V, N3);
    split_wT_kernel<<<dim3(N3 / 32, 32), wtb>>>(Wq, wthi + WO_Q, wtlo + WO_Q, N3);
    split_wT_kernel<<<dim3(N3 / 32, 32), wtb>>>(Wc, wthi + WO_C, wtlo + WO_C, N3);
    split_wT_kernel<<<dim3(D_ / 32, 32), wtb>>>(Wvo, wthi + WO_VO, wtlo + WO_VO, D_);
    split_wT_kernel<<<dim3(D_ / 32, 32), wtb>>>(Wqo, wthi + WO_QO, wtlo + WO_QO, D_);
    split_wT_kernel<<<dim3(D_ / 32, 32), wtb>>>(Wco, wthi + WO_CO, wtlo + WO_CO, D_);
    // activation relu + split
    split_act_kernel<<<16384, 256>>>(v, ahi_v, alo_v);
    split_act_kernel<<<8192,  256>>>(q, ahi_q, alo_q);
    split_act_kernel<<<16384, 256>>>(c, ahi_c, alo_c);
    // masked means -> gates
    masksum_kernel<<<B_, 256>>>(v_mask, iv, SV);
    masksum_kernel<<<B_, 256>>>(q_mask, iq, SQ);
    mean_relu_kernel<<<dim3(4, B_), 256>>>(v, v_mask, iv, mnv, SV);
    mean_relu_kernel<<<dim3(4, B_), 256>>>(q, q_mask, iq, mnq, SQ);
    gate_kernel<<<dim3(8, B_), 128>>>(mnv, Wv4q, bv4q, gv4q);
    gate_kernel<<<dim3(8, B_), 128>>>(mnq, Wq4v, bq4v, gq4v);
    // memory tokens
    memtok_kernel<<<B_, 1024>>>(vKh, vKl, vVh, vVl, m_v_k, m_v_v, gq4v, SV + 1);
    memtok_kernel<<<B_, 1024>>>(cKh, cKl, cVh, cVl, m_c_k, m_c_v, nullptr, SC + 1);
    // QKV projections -> fused gated bf16 hi/lo split K/Q/V
    mma_gemm_kernel<true, true><<<dim3(24, 128), 128, MMA_SMEM_BYTES>>>(
        ahi_v, alo_v, wthi + WO_V, wtlo + WO_V, bv, v_mask, nullptr, 0,
        gq4v, vKh, vKl, vQh, vQl, vVh, vVl, SV, SV + 1, 1);
    mma_gemm_kernel<true, true><<<dim3(24, 64), 128, MMA_SMEM_BYTES>>>(
        ahi_q, alo_q, wthi + WO_Q, wtlo + WO_Q, bq, q_mask, nullptr, 0,
        gv4q, qKh, qKl, qQh, qQl, qVh, qVl, SQ, SQ, 0);
    mma_gemm_kernel<true, true><<<dim3(24, 128), 128, MMA_SMEM_BYTES>>>(
        ahi_c, alo_c, wthi + WO_C, wtlo + WO_C, bcin, c_mask, nullptr, 0,
        nullptr, cKh, cKl, cQh, cQl, cVh, cVl, SC, SC + 1, 1);
    // tensor-core flash attention; epilogue writes split(resid + attn) into A buffers
    attn_mma_kernel<<<dim3(SV / 128, H_, B_), 256, ATT_SMEM_BYTES>>>(
        vKh, vKl, vQh, vQl, vVh, vVl, v_mask, v, ahi_v, alo_v, SV, SV + 1, 1);
    attn_mma_kernel<<<dim3(SQ / 128, H_, B_), 256, ATT_SMEM_BYTES>>>(
        qKh, qKl, qQh, qQl, qVh, qVl, q_mask, q, ahi_q, alo_q, SQ, SQ, 0);
    attn_mma_kernel<<<dim3(SC / 128, H_, B_), 256, ATT_SMEM_BYTES>>>(
        cKh, cKl, cQh, cQl, cVh, cVl, c_mask, c, ahi_c, alo_c, SC, SC + 1, 1);
    // output projections
    float* out = (float*)d_out;
    mma_gemm_kernel<false, false><<<dim3(8, 128), 128, MMA_SMEM_BYTES>>>(
        ahi_v, alo_v, wthi + WO_VO, wtlo + WO_VO, bvo, nullptr, out, D_,
        nullptr, nullptr, nullptr, nullptr, nullptr, nullptr, nullptr, 0, 0, 0);
    mma_gemm_kernel<false, false><<<dim3(8, 64), 128, MMA_SMEM_BYTES>>>(
        ahi_q, alo_q, wthi + WO_QO, wtlo + WO_QO, bqo, nullptr, out + (size_t)B_ * SV * D_, D_,
        nullptr, nullptr, nullptr, nullptr, nullptr, nullptr, nullptr, 0, 0, 0);
    mma_gemm_kernel<false, false><<<dim3(8, 128), 128, MMA_SMEM_BYTES>>>(
        ahi_c, alo_c, wthi + WO_CO, wtlo + WO_CO, bco, nullptr, out + (size_t)B_ * (SV + SQ) * D_, D_,
        nullptr, nullptr, nullptr, nullptr, nullptr, nullptr, nullptr, 0, 0, 0);
}

// round 6
// speedup vs baseline: 6.6022x; 2.0461x over previous
#include <cuda_runtime.h>
#include <cuda_fp16.h>
#include <cstdint>

#define B_   32
#define SV   512
#define SQ   256
#define SC   512
#define D_   1024
#define H_   8
#define DHD  128
#define N3   3072
#define GK   1024

// ---------------- scratch (device globals; no allocations allowed) ----------------
__device__ float g_gate_v4q[32768];
__device__ float g_gate_q4v[32768];
__device__ float g_mean_v[32768];
__device__ float g_mean_q[32768];
__device__ float g_inv_v[32];
__device__ float g_inv_q[32];

// fp16 activations + transposed weights for GEMMs
// (a_* double-duty: relu(x) for QKV proj, then x+attn for out-proj)
__device__ __half g_a_v[16777216];
__device__ __half g_a_q[8388608];
__device__ __half g_a_c[16777216];
__device__ __half g_wt[12582912];
// offsets: Wv=0, Wq=3145728, Wc=6291456, Wvo=9437184, Wqo=10485760, Wco=11534336

// fp16 K/Q/V in [B,H,T,dh] layout (gates + mask pre-applied; mem token at t=0)
__device__ __half g_vK[16809984], g_vQ[16777216], g_vV[16809984];
__device__ __half g_qK[8388608],  g_qQ[8388608],  g_qV[8388608];
__device__ __half g_cK[16809984], g_cQ[16777216], g_cV[16809984];

// ---------------- base-target tensor helpers ----------------
__device__ __forceinline__ uint32_t smem_u32(const void* p) {
    uint32_t a;
    asm("{ .reg .u64 t; cvta.to.shared.u64 t, %1; cvt.u32.u64 %0, t; }" : "=r"(a) : "l"(p));
    return a;
}
__device__ __forceinline__ void cp16(uint32_t dst, const void* src) {
    asm volatile("cp.async.cg.shared.global [%0], [%1], 16;" :: "r"(dst), "l"(src));
}
__device__ __forceinline__ void cp16z(uint32_t dst, const void* src, int sz) {
    asm volatile("cp.async.cg.shared.global [%0], [%1], 16, %2;" :: "r"(dst), "l"(src), "r"(sz));
}
__device__ __forceinline__ void cp_commit() { asm volatile("cp.async.commit_group;" ::: "memory"); }
__device__ __forceinline__ void cp_wait1()  { asm volatile("cp.async.wait_group 1;" ::: "memory"); }
__device__ __forceinline__ void cp_wait0()  { asm volatile("cp.async.wait_group 0;" ::: "memory"); }

__device__ __forceinline__ void ldmx4(uint32_t* r, uint32_t addr) {
    asm volatile("ldmatrix.sync.aligned.m8n8.x4.shared.b16 {%0,%1,%2,%3}, [%4];"
                 : "=r"(r[0]), "=r"(r[1]), "=r"(r[2]), "=r"(r[3]) : "r"(addr));
}
__device__ __forceinline__ void ldmx4t(uint32_t* r, uint32_t addr) {
    asm volatile("ldmatrix.sync.aligned.m8n8.x4.trans.shared.b16 {%0,%1,%2,%3}, [%4];"
                 : "=r"(r[0]), "=r"(r[1]), "=r"(r[2]), "=r"(r[3]) : "r"(addr));
}
__device__ __forceinline__ void mma16816(float* d, const uint32_t* a, uint32_t b0, uint32_t b1) {
    asm volatile("mma.sync.aligned.m16n8k16.row.col.f32.f16.f16.f32 "
                 "{%0,%1,%2,%3}, {%4,%5,%6,%7}, {%8,%9}, {%0,%1,%2,%3};"
                 : "+f"(d[0]), "+f"(d[1]), "+f"(d[2]), "+f"(d[3])
                 : "r"(a[0]), "r"(a[1]), "r"(a[2]), "r"(a[3]), "r"(b0), "r"(b1));
}

// ---------------- fp16 pack helpers ----------------
__device__ __forceinline__ uint32_t packh2(float x, float y) {
    __half2 h = __floats2half2_rn(x, y);
    return *(uint32_t*)&h;
}
__device__ __forceinline__ void store_h2(__half* H, size_t idx, float x, float y) {
    *(__half2*)(H + idx) = __floats2half2_rn(x, y);
}

// ---------------- conversion kernels ----------------
__global__ void cvt_act_kernel(const float* __restrict__ x, __half* __restrict__ out) {
    int idx = blockIdx.x * 256 + threadIdx.x;
    float4 v = ((const float4*)x)[idx];
    v.x = fmaxf(v.x, 0.f); v.y = fmaxf(v.y, 0.f);
    v.z = fmaxf(v.z, 0.f); v.w = fmaxf(v.w, 0.f);
    uint2 o;
    o.x = packh2(v.x, v.y);
    o.y = packh2(v.z, v.w);
    ((uint2*)out)[idx] = o;
}

// transpose W[K,N] -> Wt[N,K] fp16 (K = 1024)
__global__ void cvt_wT_kernel(const float* __restrict__ W, __half* __restrict__ th, int N) {
    __shared__ float t[32][33];
    int n0 = blockIdx.x * 32, k0 = blockIdx.y * 32;
    int tx = threadIdx.x, ty = threadIdx.y;   // (32, 8)
    #pragma unroll
    for (int r = 0; r < 4; r++)
        t[ty + 8 * r][tx] = W[(size_t)(k0 + ty + 8 * r) * N + n0 + tx];
    __syncthreads();
    #pragma unroll
    for (int r = 0; r < 4; r++) {
        size_t o = (size_t)(n0 + ty + 8 * r) * GK + k0 + tx;
        th[o] = __float2half_rn(t[tx][ty + 8 * r]);
    }
}

// ---------------- small kernels ----------------
__global__ void masksum_kernel(const float* __restrict__ mask, float* __restrict__ inv, int S) {
    __shared__ float red[256];
    int b = blockIdx.x;
    float s = 0.f;
    for (int t = threadIdx.x; t < S; t += 256) s += mask[(size_t)b * S + t];
    red[threadIdx.x] = s;
    __syncthreads();
    for (int w = 128; w > 0; w >>= 1) {
        if (threadIdx.x < w) red[threadIdx.x] += red[threadIdx.x + w];
        __syncthreads();
    }
    if (threadIdx.x == 0) inv[b] = 1.f / red[0];
}

__global__ void mean_relu_kernel(const float* __restrict__ x, const float* __restrict__ mask,
                                 const float* __restrict__ inv, float* __restrict__ out, int S) {
    int b = blockIdx.y;
    int d = blockIdx.x * 256 + threadIdx.x;
    const float* xp = x + (size_t)b * S * D_ + d;
    const float* mp = mask + (size_t)b * S;
    float s = 0.f;
    for (int t = 0; t < S; t++) s += xp[(size_t)t * D_] * mp[t];
    out[b * D_ + d] = fmaxf(s * inv[b], 0.f);
}

__global__ void gate_kernel(const float* __restrict__ rmean, const float* __restrict__ W,
                            const float* __restrict__ bias, float* __restrict__ out) {
    __shared__ float sm[D_];
    int b = blockIdx.y;
    int n = blockIdx.x * 128 + threadIdx.x;
    for (int k = threadIdx.x; k < D_; k += 128) sm[k] = rmean[b * D_ + k];
    __syncthreads();
    float acc = bias[n];
    #pragma unroll 8
    for (int k = 0; k < D_; k++) acc = fmaf(sm[k], W[(size_t)k * D_ + n], acc);
    out[b * D_ + n] = 1.f + 1.f / (1.f + __expf(-acc));
}

__global__ void memtok_kernel(__half* K, __half* V,
                              const float* __restrict__ memk, const float* __restrict__ memv,
                              const float* __restrict__ gate, int T) {
    int b = blockIdx.x;
    int i = threadIdx.x;
    int h = i >> 7;
    float kv = 32.f * memk[i];
    if (gate) kv *= gate[b * D_ + i];
    size_t idx = ((size_t)(b * H_ + h) * T) * DHD + (i & 127);
    K[idx] = __float2half_rn(kv);
    V[idx] = __float2half_rn(memv[i]);
}

// ---------------- mma.sync fp16 GEMM ----------------
// 128x128 CTA tile, BK=32, 4 warps (2x2), warp tile 64x64, cp.async double buffer.
#define ROWB 40
#define MAT_BYTES (128 * ROWB * 2)           // 10240
#define STAGE_BYTES (2 * MAT_BYTES)          // 20480
#define MMA_SMEM_BYTES (2 * STAGE_BYTES)     // 40960

template <bool MASK, bool SPLIT>
__global__ __launch_bounds__(128, 2) void mma_gemm_kernel(
    const __half* __restrict__ A, const __half* __restrict__ B,
    const float* __restrict__ bias, const float* __restrict__ mask,
    float* __restrict__ C, int N,
    const float* __restrict__ gate,
    __half* oK, __half* oQ, __half* oV,
    int S, int T, int hasMem)
{
    extern __shared__ char smem[];
    uint32_t sbase = smem_u32(smem);
    int tid = threadIdx.x;
    int wid = tid >> 5, lane = tid & 31;
    int bm = blockIdx.y * 128, bn = blockIdx.x * 128;
    int wm = (wid & 1) * 64;
    int wn = (wid >> 1) * 64;

    const __half* srcs[2] = { A + (size_t)bm * GK, B + (size_t)bn * GK };

    float acc[4][8][4];
    #pragma unroll
    for (int i = 0; i < 4; i++)
        #pragma unroll
        for (int j = 0; j < 8; j++)
            #pragma unroll
            for (int k = 0; k < 4; k++) acc[i][j][k] = 0.f;

    int lrow = tid >> 2, lc = tid & 3;
    auto load_stage = [&](int kc, int s) {
        uint32_t st = sbase + s * STAGE_BYTES;
        int k0 = kc * 32;
        #pragma unroll
        for (int m = 0; m < 2; m++) {
            const __half* src = srcs[m];
            uint32_t dst = st + m * MAT_BYTES;
            #pragma unroll
            for (int it = 0; it < 4; it++) {
                int row = lrow + it * 32;
                cp16(dst + row * 80 + lc * 16, src + (size_t)row * GK + k0 + lc * 8);
            }
        }
        cp_commit();
    };

    load_stage(0, 0);

    const int NK = GK / 32;
    for (int kc = 0; kc < NK; kc++) {
        if (kc + 1 < NK) { load_stage(kc + 1, (kc + 1) & 1); cp_wait1(); }
        else cp_wait0();
        __syncthreads();
        uint32_t st = sbase + (kc & 1) * STAGE_BYTES;
        uint32_t sA = st, sB = st + MAT_BYTES;
        #pragma unroll
        for (int ks = 0; ks < 32; ks += 16) {
            uint32_t ah[4][4];
            int arow = wm + (lane & 15);
            int ak = ks + ((lane >> 4) << 3);
            #pragma unroll
            for (int mt = 0; mt < 4; mt++)
                ldmx4(ah[mt], sA + (uint32_t)(((arow + mt * 16) * ROWB + ak) * 2));
            int r = lane & 7, qsel = lane >> 3;
            #pragma unroll
            for (int nt = 0; nt < 4; nt++) {
                int nn = wn + nt * 16 + ((qsel >> 1) << 3) + r;
                int kk = ks + ((qsel & 1) << 3);
                uint32_t bh[4];
                ldmx4(bh, sB + (uint32_t)((nn * ROWB + kk) * 2));
                #pragma unroll
                for (int mt = 0; mt < 4; mt++) {
                    mma16816(acc[mt][nt * 2 + 0], ah[mt], bh[0], bh[1]);
                    mma16816(acc[mt][nt * 2 + 1], ah[mt], bh[2], bh[3]);
                }
            }
        }
        __syncthreads();
    }

    if (!SPLIT) {
        #pragma unroll
        for (int mt = 0; mt < 4; mt++) {
            int r0 = bm + wm + mt * 16 + (lane >> 2);
            float m0 = MASK ? mask[r0] : 1.f;
            float m1 = MASK ? mask[r0 + 8] : 1.f;
            #pragma unroll
            for (int nt = 0; nt < 8; nt++) {
                int col = bn + wn + nt * 8 + ((lane & 3) << 1);
                float2 bb = *(const float2*)&bias[col];
                float2 o0, o1;
                o0.x = (acc[mt][nt][0] + bb.x) * m0; o0.y = (acc[mt][nt][1] + bb.y) * m0;
                o1.x = (acc[mt][nt][2] + bb.x) * m1; o1.y = (acc[mt][nt][3] + bb.y) * m1;
                *(float2*)(C + (size_t)r0 * N + col) = o0;
                *(float2*)(C + (size_t)(r0 + 8) * N + col) = o1;
            }
        }
    } else {
        int colbase = bn + wn;              // 64-aligned; warp tile stays in one part/head
        int part = colbase >> 10;           // 0=k, 1=q, 2=v
        int hh = (colbase & 1023) >> 7;
        int dwarp = colbase & 127;
        int b = bm / S;
        int s0 = bm % S;
        size_t bh64 = (size_t)(b * H_ + hh);
        #pragma unroll
        for (int mt = 0; mt < 4; mt++) {
            int rl0 = wm + mt * 16 + (lane >> 2);
            int gr0 = bm + rl0;
            float mk0 = MASK ? mask[gr0] : 1.f;
            float mk1 = MASK ? mask[gr0 + 8] : 1.f;
            int s_0 = s0 + rl0, s_1 = s_0 + 8;
            #pragma unroll
            for (int nt = 0; nt < 8; nt++) {
                int d = dwarp + nt * 8 + ((lane & 3) << 1);
                int col = colbase + nt * 8 + ((lane & 3) << 1);
                float2 bb = *(const float2*)&bias[col];
                float x0 = (acc[mt][nt][0] + bb.x) * mk0;
                float y0 = (acc[mt][nt][1] + bb.y) * mk0;
                float x1 = (acc[mt][nt][2] + bb.x) * mk1;
                float y1 = (acc[mt][nt][3] + bb.y) * mk1;
                if (gate != nullptr && part < 2) {
                    float2 g2 = *(const float2*)&gate[b * D_ + hh * DHD + d];
                    x0 *= g2.x; y0 *= g2.y; x1 *= g2.x; y1 *= g2.y;
                }
                if (part == 0) {
                    store_h2(oK, (bh64 * T + (s_0 + hasMem)) * DHD + d, x0, y0);
                    store_h2(oK, (bh64 * T + (s_1 + hasMem)) * DHD + d, x1, y1);
                } else if (part == 1) {
                    store_h2(oQ, (bh64 * S + s_0) * DHD + d, x0, y0);
                    store_h2(oQ, (bh64 * S + s_1) * DHD + d, x1, y1);
                } else {
                    store_h2(oV, (bh64 * T + (s_0 + hasMem)) * DHD + d, x0, y0);
                    store_h2(oV, (bh64 * T + (s_1 + hasMem)) * DHD + d, x1, y1);
                }
            }
        }
    }
}

// ---------------- tensor-core flash attention (fp16) ----------------
// CTA: 128 q-rows x 1 head x 1 batch, 8 warps x 16 rows. 64-key tiles, double-buffered.
// Epilogue: writes fp16(resid + attn_out) into the fp16 A-operand buffers.
#define APAD 136
constexpr int A_Q   = 0;
constexpr int A_ST0 = 128 * APAD * 2;            // 34816
constexpr int A_STG = 2 * 64 * APAD * 2;         // 34816 (K | V)
constexpr int A_K   = 0;
constexpr int A_V   = 64 * APAD * 2;             // 17408
constexpr int A_KM  = A_ST0 + 2 * A_STG;         // 104448
constexpr int ATT_SMEM_BYTES = A_KM + 2 * 64 * 4;   // 104960

__global__ __launch_bounds__(256) void attn_mma_kernel(
    const __half* __restrict__ K, const __half* __restrict__ Q,
    const __half* __restrict__ V,
    const float* __restrict__ mask,
    const float* __restrict__ resid,
    __half* __restrict__ outA,
    int S, int T, int hasMem)
{
    extern __shared__ char sm[];
    uint32_t sb = smem_u32(sm);
    float* km = (float*)(sm + A_KM);
    int tid = threadIdx.x, wid = tid >> 5, lane = tid & 31;
    int b = blockIdx.z, h = blockIdx.y, m0 = blockIdx.x * 128;
    size_t bh = (size_t)(b * H_ + h);
    const __half* gQ = Q + (bh * S + m0) * DHD;
    const __half* gK = K + bh * T * DHD;
    const __half* gV = V + bh * T * DHD;

    // Q tile load (once)
    #pragma unroll
    for (int it = 0; it < 8; it++) {
        int id = tid + it * 256; int row = id >> 4, cc = id & 15;
        cp16(sb + A_Q + row * (APAD * 2) + cc * 16, gQ + row * DHD + cc * 8);
    }
    auto load_kv = [&](int kt, int s) {
        int t0 = kt * 64;
        uint32_t st = sb + A_ST0 + s * A_STG;
        const __half* gm[2] = { gK, gV };
        #pragma unroll
        for (int m = 0; m < 2; m++) {
            #pragma unroll
            for (int it = 0; it < 4; it++) {
                int id = tid + it * 256; int row = id >> 4, cc = id & 15;
                int t = t0 + row;
                int tc = (t < T) ? t : (T - 1);
                int sz = (t < T) ? 16 : 0;
                cp16z(st + m * (64 * APAD * 2) + row * (APAD * 2) + cc * 16,
                      gm[m] + (size_t)tc * DHD + cc * 8, sz);
            }
        }
        if (tid < 64) {
            int t = t0 + tid;
            float mv = 0.f;
            if (t < T) mv = (hasMem && t == 0) ? 1.f : mask[(size_t)b * S + (t - hasMem)];
            km[s * 64 + tid] = mv;
        }
    };

    load_kv(0, 0);
    cp_commit();

    float o[16][4];
    #pragma unroll
    for (int i = 0; i < 16; i++) { o[i][0] = 0.f; o[i][1] = 0.f; o[i][2] = 0.f; o[i][3] = 0.f; }
    float mprev0 = -1e30f, mprev1 = -1e30f, lsum0 = 0.f, lsum1 = 0.f;
    const float SCL  = 0.088388347648318447f;
    const float NEGS = -1e9f * 0.088388347648318447f;
    int wm = wid * 16;
    int ntile = (T + 63) / 64;

    for (int kt = 0; kt < ntile; kt++) {
        if (kt + 1 < ntile) { load_kv(kt + 1, (kt + 1) & 1); cp_commit(); cp_wait1(); }
        else cp_wait0();
        __syncthreads();
        uint32_t st = sb + A_ST0 + (kt & 1) * A_STG;

        // ---- scores S[16 x 64] per warp ----
        float sf[8][4];
        #pragma unroll
        for (int i = 0; i < 8; i++) { sf[i][0]=0.f; sf[i][1]=0.f; sf[i][2]=0.f; sf[i][3]=0.f; }
        #pragma unroll
        for (int ks = 0; ks < 128; ks += 16) {
            int arow = wm + (lane & 15), ak = ks + ((lane >> 4) << 3);
            uint32_t ah[4];
            ldmx4(ah, sb + A_Q + (uint32_t)(arow * APAD + ak) * 2);
            int r = lane & 7, qs = lane >> 3;
            #pragma unroll
            for (int pr = 0; pr < 4; pr++) {
                int nn = pr * 16 + ((qs >> 1) << 3) + r;
                int kk2 = ks + ((qs & 1) << 3);
                uint32_t bh4[4];
                ldmx4(bh4, st + A_K + (uint32_t)(nn * APAD + kk2) * 2);
                mma16816(sf[pr * 2 + 0], ah, bh4[0], bh4[1]);
                mma16816(sf[pr * 2 + 1], ah, bh4[2], bh4[3]);
            }
        }
        // ---- mask (before scale), scale, online softmax ----
        const float* kmc = km + (kt & 1) * 64;
        float mx0 = mprev0, mx1 = mprev1;
        #pragma unroll
        for (int nt = 0; nt < 8; nt++) {
            int c0 = nt * 8 + ((lane & 3) << 1);
            float k0v = kmc[c0], k1v = kmc[c0 + 1];
            sf[nt][0] = (k0v != 0.f) ? sf[nt][0] * SCL : NEGS;
            sf[nt][1] = (k1v != 0.f) ? sf[nt][1] * SCL : NEGS;
            sf[nt][2] = (k0v != 0.f) ? sf[nt][2] * SCL : NEGS;
            sf[nt][3] = (k1v != 0.f) ? sf[nt][3] * SCL : NEGS;
            mx0 = fmaxf(mx0, fmaxf(sf[nt][0], sf[nt][1]));
            mx1 = fmaxf(mx1, fmaxf(sf[nt][2], sf[nt][3]));
        }
        mx0 = fmaxf(mx0, __shfl_xor_sync(0xffffffffu, mx0, 1));
        mx0 = fmaxf(mx0, __shfl_xor_sync(0xffffffffu, mx0, 2));
        mx1 = fmaxf(mx1, __shfl_xor_sync(0xffffffffu, mx1, 1));
        mx1 = fmaxf(mx1, __shfl_xor_sync(0xffffffffu, mx1, 2));
        float corr0 = __expf(mprev0 - mx0), corr1 = __expf(mprev1 - mx1);
        mprev0 = mx0; mprev1 = mx1;
        float ps0 = 0.f, ps1 = 0.f;
        #pragma unroll
        for (int nt = 0; nt < 8; nt++) {
            sf[nt][0] = __expf(sf[nt][0] - mx0);
            sf[nt][1] = __expf(sf[nt][1] - mx0);
            sf[nt][2] = __expf(sf[nt][2] - mx1);
            sf[nt][3] = __expf(sf[nt][3] - mx1);
            ps0 += sf[nt][0] + sf[nt][1];
            ps1 += sf[nt][2] + sf[nt][3];
        }
        ps0 += __shfl_xor_sync(0xffffffffu, ps0, 1);
        ps0 += __shfl_xor_sync(0xffffffffu, ps0, 2);
        ps1 += __shfl_xor_sync(0xffffffffu, ps1, 1);
        ps1 += __shfl_xor_sync(0xffffffffu, ps1, 2);
        lsum0 = lsum0 * corr0 + ps0;
        lsum1 = lsum1 * corr1 + ps1;
        #pragma unroll
        for (int dd = 0; dd < 16; dd++) {
            o[dd][0] *= corr0; o[dd][1] *= corr0;
            o[dd][2] *= corr1; o[dd][3] *= corr1;
        }
        // ---- PV: O += P @ V ----
        int mi = lane >> 3, rr = lane & 7;
        #pragma unroll
        for (int kk = 0; kk < 4; kk++) {
            uint32_t ph4[4];
            ph4[0] = packh2(sf[2*kk][0],   sf[2*kk][1]);
            ph4[1] = packh2(sf[2*kk][2],   sf[2*kk][3]);
            ph4[2] = packh2(sf[2*kk+1][0], sf[2*kk+1][1]);
            ph4[3] = packh2(sf[2*kk+1][2], sf[2*kk+1][3]);
            #pragma unroll
            for (int db = 0; db < 8; db++) {
                uint32_t voff = (uint32_t)((kk * 16 + (mi & 1) * 8 + rr) * APAD
                                           + db * 16 + (mi >> 1) * 8) * 2;
                uint32_t vh4[4];
                ldmx4t(vh4, st + A_V + voff);
                mma16816(o[db * 2],     ph4, vh4[0], vh4[1]);
                mma16816(o[db * 2 + 1], ph4, vh4[2], vh4[3]);
            }
        }
        __syncthreads();
    }

    // epilogue: fp16(resid + O/lsum), row-major [B*S, D]
    float i0 = 1.f / lsum0, i1 = 1.f / lsum1;
    int g = lane >> 2;
    size_t row0 = (size_t)(b * S + m0 + wm + g);
    const float* rs0 = resid + row0 * D_ + h * DHD;
    size_t ob0 = row0 * D_ + h * DHD;
    #pragma unroll
    for (int dd = 0; dd < 16; dd++) {
        int d = dd * 8 + ((lane & 3) << 1);
        float2 rv0 = *(const float2*)(rs0 + d);
        float2 rv1 = *(const float2*)(rs0 + 8 * D_ + d);
        store_h2(outA, ob0 + d,          rv0.x + o[dd][0] * i0, rv0.y + o[dd][1] * i0);
        store_h2(outA, ob0 + 8 * D_ + d, rv1.x + o[dd][2] * i1, rv1.y + o[dd][3] * i1);
    }
}

// ---------------- launch ----------------
extern "C" void kernel_launch(void* const* d_in, const int* in_sizes, int n_in,
                              void* d_out, int out_size) {
    const float* v      = (const float*)d_in[0];
    const float* q      = (const float*)d_in[1];
    const float* c      = (const float*)d_in[2];
    const float* v_mask = (const float*)d_in[3];
    const float* q_mask = (const float*)d_in[4];
    const float* c_mask = (const float*)d_in[5];
    const float* Wv4q   = (const float*)d_in[6];
    const float* bv4q   = (const float*)d_in[7];
    const float* Wq4v   = (const float*)d_in[8];
    const float* bq4v   = (const float*)d_in[9];
    const float* Wv     = (const float*)d_in[10];
    const float* bv     = (const float*)d_in[11];
    const float* Wq     = (const float*)d_in[12];
    const float* bq     = (const float*)d_in[13];
    const float* Wc     = (const float*)d_in[14];
    const float* bcin   = (const float*)d_in[15];
    const float* m_v_k  = (const float*)d_in[16];
    const float* m_v_v  = (const float*)d_in[17];
    const float* m_c_k  = (const float*)d_in[18];
    const float* m_c_v  = (const float*)d_in[19];
    const float* Wvo    = (const float*)d_in[20];
    const float* bvo    = (const float*)d_in[21];
    const float* Wqo    = (const float*)d_in[22];
    const float* bqo    = (const float*)d_in[23];
    const float* Wco    = (const float*)d_in[24];
    const float* bco    = (const float*)d_in[25];
    (void)in_sizes; (void)n_in; (void)out_size;

    float *gv4q, *gq4v, *mnv, *mnq, *iv, *iq;
    __half *a_v, *a_q, *a_c, *wt;
    __half *vK,*vQ,*vV, *qK,*qQ,*qV, *cK,*cQ,*cV;
    cudaGetSymbolAddress((void**)&gv4q,  g_gate_v4q);
    cudaGetSymbolAddress((void**)&gq4v,  g_gate_q4v);
    cudaGetSymbolAddress((void**)&mnv,   g_mean_v);
    cudaGetSymbolAddress((void**)&mnq,   g_mean_q);
    cudaGetSymbolAddress((void**)&iv,    g_inv_v);
    cudaGetSymbolAddress((void**)&iq,    g_inv_q);
    cudaGetSymbolAddress((void**)&a_v,   g_a_v);
    cudaGetSymbolAddress((void**)&a_q,   g_a_q);
    cudaGetSymbolAddress((void**)&a_c,   g_a_c);
    cudaGetSymbolAddress((void**)&wt,    g_wt);
    cudaGetSymbolAddress((void**)&vK, g_vK); cudaGetSymbolAddress((void**)&vQ, g_vQ);
    cudaGetSymbolAddress((void**)&vV, g_vV);
    cudaGetSymbolAddress((void**)&qK, g_qK); cudaGetSymbolAddress((void**)&qQ, g_qQ);
    cudaGetSymbolAddress((void**)&qV, g_qV);
    cudaGetSymbolAddress((void**)&cK, g_cK); cudaGetSymbolAddress((void**)&cQ, g_cQ);
    cudaGetSymbolAddress((void**)&cV, g_cV);

    cudaFuncSetAttribute(mma_gemm_kernel<true, true>,   cudaFuncAttributeMaxDynamicSharedMemorySize, MMA_SMEM_BYTES);
    cudaFuncSetAttribute(mma_gemm_kernel<false, false>, cudaFuncAttributeMaxDynamicSharedMemorySize, MMA_SMEM_BYTES);
    cudaFuncSetAttribute(attn_mma_kernel, cudaFuncAttributeMaxDynamicSharedMemorySize, ATT_SMEM_BYTES);

    const size_t WO_V = 0, WO_Q = 3145728, WO_C = 6291456;
    const size_t WO_VO = 9437184, WO_QO = 10485760, WO_CO = 11534336;

    // weight transpose + fp16 convert
    dim3 wtb(32, 8);
    cvt_wT_kernel<<<dim3(N3 / 32, 32), wtb>>>(Wv, wt + WO_V, N3);
    cvt_wT_kernel<<<dim3(N3 / 32, 32), wtb>>>(Wq, wt + WO_Q, N3);
    cvt_wT_kernel<<<dim3(N3 / 32, 32), wtb>>>(Wc, wt + WO_C, N3);
    cvt_wT_kernel<<<dim3(D_ / 32, 32), wtb>>>(Wvo, wt + WO_VO, D_);
    cvt_wT_kernel<<<dim3(D_ / 32, 32), wtb>>>(Wqo, wt + WO_QO, D_);
    cvt_wT_kernel<<<dim3(D_ / 32, 32), wtb>>>(Wco, wt + WO_CO, D_);
    // activation relu + fp16 convert
    cvt_act_kernel<<<16384, 256>>>(v, a_v);
    cvt_act_kernel<<<8192,  256>>>(q, a_q);
    cvt_act_kernel<<<16384, 256>>>(c, a_c);
    // masked means -> gates
    masksum_kernel<<<B_, 256>>>(v_mask, iv, SV);
    masksum_kernel<<<B_, 256>>>(q_mask, iq, SQ);
    mean_relu_kernel<<<dim3(4, B_), 256>>>(v, v_mask, iv, mnv, SV);
    mean_relu_kernel<<<dim3(4, B_), 256>>>(q, q_mask, iq, mnq, SQ);
    gate_kernel<<<dim3(8, B_), 128>>>(mnv, Wv4q, bv4q, gv4q);
    gate_kernel<<<dim3(8, B_), 128>>>(mnq, Wq4v, bq4v, gq4v);
    // memory tokens
    memtok_kernel<<<B_, 1024>>>(vK, vV, m_v_k, m_v_v, gq4v, SV + 1);
    memtok_kernel<<<B_, 1024>>>(cK, cV, m_c_k, m_c_v, nullptr, SC + 1);
    // QKV projections -> fused gated fp16 K/Q/V
    mma_gemm_kernel<true, true><<<dim3(24, 128), 128, MMA_SMEM_BYTES>>>(
        a_v, wt + WO_V, bv, v_mask, nullptr, 0, gq4v, vK, vQ, vV, SV, SV + 1, 1);
    mma_gemm_kernel<true, true><<<dim3(24, 64), 128, MMA_SMEM_BYTES>>>(
        a_q, wt + WO_Q, bq, q_mask, nullptr, 0, gv4q, qK, qQ, qV, SQ, SQ, 0);
    mma_gemm_kernel<true, true><<<dim3(24, 128), 128, MMA_SMEM_BYTES>>>(
        a_c, wt + WO_C, bcin, c_mask, nullptr, 0, nullptr, cK, cQ, cV, SC, SC + 1, 1);
    // tensor-core flash attention; epilogue writes fp16(resid + attn) into A buffers
    attn_mma_kernel<<<dim3(SV / 128, H_, B_), 256, ATT_SMEM_BYTES>>>(
        vK, vQ, vV, v_mask, v, a_v, SV, SV + 1, 1);
    attn_mma_kernel<<<dim3(SQ / 128, H_, B_), 256, ATT_SMEM_BYTES>>>(
        qK, qQ, qV, q_mask, q, a_q, SQ, SQ, 0);
    attn_mma_kernel<<<dim3(SC / 128, H_, B_), 256, ATT_SMEM_BYTES>>>(
        cK, cQ, cV, c_mask, c, a_c, SC, SC + 1, 1);
    // output projections
    float* out = (float*)d_out;
    mma_gemm_kernel<false, false><<<dim3(8, 128), 128, MMA_SMEM_BYTES>>>(
        a_v, wt + WO_VO, bvo, nullptr, out, D_,
        nullptr, nullptr, nullptr, nullptr, 0, 0, 0);
    mma_gemm_kernel<false, false><<<dim3(8, 64), 128, MMA_SMEM_BYTES>>>(
        a_q, wt + WO_QO, bqo, nullptr, out + (size_t)B_ * SV * D_, D_,
        nullptr, nullptr, nullptr, nullptr, 0, 0, 0);
    mma_gemm_kernel<false, false><<<dim3(8, 128), 128, MMA_SMEM_BYTES>>>(
        a_c, wt + WO_CO, bco, nullptr, out + (size_t)B_ * (SV + SQ) * D_, D_,
        nullptr, nullptr, nullptr, nullptr, 0, 0, 0);
}

// round 7
// speedup vs baseline: 6.8235x; 1.0335x over previous
#include <cuda_runtime.h>
#include <cuda_fp16.h>
#include <cstdint>

#define B_   32
#define SV   512
#define SQ   256
#define SC   512
#define D_   1024
#define H_   8
#define DHD  128
#define N3   3072
#define GK   1024

// ---------------- scratch (device globals; no allocations allowed) ----------------
__device__ float g_gate_v4q[32768];
__device__ float g_gate_q4v[32768];
__device__ float g_mean_v[32768];
__device__ float g_mean_q[32768];

// fp16 activations + transposed weights for GEMMs
// (a_* double-duty: relu(x) for QKV proj, then x+attn for out-proj)
__device__ __half g_a_v[16777216];
__device__ __half g_a_q[8388608];
__device__ __half g_a_c[16777216];
__device__ __half g_wt[12582912];
// offsets: Wv=0, Wq=3145728, Wc=6291456, Wvo=9437184, Wqo=10485760, Wco=11534336

// fp16 K/Q/V in [B,H,T,dh] layout (gates + mask pre-applied; mem token at t=0)
__device__ __half g_vK[16809984], g_vQ[16777216], g_vV[16809984];
__device__ __half g_qK[8388608],  g_qQ[8388608],  g_qV[8388608];
__device__ __half g_cK[16809984], g_cQ[16777216], g_cV[16809984];

// ---------------- base-target tensor helpers ----------------
__device__ __forceinline__ uint32_t smem_u32(const void* p) {
    uint32_t a;
    asm("{ .reg .u64 t; cvta.to.shared.u64 t, %1; cvt.u32.u64 %0, t; }" : "=r"(a) : "l"(p));
    return a;
}
__device__ __forceinline__ void cp16(uint32_t dst, const void* src) {
    asm volatile("cp.async.cg.shared.global [%0], [%1], 16;" :: "r"(dst), "l"(src));
}
__device__ __forceinline__ void cp16z(uint32_t dst, const void* src, int sz) {
    asm volatile("cp.async.cg.shared.global [%0], [%1], 16, %2;" :: "r"(dst), "l"(src), "r"(sz));
}
__device__ __forceinline__ void cp_commit() { asm volatile("cp.async.commit_group;" ::: "memory"); }
__device__ __forceinline__ void cp_wait1()  { asm volatile("cp.async.wait_group 1;" ::: "memory"); }
__device__ __forceinline__ void cp_wait0()  { asm volatile("cp.async.wait_group 0;" ::: "memory"); }

__device__ __forceinline__ void ldmx4(uint32_t* r, uint32_t addr) {
    asm volatile("ldmatrix.sync.aligned.m8n8.x4.shared.b16 {%0,%1,%2,%3}, [%4];"
                 : "=r"(r[0]), "=r"(r[1]), "=r"(r[2]), "=r"(r[3]) : "r"(addr));
}
__device__ __forceinline__ void ldmx4t(uint32_t* r, uint32_t addr) {
    asm volatile("ldmatrix.sync.aligned.m8n8.x4.trans.shared.b16 {%0,%1,%2,%3}, [%4];"
                 : "=r"(r[0]), "=r"(r[1]), "=r"(r[2]), "=r"(r[3]) : "r"(addr));
}
__device__ __forceinline__ void mma16816(float* d, const uint32_t* a, uint32_t b0, uint32_t b1) {
    asm volatile("mma.sync.aligned.m16n8k16.row.col.f32.f16.f16.f32 "
                 "{%0,%1,%2,%3}, {%4,%5,%6,%7}, {%8,%9}, {%0,%1,%2,%3};"
                 : "+f"(d[0]), "+f"(d[1]), "+f"(d[2]), "+f"(d[3])
                 : "r"(a[0]), "r"(a[1]), "r"(a[2]), "r"(a[3]), "r"(b0), "r"(b1));
}

// ---------------- fp16 pack helpers ----------------
__device__ __forceinline__ uint32_t packh2(float x, float y) {
    __half2 h = __floats2half2_rn(x, y);
    return *(uint32_t*)&h;
}
__device__ __forceinline__ void store_h2(__half* H, size_t idx, float x, float y) {
    *(__half2*)(H + idx) = __floats2half2_rn(x, y);
}

// ---------------- fused conversion kernels ----------------
struct ActArgs { const float* x[3]; __half* out[3]; int nblk0, nblk1; };
__global__ void cvt_act_kernel(ActArgs a) {
    int bx = blockIdx.x;
    int z, base;
    if (bx < a.nblk0) { z = 0; base = 0; }
    else if (bx < a.nblk0 + a.nblk1) { z = 1; base = a.nblk0; }
    else { z = 2; base = a.nblk0 + a.nblk1; }
    int idx = (bx - base) * 256 + threadIdx.x;
    float4 v = ((const float4*)a.x[z])[idx];
    v.x = fmaxf(v.x, 0.f); v.y = fmaxf(v.y, 0.f);
    v.z = fmaxf(v.z, 0.f); v.w = fmaxf(v.w, 0.f);
    uint2 o;
    o.x = packh2(v.x, v.y);
    o.y = packh2(v.z, v.w);
    ((uint2*)a.out[z])[idx] = o;
}

struct WTArgs { const float* W[6]; __half* out[6]; int N[6]; };
__global__ void cvt_wT_kernel(WTArgs a) {
    int z = blockIdx.z;
    const float* W = a.W[z];
    __half* th = a.out[z];
    int N = a.N[z];
    if (blockIdx.x * 32 >= N) return;
    __shared__ float t[32][33];
    int n0 = blockIdx.x * 32, k0 = blockIdx.y * 32;
    int tx = threadIdx.x, ty = threadIdx.y;   // (32, 8)
    #pragma unroll
    for (int r = 0; r < 4; r++)
        t[ty + 8 * r][tx] = W[(size_t)(k0 + ty + 8 * r) * N + n0 + tx];
    __syncthreads();
    #pragma unroll
    for (int r = 0; r < 4; r++) {
        size_t o = (size_t)(n0 + ty + 8 * r) * GK + k0 + tx;
        th[o] = __float2half_rn(t[tx][ty + 8 * r]);
    }
}

// ---------------- small fused kernels ----------------
// masked mean + relu, mask-sum computed in-block; z selects (v | q)
struct MeanArgs { const float* x[2]; const float* mask[2]; float* out[2]; int S[2]; };
__global__ void mean_relu_kernel(MeanArgs a) {
    __shared__ float red[256];
    __shared__ float sinv;
    int z = blockIdx.z;
    int S = a.S[z];
    int b = blockIdx.y;
    const float* mp = a.mask[z] + (size_t)b * S;
    float s = 0.f;
    for (int t = threadIdx.x; t < S; t += 256) s += mp[t];
    red[threadIdx.x] = s;
    __syncthreads();
    for (int w = 128; w > 0; w >>= 1) {
        if (threadIdx.x < w) red[threadIdx.x] += red[threadIdx.x + w];
        __syncthreads();
    }
    if (threadIdx.x == 0) sinv = 1.f / red[0];
    __syncthreads();
    int d = blockIdx.x * 256 + threadIdx.x;
    const float* xp = a.x[z] + (size_t)b * S * D_ + d;
    float acc = 0.f;
    for (int t = 0; t < S; t++) acc += xp[(size_t)t * D_] * mp[t];
    a.out[z][b * D_ + d] = fmaxf(acc * sinv, 0.f);
}

struct GateArgs { const float* mean[2]; const float* W[2]; const float* bias[2]; float* out[2]; };
__global__ void gate_kernel(GateArgs a) {
    __shared__ float sm[D_];
    int z = blockIdx.z;
    int b = blockIdx.y;
    int n = blockIdx.x * 128 + threadIdx.x;
    const float* rmean = a.mean[z];
    const float* W = a.W[z];
    for (int k = threadIdx.x; k < D_; k += 128) sm[k] = rmean[b * D_ + k];
    __syncthreads();
    float acc = a.bias[z][n];
    #pragma unroll 8
    for (int k = 0; k < D_; k++) acc = fmaf(sm[k], W[(size_t)k * D_ + n], acc);
    a.out[z][b * D_ + n] = 1.f + 1.f / (1.f + __expf(-acc));
}

struct MemArgs { __half* K[2]; __half* V[2]; const float* mk[2]; const float* mv[2];
                 const float* gate[2]; int T[2]; };
__global__ void memtok_kernel(MemArgs a) {
    int z = blockIdx.y;
    int b = blockIdx.x;
    int i = threadIdx.x;
    int h = i >> 7;
    float kv = 32.f * a.mk[z][i];
    if (a.gate[z]) kv *= a.gate[z][b * D_ + i];
    size_t idx = ((size_t)(b * H_ + h) * a.T[z]) * DHD + (i & 127);
    a.K[z][idx] = __float2half_rn(kv);
    a.V[z][idx] = __float2half_rn(a.mv[z][i]);
}

// ---------------- mma.sync fp16 GEMM ----------------
// 128x128 CTA tile, BK=32, 4 warps (2x2), warp tile 64x64, cp.async double buffer.
#define ROWB 40
#define MAT_BYTES (128 * ROWB * 2)           // 10240
#define STAGE_BYTES (2 * MAT_BYTES)          // 20480
#define MMA_SMEM_BYTES (2 * STAGE_BYTES)     // 40960

template <bool MASK, bool SPLIT>
__global__ __launch_bounds__(128, 2) void mma_gemm_kernel(
    const __half* __restrict__ A, const __half* __restrict__ B,
    const float* __restrict__ bias, const float* __restrict__ mask,
    float* __restrict__ C, int N,
    const float* __restrict__ gate,
    __half* oK, __half* oQ, __half* oV,
    int S, int T, int hasMem)
{
    extern __shared__ char smem[];
    uint32_t sbase = smem_u32(smem);
    int tid = threadIdx.x;
    int wid = tid >> 5, lane = tid & 31;
    int bm = blockIdx.y * 128, bn = blockIdx.x * 128;
    int wm = (wid & 1) * 64;
    int wn = (wid >> 1) * 64;

    const __half* srcs[2] = { A + (size_t)bm * GK, B + (size_t)bn * GK };

    float acc[4][8][4];
    #pragma unroll
    for (int i = 0; i < 4; i++)
        #pragma unroll
        for (int j = 0; j < 8; j++)
            #pragma unroll
            for (int k = 0; k < 4; k++) acc[i][j][k] = 0.f;

    int lrow = tid >> 2, lc = tid & 3;
    auto load_stage = [&](int kc, int s) {
        uint32_t st = sbase + s * STAGE_BYTES;
        int k0 = kc * 32;
        #pragma unroll
        for (int m = 0; m < 2; m++) {
            const __half* src = srcs[m];
            uint32_t dst = st + m * MAT_BYTES;
            #pragma unroll
            for (int it = 0; it < 4; it++) {
                int row = lrow + it * 32;
                cp16(dst + row * 80 + lc * 16, src + (size_t)row * GK + k0 + lc * 8);
            }
        }
        cp_commit();
    };

    load_stage(0, 0);

    const int NK = GK / 32;
    for (int kc = 0; kc < NK; kc++) {
        if (kc + 1 < NK) { load_stage(kc + 1, (kc + 1) & 1); cp_wait1(); }
        else cp_wait0();
        __syncthreads();
        uint32_t st = sbase + (kc & 1) * STAGE_BYTES;
        uint32_t sA = st, sB = st + MAT_BYTES;
        #pragma unroll
        for (int ks = 0; ks < 32; ks += 16) {
            uint32_t ah[4][4];
            int arow = wm + (lane & 15);
            int ak = ks + ((lane >> 4) << 3);
            #pragma unroll
            for (int mt = 0; mt < 4; mt++)
                ldmx4(ah[mt], sA + (uint32_t)(((arow + mt * 16) * ROWB + ak) * 2));
            int r = lane & 7, qsel = lane >> 3;
            #pragma unroll
            for (int nt = 0; nt < 4; nt++) {
                int nn = wn + nt * 16 + ((qsel >> 1) << 3) + r;
                int kk = ks + ((qsel & 1) << 3);
                uint32_t bh[4];
                ldmx4(bh, sB + (uint32_t)((nn * ROWB + kk) * 2));
                #pragma unroll
                for (int mt = 0; mt < 4; mt++) {
                    mma16816(acc[mt][nt * 2 + 0], ah[mt], bh[0], bh[1]);
                    mma16816(acc[mt][nt * 2 + 1], ah[mt], bh[2], bh[3]);
                }
            }
        }
        __syncthreads();
    }

    if (!SPLIT) {
        #pragma unroll
        for (int mt = 0; mt < 4; mt++) {
            int r0 = bm + wm + mt * 16 + (lane >> 2);
            float m0 = MASK ? mask[r0] : 1.f;
            float m1 = MASK ? mask[r0 + 8] : 1.f;
            #pragma unroll
            for (int nt = 0; nt < 8; nt++) {
                int col = bn + wn + nt * 8 + ((lane & 3) << 1);
                float2 bb = *(const float2*)&bias[col];
                float2 o0, o1;
                o0.x = (acc[mt][nt][0] + bb.x) * m0; o0.y = (acc[mt][nt][1] + bb.y) * m0;
                o1.x = (acc[mt][nt][2] + bb.x) * m1; o1.y = (acc[mt][nt][3] + bb.y) * m1;
                *(float2*)(C + (size_t)r0 * N + col) = o0;
                *(float2*)(C + (size_t)(r0 + 8) * N + col) = o1;
            }
        }
    } else {
        int colbase = bn + wn;              // 64-aligned; warp tile stays in one part/head
        int part = colbase >> 10;           // 0=k, 1=q, 2=v
        int hh = (colbase & 1023) >> 7;
        int dwarp = colbase & 127;
        int b = bm / S;
        int s0 = bm % S;
        size_t bh64 = (size_t)(b * H_ + hh);
        #pragma unroll
        for (int mt = 0; mt < 4; mt++) {
            int rl0 = wm + mt * 16 + (lane >> 2);
            int gr0 = bm + rl0;
            float mk0 = MASK ? mask[gr0] : 1.f;
            float mk1 = MASK ? mask[gr0 + 8] : 1.f;
            int s_0 = s0 + rl0, s_1 = s_0 + 8;
            #pragma unroll
            for (int nt = 0; nt < 8; nt++) {
                int d = dwarp + nt * 8 + ((lane & 3) << 1);
                int col = colbase + nt * 8 + ((lane & 3) << 1);
                float2 bb = *(const float2*)&bias[col];
                float x0 = (acc[mt][nt][0] + bb.x) * mk0;
                float y0 = (acc[mt][nt][1] + bb.y) * mk0;
                float x1 = (acc[mt][nt][2] + bb.x) * mk1;
                float y1 = (acc[mt][nt][3] + bb.y) * mk1;
                if (gate != nullptr && part < 2) {
                    float2 g2 = *(const float2*)&gate[b * D_ + hh * DHD + d];
                    x0 *= g2.x; y0 *= g2.y; x1 *= g2.x; y1 *= g2.y;
                }
                if (part == 0) {
                    store_h2(oK, (bh64 * T + (s_0 + hasMem)) * DHD + d, x0, y0);
                    store_h2(oK, (bh64 * T + (s_1 + hasMem)) * DHD + d, x1, y1);
                } else if (part == 1) {
                    store_h2(oQ, (bh64 * S + s_0) * DHD + d, x0, y0);
                    store_h2(oQ, (bh64 * S + s_1) * DHD + d, x1, y1);
                } else {
                    store_h2(oV, (bh64 * T + (s_0 + hasMem)) * DHD + d, x0, y0);
                    store_h2(oV, (bh64 * T + (s_1 + hasMem)) * DHD + d, x1, y1);
                }
            }
        }
    }
}

// ---------------- tensor-core flash attention (fp16) ----------------
// CTA: 128 q-rows x 1 head x 1 batch, 8 warps x 16 rows. 64-key tiles, double-buffered.
// __launch_bounds__(256, 2): cap 128 regs so 2 CTAs/SM co-reside (2 x 105KB smem fits 228KB).
#define APAD 136
constexpr int A_Q   = 0;
constexpr int A_ST0 = 128 * APAD * 2;            // 34816
constexpr int A_STG = 2 * 64 * APAD * 2;         // 34816 (K | V)
constexpr int A_K   = 0;
constexpr int A_V   = 64 * APAD * 2;             // 17408
constexpr int A_KM  = A_ST0 + 2 * A_STG;         // 104448
constexpr int ATT_SMEM_BYTES = A_KM + 2 * 64 * 4;   // 104960

__global__ __launch_bounds__(256, 2) void attn_mma_kernel(
    const __half* __restrict__ K, const __half* __restrict__ Q,
    const __half* __restrict__ V,
    const float* __restrict__ mask,
    const float* __restrict__ resid,
    __half* __restrict__ outA,
    int S, int T, int hasMem)
{
    extern __shared__ char sm[];
    uint32_t sb = smem_u32(sm);
    float* km = (float*)(sm + A_KM);
    int tid = threadIdx.x, wid = tid >> 5, lane = tid & 31;
    int b = blockIdx.z, h = blockIdx.y, m0 = blockIdx.x * 128;
    size_t bh = (size_t)(b * H_ + h);
    const __half* gQ = Q + (bh * S + m0) * DHD;
    const __half* gK = K + bh * T * DHD;
    const __half* gV = V + bh * T * DHD;

    // Q tile load (once)
    #pragma unroll
    for (int it = 0; it < 8; it++) {
        int id = tid + it * 256; int row = id >> 4, cc = id & 15;
        cp16(sb + A_Q + row * (APAD * 2) + cc * 16, gQ + row * DHD + cc * 8);
    }
    auto load_kv = [&](int kt, int s) {
        int t0 = kt * 64;
        uint32_t st = sb + A_ST0 + s * A_STG;
        const __half* gm[2] = { gK, gV };
        #pragma unroll
        for (int m = 0; m < 2; m++) {
            #pragma unroll
            for (int it = 0; it < 4; it++) {
                int id = tid + it * 256; int row = id >> 4, cc = id & 15;
                int t = t0 + row;
                int tc = (t < T) ? t : (T - 1);
                int sz = (t < T) ? 16 : 0;
                cp16z(st + m * (64 * APAD * 2) + row * (APAD * 2) + cc * 16,
                      gm[m] + (size_t)tc * DHD + cc * 8, sz);
            }
        }
        if (tid < 64) {
            int t = t0 + tid;
            float mv = 0.f;
            if (t < T) mv = (hasMem && t == 0) ? 1.f : mask[(size_t)b * S + (t - hasMem)];
            km[s * 64 + tid] = mv;
        }
    };

    load_kv(0, 0);
    cp_commit();

    float o[16][4];
    #pragma unroll
    for (int i = 0; i < 16; i++) { o[i][0] = 0.f; o[i][1] = 0.f; o[i][2] = 0.f; o[i][3] = 0.f; }
    float mprev0 = -1e30f, mprev1 = -1e30f, lsum0 = 0.f, lsum1 = 0.f;
    const float SCL  = 0.088388347648318447f;
    const float NEGS = -1e9f * 0.088388347648318447f;
    int wm = wid * 16;
    int ntile = (T + 63) / 64;

    for (int kt = 0; kt < ntile; kt++) {
        if (kt + 1 < ntile) { load_kv(kt + 1, (kt + 1) & 1); cp_commit(); cp_wait1(); }
        else cp_wait0();
        __syncthreads();
        uint32_t st = sb + A_ST0 + (kt & 1) * A_STG;

        // ---- scores S[16 x 64] per warp ----
        float sf[8][4];
        #pragma unroll
        for (int i = 0; i < 8; i++) { sf[i][0]=0.f; sf[i][1]=0.f; sf[i][2]=0.f; sf[i][3]=0.f; }
        #pragma unroll
        for (int ks = 0; ks < 128; ks += 16) {
            int arow = wm + (lane & 15), ak = ks + ((lane >> 4) << 3);
            uint32_t ah[4];
            ldmx4(ah, sb + A_Q + (uint32_t)(arow * APAD + ak) * 2);
            int r = lane & 7, qs = lane >> 3;
            #pragma unroll
            for (int pr = 0; pr < 4; pr++) {
                int nn = pr * 16 + ((qs >> 1) << 3) + r;
                int kk2 = ks + ((qs & 1) << 3);
                uint32_t bh4[4];
                ldmx4(bh4, st + A_K + (uint32_t)(nn * APAD + kk2) * 2);
                mma16816(sf[pr * 2 + 0], ah, bh4[0], bh4[1]);
                mma16816(sf[pr * 2 + 1], ah, bh4[2], bh4[3]);
            }
        }
        // ---- mask (before scale), scale, online softmax ----
        const float* kmc = km + (kt & 1) * 64;
        float mx0 = mprev0, mx1 = mprev1;
        #pragma unroll
        for (int nt = 0; nt < 8; nt++) {
            int c0 = nt * 8 + ((lane & 3) << 1);
            float k0v = kmc[c0], k1v = kmc[c0 + 1];
            sf[nt][0] = (k0v != 0.f) ? sf[nt][0] * SCL : NEGS;
            sf[nt][1] = (k1v != 0.f) ? sf[nt][1] * SCL : NEGS;
            sf[nt][2] = (k0v != 0.f) ? sf[nt][2] * SCL : NEGS;
            sf[nt][3] = (k1v != 0.f) ? sf[nt][3] * SCL : NEGS;
            mx0 = fmaxf(mx0, fmaxf(sf[nt][0], sf[nt][1]));
            mx1 = fmaxf(mx1, fmaxf(sf[nt][2], sf[nt][3]));
        }
        mx0 = fmaxf(mx0, __shfl_xor_sync(0xffffffffu, mx0, 1));
        mx0 = fmaxf(mx0, __shfl_xor_sync(0xffffffffu, mx0, 2));
        mx1 = fmaxf(mx1, __shfl_xor_sync(0xffffffffu, mx1, 1));
        mx1 = fmaxf(mx1, __shfl_xor_sync(0xffffffffu, mx1, 2));
        float corr0 = __expf(mprev0 - mx0), corr1 = __expf(mprev1 - mx1);
        mprev0 = mx0; mprev1 = mx1;
        float ps0 = 0.f, ps1 = 0.f;
        #pragma unroll
        for (int nt = 0; nt < 8; nt++) {
            sf[nt][0] = __expf(sf[nt][0] - mx0);
            sf[nt][1] = __expf(sf[nt][1] - mx0);
            sf[nt][2] = __expf(sf[nt][2] - mx1);
            sf[nt][3] = __expf(sf[nt][3] - mx1);
            ps0 += sf[nt][0] + sf[nt][1];
            ps1 += sf[nt][2] + sf[nt][3];
        }
        ps0 += __shfl_xor_sync(0xffffffffu, ps0, 1);
        ps0 += __shfl_xor_sync(0xffffffffu, ps0, 2);
        ps1 += __shfl_xor_sync(0xffffffffu, ps1, 1);
        ps1 += __shfl_xor_sync(0xffffffffu, ps1, 2);
        lsum0 = lsum0 * corr0 + ps0;
        lsum1 = lsum1 * corr1 + ps1;
        #pragma unroll
        for (int dd = 0; dd < 16; dd++) {
            o[dd][0] *= corr0; o[dd][1] *= corr0;
            o[dd][2] *= corr1; o[dd][3] *= corr1;
        }
        // ---- PV: O += P @ V ----
        int mi = lane >> 3, rr = lane & 7;
        #pragma unroll
        for (int kk = 0; kk < 4; kk++) {
            uint32_t ph4[4];
            ph4[0] = packh2(sf[2*kk][0],   sf[2*kk][1]);
            ph4[1] = packh2(sf[2*kk][2],   sf[2*kk][3]);
            ph4[2] = packh2(sf[2*kk+1][0], sf[2*kk+1][1]);
            ph4[3] = packh2(sf[2*kk+1][2], sf[2*kk+1][3]);
            #pragma unroll
            for (int db = 0; db < 8; db++) {
                uint32_t voff = (uint32_t)((kk * 16 + (mi & 1) * 8 + rr) * APAD
                                           + db * 16 + (mi >> 1) * 8) * 2;
                uint32_t vh4[4];
                ldmx4t(vh4, st + A_V + voff);
                mma16816(o[db * 2],     ph4, vh4[0], vh4[1]);
                mma16816(o[db * 2 + 1], ph4, vh4[2], vh4[3]);
            }
        }
        __syncthreads();
    }

    // epilogue: fp16(resid + O/lsum), row-major [B*S, D]
    float i0 = 1.f / lsum0, i1 = 1.f / lsum1;
    int g = lane >> 2;
    size_t row0 = (size_t)(b * S + m0 + wm + g);
    const float* rs0 = resid + row0 * D_ + h * DHD;
    size_t ob0 = row0 * D_ + h * DHD;
    #pragma unroll
    for (int dd = 0; dd < 16; dd++) {
        int d = dd * 8 + ((lane & 3) << 1);
        float2 rv0 = *(const float2*)(rs0 + d);
        float2 rv1 = *(const float2*)(rs0 + 8 * D_ + d);
        store_h2(outA, ob0 + d,          rv0.x + o[dd][0] * i0, rv0.y + o[dd][1] * i0);
        store_h2(outA, ob0 + 8 * D_ + d, rv1.x + o[dd][2] * i1, rv1.y + o[dd][3] * i1);
    }
}

// ---------------- launch ----------------
extern "C" void kernel_launch(void* const* d_in, const int* in_sizes, int n_in,
                              void* d_out, int out_size) {
    const float* v      = (const float*)d_in[0];
    const float* q      = (const float*)d_in[1];
    const float* c      = (const float*)d_in[2];
    const float* v_mask = (const float*)d_in[3];
    const float* q_mask = (const float*)d_in[4];
    const float* c_mask = (const float*)d_in[5];
    const float* Wv4q   = (const float*)d_in[6];
    const float* bv4q   = (const float*)d_in[7];
    const float* Wq4v   = (const float*)d_in[8];
    const float* bq4v   = (const float*)d_in[9];
    const float* Wv     = (const float*)d_in[10];
    const float* bv     = (const float*)d_in[11];
    const float* Wq     = (const float*)d_in[12];
    const float* bq     = (const float*)d_in[13];
    const float* Wc     = (const float*)d_in[14];
    const float* bcin   = (const float*)d_in[15];
    const float* m_v_k  = (const float*)d_in[16];
    const float* m_v_v  = (const float*)d_in[17];
    const float* m_c_k  = (const float*)d_in[18];
    const float* m_c_v  = (const float*)d_in[19];
    const float* Wvo    = (const float*)d_in[20];
    const float* bvo    = (const float*)d_in[21];
    const float* Wqo    = (const float*)d_in[22];
    const float* bqo    = (const float*)d_in[23];
    const float* Wco    = (const float*)d_in[24];
    const float* bco    = (const float*)d_in[25];
    (void)in_sizes; (void)n_in; (void)out_size;

    float *gv4q, *gq4v, *mnv, *mnq;
    __half *a_v, *a_q, *a_c, *wt;
    __half *vK,*vQ,*vV, *qK,*qQ,*qV, *cK,*cQ,*cV;
    cudaGetSymbolAddress((void**)&gv4q,  g_gate_v4q);
    cudaGetSymbolAddress((void**)&gq4v,  g_gate_q4v);
    cudaGetSymbolAddress((void**)&mnv,   g_mean_v);
    cudaGetSymbolAddress((void**)&mnq,   g_mean_q);
    cudaGetSymbolAddress((void**)&a_v,   g_a_v);
    cudaGetSymbolAddress((void**)&a_q,   g_a_q);
    cudaGetSymbolAddress((void**)&a_c,   g_a_c);
    cudaGetSymbolAddress((void**)&wt,    g_wt);
    cudaGetSymbolAddress((void**)&vK, g_vK); cudaGetSymbolAddress((void**)&vQ, g_vQ);
    cudaGetSymbolAddress((void**)&vV, g_vV);
    cudaGetSymbolAddress((void**)&qK, g_qK); cudaGetSymbolAddress((void**)&qQ, g_qQ);
    cudaGetSymbolAddress((void**)&qV, g_qV);
    cudaGetSymbolAddress((void**)&cK, g_cK); cudaGetSymbolAddress((void**)&cQ, g_cQ);
    cudaGetSymbolAddress((void**)&cV, g_cV);

    cudaFuncSetAttribute(mma_gemm_kernel<true, true>,   cudaFuncAttributeMaxDynamicSharedMemorySize, MMA_SMEM_BYTES);
    cudaFuncSetAttribute(mma_gemm_kernel<false, false>, cudaFuncAttributeMaxDynamicSharedMemorySize, MMA_SMEM_BYTES);
    cudaFuncSetAttribute(attn_mma_kernel, cudaFuncAttributeMaxDynamicSharedMemorySize, ATT_SMEM_BYTES);

    const size_t WO_V = 0, WO_Q = 3145728, WO_C = 6291456;
    const size_t WO_VO = 9437184, WO_QO = 10485760, WO_CO = 11534336;

    // 1) weight transpose + fp16 convert (one launch, z over 6 weights)
    {
        WTArgs wa;
        wa.W[0] = Wv;  wa.out[0] = wt + WO_V;  wa.N[0] = N3;
        wa.W[1] = Wq;  wa.out[1] = wt + WO_Q;  wa.N[1] = N3;
        wa.W[2] = Wc;  wa.out[2] = wt + WO_C;  wa.N[2] = N3;
        wa.W[3] = Wvo; wa.out[3] = wt + WO_VO; wa.N[3] = D_;
        wa.W[4] = Wqo; wa.out[4] = wt + WO_QO; wa.N[4] = D_;
        wa.W[5] = Wco; wa.out[5] = wt + WO_CO; wa.N[5] = D_;
        cvt_wT_kernel<<<dim3(N3 / 32, 32, 6), dim3(32, 8)>>>(wa);
    }
    // 2) activation relu + fp16 convert (one launch over 3 tensors)
    {
        ActArgs aa;
        aa.x[0] = v; aa.out[0] = a_v; aa.nblk0 = 16384;
        aa.x[1] = q; aa.out[1] = a_q; aa.nblk1 = 8192;
        aa.x[2] = c; aa.out[2] = a_c;
        cvt_act_kernel<<<16384 + 8192 + 16384, 256>>>(aa);
    }
    // 3) masked means (mask-sum fused in-block; z over v/q)
    {
        MeanArgs ma;
        ma.x[0] = v; ma.mask[0] = v_mask; ma.out[0] = mnv; ma.S[0] = SV;
        ma.x[1] = q; ma.mask[1] = q_mask; ma.out[1] = mnq; ma.S[1] = SQ;
        mean_relu_kernel<<<dim3(4, B_, 2), 256>>>(ma);
    }
    // 4) gates (z over v4q/q4v)
    {
        GateArgs ga;
        ga.mean[0] = mnv; ga.W[0] = Wv4q; ga.bias[0] = bv4q; ga.out[0] = gv4q;
        ga.mean[1] = mnq; ga.W[1] = Wq4v; ga.bias[1] = bq4v; ga.out[1] = gq4v;
        gate_kernel<<<dim3(8, B_, 2), 128>>>(ga);
    }
    // 5) memory tokens (z over v/c streams)
    {
        MemArgs me;
        me.K[0] = vK; me.V[0] = vV; me.mk[0] = m_v_k; me.mv[0] = m_v_v;
        me.gate[0] = gq4v; me.T[0] = SV + 1;
        me.K[1] = cK; me.V[1] = cV; me.mk[1] = m_c_k; me.mv[1] = m_c_v;
        me.gate[1] = nullptr; me.T[1] = SC + 1;
        memtok_kernel<<<dim3(B_, 2), 1024>>>(me);
    }
    // QKV projections -> fused gated fp16 K/Q/V
    mma_gemm_kernel<true, true><<<dim3(24, 128), 128, MMA_SMEM_BYTES>>>(
        a_v, wt + WO_V, bv, v_mask, nullptr, 0, gq4v, vK, vQ, vV, SV, SV + 1, 1);
    mma_gemm_kernel<true, true><<<dim3(24, 64), 128, MMA_SMEM_BYTES>>>(
        a_q, wt + WO_Q, bq, q_mask, nullptr, 0, gv4q, qK, qQ, qV, SQ, SQ, 0);
    mma_gemm_kernel<true, true><<<dim3(24, 128), 128, MMA_SMEM_BYTES>>>(
        a_c, wt + WO_C, bcin, c_mask, nullptr, 0, nullptr, cK, cQ, cV, SC, SC + 1, 1);
    // tensor-core flash attention; epilogue writes fp16(resid + attn) into A buffers
    attn_mma_kernel<<<dim3(SV / 128, H_, B_), 256, ATT_SMEM_BYTES>>>(
        vK, vQ, vV, v_mask, v, a_v, SV, SV + 1, 1);
    attn_mma_kernel<<<dim3(SQ / 128, H_, B_), 256, ATT_SMEM_BYTES>>>(
        qK, qQ, qV, q_mask, q, a_q, SQ, SQ, 0);
    attn_mma_kernel<<<dim3(SC / 128, H_, B_), 256, ATT_SMEM_BYTES>>>(
        cK, cQ, cV, c_mask, c, a_c, SC, SC + 1, 1);
    // output projections
    float* out = (float*)d_out;
    mma_gemm_kernel<false, false><<<dim3(8, 128), 128, MMA_SMEM_BYTES>>>(
        a_v, wt + WO_VO, bvo, nullptr, out, D_,
        nullptr, nullptr, nullptr, nullptr, 0, 0, 0);
    mma_gemm_kernel<false, false><<<dim3(8, 64), 128, MMA_SMEM_BYTES>>>(
        a_q, wt + WO_QO, bqo, nullptr, out + (size_t)B_ * SV * D_, D_,
        nullptr, nullptr, nullptr, nullptr, 0, 0, 0);
    mma_gemm_kernel<false, false><<<dim3(8, 128), 128, MMA_SMEM_BYTES>>>(
        a_c, wt + WO_CO, bco, nullptr, out + (size_t)B_ * (SV + SQ) * D_, D_,
        nullptr, nullptr, nullptr, nullptr, 0, 0, 0);
}

// round 8
// speedup vs baseline: 7.5298x; 1.1035x over previous
#include <cuda_runtime.h>
#include <cuda_fp16.h>
#include <cstdint>

#define B_   32
#define SV   512
#define SQ   256
#define SC   512
#define D_   1024
#define H_   8
#define DHD  128
#define N3   3072
#define GK   1024

// ---------------- scratch (device globals; no allocations allowed) ----------------
__device__ float g_gate_v4q[32768];
__device__ float g_gate_q4v[32768];
__device__ float g_mean_v[32768];
__device__ float g_mean_q[32768];

// fp16 activations + transposed weights for GEMMs
__device__ __half g_a_v[16777216];
__device__ __half g_a_q[8388608];
__device__ __half g_a_c[16777216];
__device__ __half g_wt[12582912];
// offsets: Wv=0, Wq=3145728, Wc=6291456, Wvo=9437184, Wqo=10485760, Wco=11534336

// fp16 K/Q/V in [B,H,T,dh] layout (gates + mask pre-applied; mem token at t=0)
__device__ __half g_vK[16809984], g_vQ[16777216], g_vV[16809984];
__device__ __half g_qK[8388608],  g_qQ[8388608],  g_qV[8388608];
__device__ __half g_cK[16809984], g_cQ[16777216], g_cV[16809984];

// ---------------- base-target tensor helpers ----------------
__device__ __forceinline__ uint32_t smem_u32(const void* p) {
    uint32_t a;
    asm("{ .reg .u64 t; cvta.to.shared.u64 t, %1; cvt.u32.u64 %0, t; }" : "=r"(a) : "l"(p));
    return a;
}
__device__ __forceinline__ void cp16(uint32_t dst, const void* src) {
    asm volatile("cp.async.cg.shared.global [%0], [%1], 16;" :: "r"(dst), "l"(src));
}
__device__ __forceinline__ void cp16z(uint32_t dst, const void* src, int sz) {
    asm volatile("cp.async.cg.shared.global [%0], [%1], 16, %2;" :: "r"(dst), "l"(src), "r"(sz));
}
__device__ __forceinline__ void cp_commit() { asm volatile("cp.async.commit_group;" ::: "memory"); }
__device__ __forceinline__ void cp_wait1()  { asm volatile("cp.async.wait_group 1;" ::: "memory"); }
__device__ __forceinline__ void cp_wait0()  { asm volatile("cp.async.wait_group 0;" ::: "memory"); }

__device__ __forceinline__ void ldmx4(uint32_t* r, uint32_t addr) {
    asm volatile("ldmatrix.sync.aligned.m8n8.x4.shared.b16 {%0,%1,%2,%3}, [%4];"
                 : "=r"(r[0]), "=r"(r[1]), "=r"(r[2]), "=r"(r[3]) : "r"(addr));
}
__device__ __forceinline__ void ldmx4t(uint32_t* r, uint32_t addr) {
    asm volatile("ldmatrix.sync.aligned.m8n8.x4.trans.shared.b16 {%0,%1,%2,%3}, [%4];"
                 : "=r"(r[0]), "=r"(r[1]), "=r"(r[2]), "=r"(r[3]) : "r"(addr));
}
__device__ __forceinline__ void mma16816(float* d, const uint32_t* a, uint32_t b0, uint32_t b1) {
    asm volatile("mma.sync.aligned.m16n8k16.row.col.f32.f16.f16.f32 "
                 "{%0,%1,%2,%3}, {%4,%5,%6,%7}, {%8,%9}, {%0,%1,%2,%3};"
                 : "+f"(d[0]), "+f"(d[1]), "+f"(d[2]), "+f"(d[3])
                 : "r"(a[0]), "r"(a[1]), "r"(a[2]), "r"(a[3]), "r"(b0), "r"(b1));
}

// ---------------- fp16 pack helpers ----------------
__device__ __forceinline__ uint32_t packh2(float x, float y) {
    __half2 h = __floats2half2_rn(x, y);
    return *(uint32_t*)&h;
}
__device__ __forceinline__ void store_h2(__half* H, size_t idx, float x, float y) {
    *(__half2*)(H + idx) = __floats2half2_rn(x, y);
}

// ---------------- fused conversion kernels ----------------
struct ActArgs { const float* x[3]; __half* out[3]; int nblk0, nblk1; };
__global__ void cvt_act_kernel(ActArgs a) {
    int bx = blockIdx.x;
    int z, base;
    if (bx < a.nblk0) { z = 0; base = 0; }
    else if (bx < a.nblk0 + a.nblk1) { z = 1; base = a.nblk0; }
    else { z = 2; base = a.nblk0 + a.nblk1; }
    int idx = (bx - base) * 256 + threadIdx.x;
    float4 v = ((const float4*)a.x[z])[idx];
    v.x = fmaxf(v.x, 0.f); v.y = fmaxf(v.y, 0.f);
    v.z = fmaxf(v.z, 0.f); v.w = fmaxf(v.w, 0.f);
    uint2 o;
    o.x = packh2(v.x, v.y);
    o.y = packh2(v.z, v.w);
    ((uint2*)a.out[z])[idx] = o;
}

struct WTArgs { const float* W[6]; __half* out[6]; int N[6]; };
__global__ void cvt_wT_kernel(WTArgs a) {
    int z = blockIdx.z;
    const float* W = a.W[z];
    __half* th = a.out[z];
    int N = a.N[z];
    if (blockIdx.x * 32 >= N) return;
    __shared__ float t[32][33];
    int n0 = blockIdx.x * 32, k0 = blockIdx.y * 32;
    int tx = threadIdx.x, ty = threadIdx.y;   // (32, 8)
    #pragma unroll
    for (int r = 0; r < 4; r++)
        t[ty + 8 * r][tx] = W[(size_t)(k0 + ty + 8 * r) * N + n0 + tx];
    __syncthreads();
    #pragma unroll
    for (int r = 0; r < 4; r++) {
        size_t o = (size_t)(n0 + ty + 8 * r) * GK + k0 + tx;
        th[o] = __float2half_rn(t[tx][ty + 8 * r]);
    }
}

// ---------------- small fused kernels ----------------
// masked mean + relu, mask-sum computed in-block; z selects (v | q). 4-way ILP.
struct MeanArgs { const float* x[2]; const float* mask[2]; float* out[2]; int S[2]; };
__global__ void mean_relu_kernel(MeanArgs a) {
    __shared__ float red[256];
    __shared__ float sinv;
    int z = blockIdx.z;
    int S = a.S[z];
    int b = blockIdx.y;
    const float* mp = a.mask[z] + (size_t)b * S;
    float s = 0.f;
    for (int t = threadIdx.x; t < S; t += 256) s += mp[t];
    red[threadIdx.x] = s;
    __syncthreads();
    for (int w = 128; w > 0; w >>= 1) {
        if (threadIdx.x < w) red[threadIdx.x] += red[threadIdx.x + w];
        __syncthreads();
    }
    if (threadIdx.x == 0) sinv = 1.f / red[0];
    __syncthreads();
    int d = blockIdx.x * 256 + threadIdx.x;
    const float* xp = a.x[z] + (size_t)b * S * D_ + d;
    float a0 = 0.f, a1 = 0.f, a2 = 0.f, a3 = 0.f;
    for (int t = 0; t < S; t += 4) {
        a0 = fmaf(xp[(size_t)(t + 0) * D_], mp[t + 0], a0);
        a1 = fmaf(xp[(size_t)(t + 1) * D_], mp[t + 1], a1);
        a2 = fmaf(xp[(size_t)(t + 2) * D_], mp[t + 2], a2);
        a3 = fmaf(xp[(size_t)(t + 3) * D_], mp[t + 3], a3);
    }
    a.out[z][b * D_ + d] = fmaxf(((a0 + a1) + (a2 + a3)) * sinv, 0.f);
}

// gate: k-parallel (4 k-groups x 128 n), smem reduce. grid (8, B, 2), block 512.
struct GateArgs { const float* mean[2]; const float* W[2]; const float* bias[2]; float* out[2]; };
__global__ __launch_bounds__(512) void gate_kernel(GateArgs a) {
    __shared__ float sm[D_];
    __shared__ float red[512];
    int z = blockIdx.z;
    int b = blockIdx.y;
    int tid = threadIdx.x;
    int g = tid >> 7;            // k-group 0..3
    int nl = tid & 127;
    const float* rmean = a.mean[z];
    const float* W = a.W[z];
    for (int k = tid; k < D_; k += 512) sm[k] = rmean[b * D_ + k];
    __syncthreads();
    int n = blockIdx.x * 128 + nl;
    int k0 = g * 256;
    float acc = 0.f;
    #pragma unroll 8
    for (int k = 0; k < 256; k++)
        acc = fmaf(sm[k0 + k], W[(size_t)(k0 + k) * D_ + n], acc);
    red[tid] = acc;
    __syncthreads();
    if (g == 0) {
        float t = red[nl] + red[nl + 128] + red[nl + 256] + red[nl + 384] + a.bias[z][n];
        a.out[z][b * D_ + n] = 1.f + 1.f / (1.f + __expf(-t));
    }
}

struct MemArgs { __half* K[2]; __half* V[2]; const float* mk[2]; const float* mv[2];
                 const float* gate[2]; int T[2]; };
__global__ void memtok_kernel(MemArgs a) {
    int z = blockIdx.y;
    int b = blockIdx.x;
    int i = threadIdx.x;
    int h = i >> 7;
    float kv = 32.f * a.mk[z][i];
    if (a.gate[z]) kv *= a.gate[z][b * D_ + i];
    size_t idx = ((size_t)(b * H_ + h) * a.T[z]) * DHD + (i & 127);
    a.K[z][idx] = __float2half_rn(kv);
    a.V[z][idx] = __float2half_rn(a.mv[z][i]);
}

// ---------------- mma.sync fp16 GEMM (3-stream merged) ----------------
#define ROWB 40
#define MAT_BYTES (128 * ROWB * 2)
#define STAGE_BYTES (2 * MAT_BYTES)
#define MMA_SMEM_BYTES (2 * STAGE_BYTES)

struct GemmS {
    const __half *A, *B;
    const float *bias, *mask, *gate;
    __half *oK, *oQ, *oV;
    float* C;
    int S, T, hasMem;
};
struct Gemm3 { GemmS s[3]; int nby0, nby1; };

template <bool MASK, bool SPLIT>
__global__ __launch_bounds__(128, 2) void mma_gemm_kernel(Gemm3 ga, int N)
{
    extern __shared__ char smem[];
    uint32_t sbase = smem_u32(smem);
    int tid = threadIdx.x;
    int wid = tid >> 5, lane = tid & 31;
    int byg = blockIdx.y;
    int z, ybase;
    if (byg < ga.nby0) { z = 0; ybase = 0; }
    else if (byg < ga.nby0 + ga.nby1) { z = 1; ybase = ga.nby0; }
    else { z = 2; ybase = ga.nby0 + ga.nby1; }
    const GemmS s = ga.s[z];
    int bm = (byg - ybase) * 128, bn = blockIdx.x * 128;
    int wm = (wid & 1) * 64;
    int wn = (wid >> 1) * 64;

    const __half* srcs[2] = { s.A + (size_t)bm * GK, s.B + (size_t)bn * GK };

    float acc[4][8][4];
    #pragma unroll
    for (int i = 0; i < 4; i++)
        #pragma unroll
        for (int j = 0; j < 8; j++)
            #pragma unroll
            for (int k = 0; k < 4; k++) acc[i][j][k] = 0.f;

    int lrow = tid >> 2, lc = tid & 3;
    auto load_stage = [&](int kc, int st2) {
        uint32_t st = sbase + st2 * STAGE_BYTES;
        int k0 = kc * 32;
        #pragma unroll
        for (int m = 0; m < 2; m++) {
            const __half* src = srcs[m];
            uint32_t dst = st + m * MAT_BYTES;
            #pragma unroll
            for (int it = 0; it < 4; it++) {
                int row = lrow + it * 32;
                cp16(dst + row * 80 + lc * 16, src + (size_t)row * GK + k0 + lc * 8);
            }
        }
        cp_commit();
    };

    load_stage(0, 0);

    const int NK = GK / 32;
    for (int kc = 0; kc < NK; kc++) {
        if (kc + 1 < NK) { load_stage(kc + 1, (kc + 1) & 1); cp_wait1(); }
        else cp_wait0();
        __syncthreads();
        uint32_t st = sbase + (kc & 1) * STAGE_BYTES;
        uint32_t sA = st, sB = st + MAT_BYTES;
        #pragma unroll
        for (int ks = 0; ks < 32; ks += 16) {
            uint32_t ah[4][4];
            int arow = wm + (lane & 15);
            int ak = ks + ((lane >> 4) << 3);
            #pragma unroll
            for (int mt = 0; mt < 4; mt++)
                ldmx4(ah[mt], sA + (uint32_t)(((arow + mt * 16) * ROWB + ak) * 2));
            int r = lane & 7, qsel = lane >> 3;
            #pragma unroll
            for (int nt = 0; nt < 4; nt++) {
                int nn = wn + nt * 16 + ((qsel >> 1) << 3) + r;
                int kk = ks + ((qsel & 1) << 3);
                uint32_t bh[4];
                ldmx4(bh, sB + (uint32_t)((nn * ROWB + kk) * 2));
                #pragma unroll
                for (int mt = 0; mt < 4; mt++) {
                    mma16816(acc[mt][nt * 2 + 0], ah[mt], bh[0], bh[1]);
                    mma16816(acc[mt][nt * 2 + 1], ah[mt], bh[2], bh[3]);
                }
            }
        }
        __syncthreads();
    }

    if (!SPLIT) {
        #pragma unroll
        for (int mt = 0; mt < 4; mt++) {
            int r0 = bm + wm + mt * 16 + (lane >> 2);
            float m0 = MASK ? s.mask[r0] : 1.f;
            float m1 = MASK ? s.mask[r0 + 8] : 1.f;
            #pragma unroll
            for (int nt = 0; nt < 8; nt++) {
                int col = bn + wn + nt * 8 + ((lane & 3) << 1);
                float2 bb = *(const float2*)&s.bias[col];
                float2 o0, o1;
                o0.x = (acc[mt][nt][0] + bb.x) * m0; o0.y = (acc[mt][nt][1] + bb.y) * m0;
                o1.x = (acc[mt][nt][2] + bb.x) * m1; o1.y = (acc[mt][nt][3] + bb.y) * m1;
                *(float2*)(s.C + (size_t)r0 * N + col) = o0;
                *(float2*)(s.C + (size_t)(r0 + 8) * N + col) = o1;
            }
        }
    } else {
        int colbase = bn + wn;
        int part = colbase >> 10;           // 0=k, 1=q, 2=v
        int hh = (colbase & 1023) >> 7;
        int dwarp = colbase & 127;
        int b = bm / s.S;
        int s0 = bm % s.S;
        size_t bh64 = (size_t)(b * H_ + hh);
        #pragma unroll
        for (int mt = 0; mt < 4; mt++) {
            int rl0 = wm + mt * 16 + (lane >> 2);
            int gr0 = bm + rl0;
            float mk0 = MASK ? s.mask[gr0] : 1.f;
            float mk1 = MASK ? s.mask[gr0 + 8] : 1.f;
            int s_0 = s0 + rl0, s_1 = s_0 + 8;
            #pragma unroll
            for (int nt = 0; nt < 8; nt++) {
                int d = dwarp + nt * 8 + ((lane & 3) << 1);
                int col = colbase + nt * 8 + ((lane & 3) << 1);
                float2 bb = *(const float2*)&s.bias[col];
                float x0 = (acc[mt][nt][0] + bb.x) * mk0;
                float y0 = (acc[mt][nt][1] + bb.y) * mk0;
                float x1 = (acc[mt][nt][2] + bb.x) * mk1;
                float y1 = (acc[mt][nt][3] + bb.y) * mk1;
                if (s.gate != nullptr && part < 2) {
                    float2 g2 = *(const float2*)&s.gate[b * D_ + hh * DHD + d];
                    x0 *= g2.x; y0 *= g2.y; x1 *= g2.x; y1 *= g2.y;
                }
                if (part == 0) {
                    store_h2(s.oK, (bh64 * s.T + (s_0 + s.hasMem)) * DHD + d, x0, y0);
                    store_h2(s.oK, (bh64 * s.T + (s_1 + s.hasMem)) * DHD + d, x1, y1);
                } else if (part == 1) {
                    store_h2(s.oQ, (bh64 * s.S + s_0) * DHD + d, x0, y0);
                    store_h2(s.oQ, (bh64 * s.S + s_1) * DHD + d, x1, y1);
                } else {
                    store_h2(s.oV, (bh64 * s.T + (s_0 + s.hasMem)) * DHD + d, x0, y0);
                    store_h2(s.oV, (bh64 * s.T + (s_1 + s.hasMem)) * DHD + d, x1, y1);
                }
            }
        }
    }
}

// ---------------- tensor-core flash attention (fp16, 3-stream merged) ----------------
#define APAD 136
constexpr int A_Q   = 0;
constexpr int A_ST0 = 128 * APAD * 2;
constexpr int A_STG = 2 * 64 * APAD * 2;
constexpr int A_K   = 0;
constexpr int A_V   = 64 * APAD * 2;
constexpr int A_KM  = A_ST0 + 2 * A_STG;
constexpr int ATT_SMEM_BYTES = A_KM + 2 * 64 * 4;

struct AttnS {
    const __half *K, *Q, *V;
    const float *mask, *resid;
    __half* outA;
    int S, T, hasMem;
};
struct Attn3 { AttnS s[3]; int nbx0, nbx1; };

__global__ __launch_bounds__(256, 2) void attn_mma_kernel(Attn3 aa)
{
    extern __shared__ char sm[];
    uint32_t sb = smem_u32(sm);
    float* km = (float*)(sm + A_KM);
    int tid = threadIdx.x, wid = tid >> 5, lane = tid & 31;
    int bxg = blockIdx.x;
    int z, xbase;
    if (bxg < aa.nbx0) { z = 0; xbase = 0; }
    else if (bxg < aa.nbx0 + aa.nbx1) { z = 1; xbase = aa.nbx0; }
    else { z = 2; xbase = aa.nbx0 + aa.nbx1; }
    const AttnS s = aa.s[z];
    int S = s.S, T = s.T, hasMem = s.hasMem;
    int b = blockIdx.z, h = blockIdx.y, m0 = (bxg - xbase) * 128;
    size_t bh = (size_t)(b * H_ + h);
    const __half* gQ = s.Q + (bh * S + m0) * DHD;
    const __half* gK = s.K + bh * T * DHD;
    const __half* gV = s.V + bh * T * DHD;

    // Q tile load (once)
    #pragma unroll
    for (int it = 0; it < 8; it++) {
        int id = tid + it * 256; int row = id >> 4, cc = id & 15;
        cp16(sb + A_Q + row * (APAD * 2) + cc * 16, gQ + row * DHD + cc * 8);
    }
    auto load_kv = [&](int kt, int st2) {
        int t0 = kt * 64;
        uint32_t st = sb + A_ST0 + st2 * A_STG;
        const __half* gm[2] = { gK, gV };
        #pragma unroll
        for (int m = 0; m < 2; m++) {
            #pragma unroll
            for (int it = 0; it < 4; it++) {
                int id = tid + it * 256; int row = id >> 4, cc = id & 15;
                int t = t0 + row;
                int tc = (t < T) ? t : (T - 1);
                int sz = (t < T) ? 16 : 0;
                cp16z(st + m * (64 * APAD * 2) + row * (APAD * 2) + cc * 16,
                      gm[m] + (size_t)tc * DHD + cc * 8, sz);
            }
        }
        if (tid < 64) {
            int t = t0 + tid;
            float mv = 0.f;
            if (t < T) mv = (hasMem && t == 0) ? 1.f : s.mask[(size_t)b * S + (t - hasMem)];
            km[st2 * 64 + tid] = mv;
        }
    };

    load_kv(0, 0);
    cp_commit();

    float o[16][4];
    #pragma unroll
    for (int i = 0; i < 16; i++) { o[i][0] = 0.f; o[i][1] = 0.f; o[i][2] = 0.f; o[i][3] = 0.f; }
    float mprev0 = -1e30f, mprev1 = -1e30f, lsum0 = 0.f, lsum1 = 0.f;
    const float SCL  = 0.088388347648318447f;
    const float NEGS = -1e9f * 0.088388347648318447f;
    int wm = wid * 16;
    int ntile = (T + 63) / 64;

    for (int kt = 0; kt < ntile; kt++) {
        if (kt + 1 < ntile) { load_kv(kt + 1, (kt + 1) & 1); cp_commit(); cp_wait1(); }
        else cp_wait0();
        __syncthreads();
        uint32_t st = sb + A_ST0 + (kt & 1) * A_STG;

        float sf[8][4];
        #pragma unroll
        for (int i = 0; i < 8; i++) { sf[i][0]=0.f; sf[i][1]=0.f; sf[i][2]=0.f; sf[i][3]=0.f; }
        #pragma unroll
        for (int ks = 0; ks < 128; ks += 16) {
            int arow = wm + (lane & 15), ak = ks + ((lane >> 4) << 3);
            uint32_t ah[4];
            ldmx4(ah, sb + A_Q + (uint32_t)(arow * APAD + ak) * 2);
            int r = lane & 7, qs = lane >> 3;
            #pragma unroll
            for (int pr = 0; pr < 4; pr++) {
                int nn = pr * 16 + ((qs >> 1) << 3) + r;
                int kk2 = ks + ((qs & 1) << 3);
                uint32_t bh4[4];
                ldmx4(bh4, st + A_K + (uint32_t)(nn * APAD + kk2) * 2);
                mma16816(sf[pr * 2 + 0], ah, bh4[0], bh4[1]);
                mma16816(sf[pr * 2 + 1], ah, bh4[2], bh4[3]);
            }
        }
        const float* kmc = km + (kt & 1) * 64;
        float mx0 = mprev0, mx1 = mprev1;
        #pragma unroll
        for (int nt = 0; nt < 8; nt++) {
            int c0 = nt * 8 + ((lane & 3) << 1);
            float k0v = kmc[c0], k1v = kmc[c0 + 1];
            sf[nt][0] = (k0v != 0.f) ? sf[nt][0] * SCL : NEGS;
            sf[nt][1] = (k1v != 0.f) ? sf[nt][1] * SCL : NEGS;
            sf[nt][2] = (k0v != 0.f) ? sf[nt][2] * SCL : NEGS;
            sf[nt][3] = (k1v != 0.f) ? sf[nt][3] * SCL : NEGS;
            mx0 = fmaxf(mx0, fmaxf(sf[nt][0], sf[nt][1]));
            mx1 = fmaxf(mx1, fmaxf(sf[nt][2], sf[nt][3]));
        }
        mx0 = fmaxf(mx0, __shfl_xor_sync(0xffffffffu, mx0, 1));
        mx0 = fmaxf(mx0, __shfl_xor_sync(0xffffffffu, mx0, 2));
        mx1 = fmaxf(mx1, __shfl_xor_sync(0xffffffffu, mx1, 1));
        mx1 = fmaxf(mx1, __shfl_xor_sync(0xffffffffu, mx1, 2));
        float corr0 = __expf(mprev0 - mx0), corr1 = __expf(mprev1 - mx1);
        mprev0 = mx0; mprev1 = mx1;
        float ps0 = 0.f, ps1 = 0.f;
        #pragma unroll
        for (int nt = 0; nt < 8; nt++) {
            sf[nt][0] = __expf(sf[nt][0] - mx0);
            sf[nt][1] = __expf(sf[nt][1] - mx0);
            sf[nt][2] = __expf(sf[nt][2] - mx1);
            sf[nt][3] = __expf(sf[nt][3] - mx1);
            ps0 += sf[nt][0] + sf[nt][1];
            ps1 += sf[nt][2] + sf[nt][3];
        }
        ps0 += __shfl_xor_sync(0xffffffffu, ps0, 1);
        ps0 += __shfl_xor_sync(0xffffffffu, ps0, 2);
        ps1 += __shfl_xor_sync(0xffffffffu, ps1, 1);
        ps1 += __shfl_xor_sync(0xffffffffu, ps1, 2);
        lsum0 = lsum0 * corr0 + ps0;
        lsum1 = lsum1 * corr1 + ps1;
        #pragma unroll
        for (int dd = 0; dd < 16; dd++) {
            o[dd][0] *= corr0; o[dd][1] *= corr0;
            o[dd][2] *= corr1; o[dd][3] *= corr1;
        }
        int mi = lane >> 3, rr = lane & 7;
        #pragma unroll
        for (int kk = 0; kk < 4; kk++) {
            uint32_t ph4[4];
            ph4[0] = packh2(sf[2*kk][0],   sf[2*kk][1]);
            ph4[1] = packh2(sf[2*kk][2],   sf[2*kk][3]);
            ph4[2] = packh2(sf[2*kk+1][0], sf[2*kk+1][1]);
            ph4[3] = packh2(sf[2*kk+1][2], sf[2*kk+1][3]);
            #pragma unroll
            for (int db = 0; db < 8; db++) {
                uint32_t voff = (uint32_t)((kk * 16 + (mi & 1) * 8 + rr) * APAD
                                           + db * 16 + (mi >> 1) * 8) * 2;
                uint32_t vh4[4];
                ldmx4t(vh4, st + A_V + voff);
                mma16816(o[db * 2],     ph4, vh4[0], vh4[1]);
                mma16816(o[db * 2 + 1], ph4, vh4[2], vh4[3]);
            }
        }
        __syncthreads();
    }

    float i0 = 1.f / lsum0, i1 = 1.f / lsum1;
    int g = lane >> 2;
    size_t row0 = (size_t)(b * S + m0 + wm + g);
    const float* rs0 = s.resid + row0 * D_ + h * DHD;
    size_t ob0 = row0 * D_ + h * DHD;
    #pragma unroll
    for (int dd = 0; dd < 16; dd++) {
        int d = dd * 8 + ((lane & 3) << 1);
        float2 rv0 = *(const float2*)(rs0 + d);
        float2 rv1 = *(const float2*)(rs0 + 8 * D_ + d);
        store_h2(s.outA, ob0 + d,          rv0.x + o[dd][0] * i0, rv0.y + o[dd][1] * i0);
        store_h2(s.outA, ob0 + 8 * D_ + d, rv1.x + o[dd][2] * i1, rv1.y + o[dd][3] * i1);
    }
}

// ---------------- launch ----------------
extern "C" void kernel_launch(void* const* d_in, const int* in_sizes, int n_in,
                              void* d_out, int out_size) {
    const float* v      = (const float*)d_in[0];
    const float* q      = (const float*)d_in[1];
    const float* c      = (const float*)d_in[2];
    const float* v_mask = (const float*)d_in[3];
    const float* q_mask = (const float*)d_in[4];
    const float* c_mask = (const float*)d_in[5];
    const float* Wv4q   = (const float*)d_in[6];
    const float* bv4q   = (const float*)d_in[7];
    const float* Wq4v   = (const float*)d_in[8];
    const float* bq4v   = (const float*)d_in[9];
    const float* Wv     = (const float*)d_in[10];
    const float* bv     = (const float*)d_in[11];
    const float* Wq     = (const float*)d_in[12];
    const float* bq     = (const float*)d_in[13];
    const float* Wc     = (const float*)d_in[14];
    const float* bcin   = (const float*)d_in[15];
    const float* m_v_k  = (const float*)d_in[16];
    const float* m_v_v  = (const float*)d_in[17];
    const float* m_c_k  = (const float*)d_in[18];
    const float* m_c_v  = (const float*)d_in[19];
    const float* Wvo    = (const float*)d_in[20];
    const float* bvo    = (const float*)d_in[21];
    const float* Wqo    = (const float*)d_in[22];
    const float* bqo    = (const float*)d_in[23];
    const float* Wco    = (const float*)d_in[24];
    const float* bco    = (const float*)d_in[25];
    (void)in_sizes; (void)n_in; (void)out_size;

    float *gv4q, *gq4v, *mnv, *mnq;
    __half *a_v, *a_q, *a_c, *wt;
    __half *vK,*vQ,*vV, *qK,*qQ,*qV, *cK,*cQ,*cV;
    cudaGetSymbolAddress((void**)&gv4q,  g_gate_v4q);
    cudaGetSymbolAddress((void**)&gq4v,  g_gate_q4v);
    cudaGetSymbolAddress((void**)&mnv,   g_mean_v);
    cudaGetSymbolAddress((void**)&mnq,   g_mean_q);
    cudaGetSymbolAddress((void**)&a_v,   g_a_v);
    cudaGetSymbolAddress((void**)&a_q,   g_a_q);
    cudaGetSymbolAddress((void**)&a_c,   g_a_c);
    cudaGetSymbolAddress((void**)&wt,    g_wt);
    cudaGetSymbolAddress((void**)&vK, g_vK); cudaGetSymbolAddress((void**)&vQ, g_vQ);
    cudaGetSymbolAddress((void**)&vV, g_vV);
    cudaGetSymbolAddress((void**)&qK, g_qK); cudaGetSymbolAddress((void**)&qQ, g_qQ);
    cudaGetSymbolAddress((void**)&qV, g_qV);
    cudaGetSymbolAddress((void**)&cK, g_cK); cudaGetSymbolAddress((void**)&cQ, g_cQ);
    cudaGetSymbolAddress((void**)&cV, g_cV);

    cudaFuncSetAttribute(mma_gemm_kernel<true, true>,   cudaFuncAttributeMaxDynamicSharedMemorySize, MMA_SMEM_BYTES);
    cudaFuncSetAttribute(mma_gemm_kernel<false, false>, cudaFuncAttributeMaxDynamicSharedMemorySize, MMA_SMEM_BYTES);
    cudaFuncSetAttribute(attn_mma_kernel, cudaFuncAttributeMaxDynamicSharedMemorySize, ATT_SMEM_BYTES);

    const size_t WO_V = 0, WO_Q = 3145728, WO_C = 6291456;
    const size_t WO_VO = 9437184, WO_QO = 10485760, WO_CO = 11534336;

    // 1) weight transpose + fp16 convert
    {
        WTArgs wa;
        wa.W[0] = Wv;  wa.out[0] = wt + WO_V;  wa.N[0] = N3;
        wa.W[1] = Wq;  wa.out[1] = wt + WO_Q;  wa.N[1] = N3;
        wa.W[2] = Wc;  wa.out[2] = wt + WO_C;  wa.N[2] = N3;
        wa.W[3] = Wvo; wa.out[3] = wt + WO_VO; wa.N[3] = D_;
        wa.W[4] = Wqo; wa.out[4] = wt + WO_QO; wa.N[4] = D_;
        wa.W[5] = Wco; wa.out[5] = wt + WO_CO; wa.N[5] = D_;
        cvt_wT_kernel<<<dim3(N3 / 32, 32, 6), dim3(32, 8)>>>(wa);
    }
    // 2) activation relu + fp16 convert
    {
        ActArgs aa;
        aa.x[0] = v; aa.out[0] = a_v; aa.nblk0 = 16384;
        aa.x[1] = q; aa.out[1] = a_q; aa.nblk1 = 8192;
        aa.x[2] = c; aa.out[2] = a_c;
        cvt_act_kernel<<<16384 + 8192 + 16384, 256>>>(aa);
    }
    // 3) masked means
    {
        MeanArgs ma;
        ma.x[0] = v; ma.mask[0] = v_mask; ma.out[0] = mnv; ma.S[0] = SV;
        ma.x[1] = q; ma.mask[1] = q_mask; ma.out[1] = mnq; ma.S[1] = SQ;
        mean_relu_kernel<<<dim3(4, B_, 2), 256>>>(ma);
    }
    // 4) gates (k-parallel)
    {
        GateArgs ga;
        ga.mean[0] = mnv; ga.W[0] = Wv4q; ga.bias[0] = bv4q; ga.out[0] = gv4q;
        ga.mean[1] = mnq; ga.W[1] = Wq4v; ga.bias[1] = bq4v; ga.out[1] = gq4v;
        gate_kernel<<<dim3(8, B_, 2), 512>>>(ga);
    }
    // 5) memory tokens
    {
        MemArgs me;
        me.K[0] = vK; me.V[0] = vV; me.mk[0] = m_v_k; me.mv[0] = m_v_v;
        me.gate[0] = gq4v; me.T[0] = SV + 1;
        me.K[1] = cK; me.V[1] = cV; me.mk[1] = m_c_k; me.mv[1] = m_c_v;
        me.gate[1] = nullptr; me.T[1] = SC + 1;
        memtok_kernel<<<dim3(B_, 2), 1024>>>(me);
    }
    // 6) QKV projections (merged 3 streams)
    {
        Gemm3 g3{};
        g3.s[0] = { a_v, wt + WO_V, bv,   v_mask, gq4v, vK, vQ, vV, nullptr, SV, SV + 1, 1 };
        g3.s[1] = { a_q, wt + WO_Q, bq,   q_mask, gv4q, qK, qQ, qV, nullptr, SQ, SQ,     0 };
        g3.s[2] = { a_c, wt + WO_C, bcin, c_mask, nullptr, cK, cQ, cV, nullptr, SC, SC + 1, 1 };
        g3.nby0 = 128; g3.nby1 = 64;
        mma_gemm_kernel<true, true><<<dim3(24, 320), 128, MMA_SMEM_BYTES>>>(g3, N3);
    }
    // 7) attention (merged 3 streams); epilogue writes fp16(resid + attn) into A buffers
    {
        Attn3 a3{};
        a3.s[0] = { vK, vQ, vV, v_mask, v, a_v, SV, SV + 1, 1 };
        a3.s[1] = { qK, qQ, qV, q_mask, q, a_q, SQ, SQ,     0 };
        a3.s[2] = { cK, cQ, cV, c_mask, c, a_c, SC, SC + 1, 1 };
        a3.nbx0 = SV / 128; a3.nbx1 = SQ / 128;
        attn_mma_kernel<<<dim3(SV / 128 + SQ / 128 + SC / 128, H_, B_), 256, ATT_SMEM_BYTES>>>(a3);
    }
    // 8) output projections (merged 3 streams)
    {
        float* out = (float*)d_out;
        Gemm3 g3{};
        g3.s[0] = { a_v, wt + WO_VO, bvo, nullptr, nullptr, nullptr, nullptr, nullptr,
                    out, 0, 0, 0 };
        g3.s[1] = { a_q, wt + WO_QO, bqo, nullptr, nullptr, nullptr, nullptr, nullptr,
                    out + (size_t)B_ * SV * D_, 0, 0, 0 };
        g3.s[2] = { a_c, wt + WO_CO, bco, nullptr, nullptr, nullptr, nullptr, nullptr,
                    out + (size_t)B_ * (SV + SQ) * D_, 0, 0, 0 };
        g3.nby0 = 128; g3.nby1 = 64;
        mma_gemm_kernel<false, false><<<dim3(8, 320), 128, MMA_SMEM_BYTES>>>(g3, D_);
    }
}